// round 2
// baseline (speedup 1.0000x reference)
#include <cuda_runtime.h>
#include <math.h>

#define MROWS 4096
#define DMODEL 1024
#define NH 16
#define HD 64
#define QD 16
#define SEQ 2048
#define NBH 32
#define AD 80
#define KS 68   // smem row stride (floats) for K/P/V tiles

// ---------------- scratch ----------------
__device__ float g_Q[MROWS*DMODEL];
__device__ float g_K[MROWS*DMODEL];
__device__ float g_V[MROWS*DMODEL];
__device__ float g_Cq[MROWS*DMODEL];
__device__ float g_Ck[MROWS*DMODEL];
__device__ float g_att[MROWS*DMODEL];
__device__ float g_res[MROWS*DMODEL];
__device__ float g_Qa[NBH*SEQ*AD];   // [bh][s][80] = [0.125*Qf , 0.1*qp]
__device__ float g_Kt[NBH*AD*SEQ];   // [bh][k80][s] = [Kf ; kp] transposed
__device__ float g_Va[NBH*SEQ*HD];   // [bh][s][64]
__device__ float g_probs_q[MROWS*QD];
__device__ float g_probs_k[MROWS*QD];
__device__ float g_fw_q[MROWS];
__device__ float g_fw_k[MROWS];
__device__ float g_m[NBH*SEQ];       // final row max
__device__ float g_l[NBH*SEQ];       // final row sum-exp
__device__ float g_mt[NBH*SEQ*32];   // running max snapshot per key tile
__device__ float g_M[4*256];         // qq:{qw_r@em, qw_i@em}, qk:{...}

// ---------------- prep: M = qw @ em ----------------
__global__ void prep_m_kernel(const float* __restrict__ qqr, const float* __restrict__ qqi,
                              const float* __restrict__ qkr, const float* __restrict__ qki,
                              const float* __restrict__ qqem, const float* __restrict__ qkem)
{
    int t = threadIdx.x;            // 256
    int u = t >> 4, v = t & 15;
    float a = 0.f, b = 0.f, c = 0.f, d = 0.f;
#pragma unroll
    for (int w = 0; w < 16; w++) {
        float e1 = qqem[w*16+v], e2 = qkem[w*16+v];
        a += qqr[u*16+w]*e1;
        b += qqi[u*16+w]*e1;
        c += qkr[u*16+w]*e2;
        d += qki[u*16+w]*e2;
    }
    g_M[t] = a; g_M[256+t] = b; g_M[512+t] = c; g_M[768+t] = d;
}

// ---------------- quantum small path ----------------
__global__ __launch_bounds__(128) void quantum_kernel(
    const float* __restrict__ x, const float* __restrict__ sgq, const float* __restrict__ sgk)
{
    __shared__ float xs[1024];
    __shared__ float part[8][16];
    __shared__ float qss[16];
    __shared__ float prob_s[16];
    int i = blockIdx.x;             // row 0..4095
    int t = threadIdx.x;
#pragma unroll
    for (int c = 0; c < 2; c++)
        *(float4*)&xs[(t + c*128)*4] = *(const float4*)&x[(size_t)i*1024 + (t + c*128)*4];
    __syncthreads();
    int tt = t & 15, pp = t >> 4;
#pragma unroll 1
    for (int side = 0; side < 2; side++) {
        const float* sg = side ? sgk : sgq;
        float acc = 0.f;
        int base = pp * 128;
        for (int d = 0; d < 128; d++)
            acc += xs[base + d] * sg[(base + d)*16 + tt];
        part[pp][tt] = acc;
        __syncthreads();
        if (t < 16) {
            float q = 0.f;
#pragma unroll
            for (int p = 0; p < 8; p++) q += part[p][t];
            qss[t] = q;
        }
        __syncthreads();
        if (t < 16) {
            const float* Mr = g_M + side*512;
            const float* Mi = Mr + 256;
            float er = 0.f, ei = 0.f;
#pragma unroll
            for (int u = 0; u < 16; u++) {
                er += qss[u]*Mr[u*16+t];
                ei += qss[u]*Mi[u*16+t];
            }
            float pr = er*er + ei*ei;
            prob_s[t] = pr;
            (side ? g_probs_k : g_probs_q)[i*16 + t] = pr;
        }
        __syncthreads();
        if (t == 0) {
            float ms = 0.f;
#pragma unroll
            for (int u = 0; u < 16; u++) ms += prob_s[u];
            ms *= (1.f/16.f);
            (side ? g_fw_k : g_fw_q)[i] = 1.f/(1.f + __expf(-ms));
        }
        __syncthreads();
    }
}

// ---------------- 128x128x8 SGEMM: out = [tanh](A@W + b [+ resid]) ----------------
__global__ __launch_bounds__(256) void sgemm_kernel(
    const float* __restrict__ A, const float* __restrict__ W,
    const float* __restrict__ bias, const float* __restrict__ resid,
    float* __restrict__ out, int do_tanh)
{
    __shared__ float As[8][128];
    __shared__ float Bs[8][128];
    int m0 = blockIdx.x * 128;
    int n0 = blockIdx.y * 128;
    int t = threadIdx.x;
    int a_row = t >> 1, a_col = (t & 1) * 4;
    int b_row = t >> 5, b_col = (t & 31) * 4;
    int tm = (t >> 4) * 8, tn = (t & 15) * 8;
    float acc[8][8];
#pragma unroll
    for (int i = 0; i < 8; i++)
#pragma unroll
        for (int j = 0; j < 8; j++) acc[i][j] = 0.f;

    for (int k0 = 0; k0 < 1024; k0 += 8) {
        float4 av = *(const float4*)&A[(size_t)(m0 + a_row)*1024 + k0 + a_col];
        As[a_col+0][a_row] = av.x;
        As[a_col+1][a_row] = av.y;
        As[a_col+2][a_row] = av.z;
        As[a_col+3][a_row] = av.w;
        *(float4*)&Bs[b_row][b_col] = *(const float4*)&W[(size_t)(k0 + b_row)*1024 + n0 + b_col];
        __syncthreads();
#pragma unroll
        for (int kk = 0; kk < 8; kk++) {
            float ra[8], rb[8];
            *(float4*)&ra[0] = *(float4*)&As[kk][tm];
            *(float4*)&ra[4] = *(float4*)&As[kk][tm+4];
            *(float4*)&rb[0] = *(float4*)&Bs[kk][tn];
            *(float4*)&rb[4] = *(float4*)&Bs[kk][tn+4];
#pragma unroll
            for (int i = 0; i < 8; i++)
#pragma unroll
                for (int j = 0; j < 8; j++)
                    acc[i][j] += ra[i] * rb[j];
        }
        __syncthreads();
    }
#pragma unroll
    for (int ii = 0; ii < 8; ii++) {
        int m = m0 + tm + ii;
#pragma unroll
        for (int jj = 0; jj < 8; jj += 4) {
            int n = n0 + tn + jj;
            float4 v;
            v.x = acc[ii][jj+0] + bias[n+0];
            v.y = acc[ii][jj+1] + bias[n+1];
            v.z = acc[ii][jj+2] + bias[n+2];
            v.w = acc[ii][jj+3] + bias[n+3];
            if (resid) {
                float4 r = *(const float4*)&resid[(size_t)m*1024 + n];
                v.x += r.x; v.y += r.y; v.z += r.z; v.w += r.w;
            }
            if (do_tanh) {
                v.x = tanhf(v.x); v.y = tanhf(v.y);
                v.z = tanhf(v.z); v.w = tanhf(v.w);
            }
            *(float4*)&out[(size_t)m*1024 + n] = v;
        }
    }
}

// ---------------- combine: build Qa / Kt / Va ----------------
__global__ __launch_bounds__(256) void combine_kernel(
    const float* __restrict__ qq_mb, const float* __restrict__ qk_mb)
{
    int i = blockIdx.x;               // row 0..4095
    int b = i >> 11, s = i & 2047;
    int t = threadIdx.x;
    __shared__ float pqs[16], pks[16];
    if (t < 16) pqs[t] = g_probs_q[i*16 + t];
    else if (t < 32) pks[t-16] = g_probs_k[i*16 + (t-16)];
    __syncthreads();
    float fq = g_fw_q[i], fk = g_fw_k[i];
    int d0 = t * 4;
    float4 qv = *(const float4*)&g_Q [(size_t)i*1024 + d0];
    float4 kv = *(const float4*)&g_K [(size_t)i*1024 + d0];
    float4 vv = *(const float4*)&g_V [(size_t)i*1024 + d0];
    float4 cq = *(const float4*)&g_Cq[(size_t)i*1024 + d0];
    float4 ck = *(const float4*)&g_Ck[(size_t)i*1024 + d0];
    const float* qvp = (const float*)&qv;
    const float* kvp = (const float*)&kv;
    const float* cqp = (const float*)&cq;
    const float* ckp = (const float*)&ck;
    float outq[4], outk[4];
#pragma unroll
    for (int j = 0; j < 4; j++) {
        int d = d0 + j;
        float qmb = 0.f, kmb = 0.f;
#pragma unroll
        for (int u = 0; u < 16; u++) {
            qmb += pqs[u] * qq_mb[u*1024 + d];
            kmb += pks[u] * qk_mb[u*1024 + d];
        }
        float qq = fq*qmb + (1.f - fq)*cqp[j];
        float kq = fk*kmb + (1.f - fk)*ckp[j];
        outq[j] = (0.7f*qvp[j] + 0.3f*qq) * 0.125f;   // 1/sqrt(64)
        outk[j] =  0.7f*kvp[j] + 0.3f*kq;
    }
    int h = d0 >> 6, dh = d0 & 63;
    int bh = b*16 + h;
    *(float4*)&g_Qa[((size_t)bh*SEQ + s)*AD + dh] = make_float4(outq[0],outq[1],outq[2],outq[3]);
#pragma unroll
    for (int j = 0; j < 4; j++)
        g_Kt[((size_t)bh*AD + dh + j)*SEQ + s] = outk[j];
    *(float4*)&g_Va[((size_t)bh*SEQ + s)*HD + dh] = vv;
    // interference tails (replicated to every head of this row)
    int h2 = t >> 4, u = t & 15;
    int bh2 = b*16 + h2;
    g_Qa[((size_t)bh2*SEQ + s)*AD + 64 + u] = 0.1f * pqs[u];
    g_Kt[((size_t)bh2*AD + 64 + u)*SEQ + s] = pks[u];
}

// ---------------- flash attention (writes unnormalized p into w) ----------------
#define FLASH_SMEM_FLOATS (64*AD + AD*KS + 64*KS)   // Qs + Ks(=Ps alias) + Vs
#define FLASH_SMEM_BYTES  (FLASH_SMEM_FLOATS * 4)

__global__ __launch_bounds__(256) void flash_kernel(float* __restrict__ w_out)
{
    extern __shared__ float sm[];
    float* Qs = sm;                 // [64][80]
    float* Ks = Qs + 64*AD;         // [80][KS]; reused as Ps [64][KS]
    float* Vs = Ks + AD*KS;         // [64][KS]
    int qt = blockIdx.x, bh = blockIdx.y;
    int t = threadIdx.x;
    int ty = t >> 4, tx = t & 15;

    const float* Qg  = g_Qa + ((size_t)bh*SEQ + qt*64)*AD;
    const float* Ktg = g_Kt + (size_t)bh*AD*SEQ;
    const float* Vg  = g_Va + (size_t)bh*SEQ*HD;

    for (int idx = t; idx < 64*AD/4; idx += 256)
        *(float4*)&Qs[idx*4] = *(const float4*)&Qg[idx*4];

    float mrow[4], lrow[4], O[4][4];
#pragma unroll
    for (int ii = 0; ii < 4; ii++) {
        mrow[ii] = -1e30f; lrow[ii] = 0.f;
#pragma unroll
        for (int jj = 0; jj < 4; jj++) O[ii][jj] = 0.f;
    }

#pragma unroll 1
    for (int kt = 0; kt < 32; kt++) {
        __syncthreads();   // prev iter done reading Ps/Vs (and Qs copy on kt=0)
        for (int idx = t; idx < AD*16; idx += 256) {
            int k = idx >> 4, n4 = idx & 15;
            *(float4*)&Ks[k*KS + n4*4] = *(const float4*)&Ktg[(size_t)k*SEQ + kt*64 + n4*4];
        }
        for (int idx = t; idx < 64*16; idx += 256) {
            int j = idx >> 4, n4 = idx & 15;
            *(float4*)&Vs[j*KS + n4*4] = *(const float4*)&Vg[(size_t)(kt*64 + j)*HD + n4*4];
        }
        __syncthreads();

        float s[4][4];
#pragma unroll
        for (int ii = 0; ii < 4; ii++)
#pragma unroll
            for (int jj = 0; jj < 4; jj++) s[ii][jj] = 0.f;

#pragma unroll
        for (int k0 = 0; k0 < AD; k0 += 4) {
            float4 aa[4], bb[4];
#pragma unroll
            for (int ii = 0; ii < 4; ii++)
                aa[ii] = *(const float4*)&Qs[(ty*4+ii)*AD + k0];
#pragma unroll
            for (int c = 0; c < 4; c++)
                bb[c] = *(const float4*)&Ks[(k0+c)*KS + tx*4];
#pragma unroll
            for (int ii = 0; ii < 4; ii++) {
                const float* av = (const float*)&aa[ii];
#pragma unroll
                for (int jj = 0; jj < 4; jj++) {
                    s[ii][jj] += av[0]*((const float*)&bb[0])[jj]
                               + av[1]*((const float*)&bb[1])[jj]
                               + av[2]*((const float*)&bb[2])[jj]
                               + av[3]*((const float*)&bb[3])[jj];
                }
            }
        }

        // online softmax update (registers only)
#pragma unroll
        for (int ii = 0; ii < 4; ii++) {
            float mx = fmaxf(fmaxf(s[ii][0], s[ii][1]), fmaxf(s[ii][2], s[ii][3]));
#pragma unroll
            for (int off = 8; off; off >>= 1)
                mx = fmaxf(mx, __shfl_xor_sync(0xffffffffu, mx, off));
            float mn = fmaxf(mrow[ii], mx);
            float alpha = __expf(mrow[ii] - mn);
            mrow[ii] = mn;
            float rs = 0.f;
#pragma unroll
            for (int jj = 0; jj < 4; jj++) {
                float p = __expf(s[ii][jj] - mn);
                s[ii][jj] = p;
                rs += p;
            }
#pragma unroll
            for (int off = 8; off; off >>= 1)
                rs += __shfl_xor_sync(0xffffffffu, rs, off);
            lrow[ii] = lrow[ii]*alpha + rs;
#pragma unroll
            for (int jj = 0; jj < 4; jj++) O[ii][jj] *= alpha;
            if (tx == 0)
                g_mt[((size_t)bh*SEQ + qt*64 + ty*4 + ii)*32 + kt] = mn;
        }

        // write unnormalized p to w
        {
            float* wr = w_out + ((size_t)bh*SEQ + qt*64 + ty*4)*SEQ + (size_t)kt*64 + tx*4;
#pragma unroll
            for (int ii = 0; ii < 4; ii++)
                *(float4*)&wr[(size_t)ii*SEQ] =
                    make_float4(s[ii][0], s[ii][1], s[ii][2], s[ii][3]);
        }

        __syncthreads();   // everyone done reading Ks
        {
            float* Ps = Ks;
#pragma unroll
            for (int ii = 0; ii < 4; ii++)
                *(float4*)&Ps[(ty*4+ii)*KS + tx*4] =
                    make_float4(s[ii][0], s[ii][1], s[ii][2], s[ii][3]);
        }
        __syncthreads();

        // O += P @ V
        {
            const float* Ps = Ks;
#pragma unroll
            for (int j0 = 0; j0 < 64; j0 += 4) {
                float4 aa[4], bb[4];
#pragma unroll
                for (int ii = 0; ii < 4; ii++)
                    aa[ii] = *(const float4*)&Ps[(ty*4+ii)*KS + j0];
#pragma unroll
                for (int c = 0; c < 4; c++)
                    bb[c] = *(const float4*)&Vs[(j0+c)*KS + tx*4];
#pragma unroll
                for (int ii = 0; ii < 4; ii++) {
                    const float* av = (const float*)&aa[ii];
#pragma unroll
                    for (int jj = 0; jj < 4; jj++) {
                        O[ii][jj] += av[0]*((const float*)&bb[0])[jj]
                                   + av[1]*((const float*)&bb[1])[jj]
                                   + av[2]*((const float*)&bb[2])[jj]
                                   + av[3]*((const float*)&bb[3])[jj];
                    }
                }
            }
        }
    }

    int b = bh >> 4, h = bh & 15;
#pragma unroll
    for (int ii = 0; ii < 4; ii++) {
        int row = qt*64 + ty*4 + ii;
        float inv = 1.f / lrow[ii];
        *(float4*)&g_att[((size_t)b*SEQ + row)*1024 + h*64 + tx*4] =
            make_float4(O[ii][0]*inv, O[ii][1]*inv, O[ii][2]*inv, O[ii][3]*inv);
        if (tx == 0) {
            g_m[(size_t)bh*SEQ + row] = mrow[ii];
            g_l[(size_t)bh*SEQ + row] = lrow[ii];
        }
    }
}

// ---------------- normalize w ----------------
__global__ __launch_bounds__(256) void norm_w_kernel(float* __restrict__ w)
{
    size_t idx = (size_t)blockIdx.x * 256 + threadIdx.x;
    size_t e0 = idx * 4;
    size_t row = e0 >> 11;
    int kt = (int)((e0 & 2047) >> 6);
    float f = __expf(g_mt[row*32 + kt] - g_m[row]) / g_l[row];
    float4 v = *(float4*)&w[e0];
    v.x *= f; v.y *= f; v.z *= f; v.w *= f;
    *(float4*)&w[e0] = v;
}

// ---------------- layernorm ----------------
__global__ __launch_bounds__(256) void ln_kernel(const float* __restrict__ gam,
    const float* __restrict__ bet, float* __restrict__ y)
{
    int i = blockIdx.x, t = threadIdx.x;
    float4 v = *(const float4*)&g_res[(size_t)i*1024 + t*4];
    float s  = v.x + v.y + v.z + v.w;
    float ss = v.x*v.x + v.y*v.y + v.z*v.z + v.w*v.w;
#pragma unroll
    for (int off = 16; off; off >>= 1) {
        s  += __shfl_xor_sync(0xffffffffu, s,  off);
        ss += __shfl_xor_sync(0xffffffffu, ss, off);
    }
    __shared__ float as[8], ass[8];
    if ((t & 31) == 0) { as[t >> 5] = s; ass[t >> 5] = ss; }
    __syncthreads();
    float S = 0.f, SS = 0.f;
#pragma unroll
    for (int u = 0; u < 8; u++) { S += as[u]; SS += ass[u]; }
    float mu  = S * (1.f/1024.f);
    float var = SS * (1.f/1024.f) - mu*mu;
    float inv = rsqrtf(var + 1e-5f);
    float4 gg = *(const float4*)&gam[t*4];
    float4 bb = *(const float4*)&bet[t*4];
    float4 o;
    o.x = (v.x - mu)*inv*gg.x + bb.x;
    o.y = (v.y - mu)*inv*gg.y + bb.y;
    o.z = (v.z - mu)*inv*gg.z + bb.z;
    o.w = (v.w - mu)*inv*gg.w + bb.w;
    *(float4*)&y[(size_t)i*1024 + t*4] = o;
}

// ---------------- launch ----------------
extern "C" void kernel_launch(void* const* d_in, const int* in_sizes, int n_in,
                              void* d_out, int out_size)
{
    const float* x       = (const float*)d_in[0];
    const float* Wq      = (const float*)d_in[1];
    const float* bq      = (const float*)d_in[2];
    const float* Wk      = (const float*)d_in[3];
    const float* bk      = (const float*)d_in[4];
    const float* Wv      = (const float*)d_in[5];
    const float* bv      = (const float*)d_in[6];
    const float* Wo      = (const float*)d_in[7];
    const float* bo      = (const float*)d_in[8];
    const float* ln_g    = (const float*)d_in[9];
    const float* ln_b    = (const float*)d_in[10];
    const float* qq_W    = (const float*)d_in[11];
    const float* qq_b    = (const float*)d_in[12];
    const float* qq_qw_r = (const float*)d_in[13];
    const float* qq_qw_i = (const float*)d_in[14];
    const float* qq_sg   = (const float*)d_in[15];
    const float* qq_em   = (const float*)d_in[16];
    const float* qq_mb   = (const float*)d_in[17];
    const float* qk_W    = (const float*)d_in[18];
    const float* qk_b    = (const float*)d_in[19];
    const float* qk_qw_r = (const float*)d_in[20];
    const float* qk_qw_i = (const float*)d_in[21];
    const float* qk_sg   = (const float*)d_in[22];
    const float* qk_em   = (const float*)d_in[23];
    const float* qk_mb   = (const float*)d_in[24];

    float* y = (float*)d_out;                 // [2,2048,1024]
    float* w = y + (size_t)MROWS*DMODEL;      // [2,16,2048,2048]

    float *pQ, *pK, *pV, *pCq, *pCk, *pAtt, *pRes;
    cudaGetSymbolAddress((void**)&pQ,   g_Q);
    cudaGetSymbolAddress((void**)&pK,   g_K);
    cudaGetSymbolAddress((void**)&pV,   g_V);
    cudaGetSymbolAddress((void**)&pCq,  g_Cq);
    cudaGetSymbolAddress((void**)&pCk,  g_Ck);
    cudaGetSymbolAddress((void**)&pAtt, g_att);
    cudaGetSymbolAddress((void**)&pRes, g_res);

    cudaFuncSetAttribute(flash_kernel,
        cudaFuncAttributeMaxDynamicSharedMemorySize, FLASH_SMEM_BYTES);

    prep_m_kernel<<<1, 256>>>(qq_qw_r, qq_qw_i, qk_qw_r, qk_qw_i, qq_em, qk_em);
    quantum_kernel<<<MROWS, 128>>>(x, qq_sg, qk_sg);

    dim3 gg(32, 8);
    sgemm_kernel<<<gg, 256>>>(x, Wq,   bq,   nullptr, pQ,  0);
    sgemm_kernel<<<gg, 256>>>(x, Wk,   bk,   nullptr, pK,  0);
    sgemm_kernel<<<gg, 256>>>(x, Wv,   bv,   nullptr, pV,  0);
    sgemm_kernel<<<gg, 256>>>(x, qq_W, qq_b, nullptr, pCq, 1);
    sgemm_kernel<<<gg, 256>>>(x, qk_W, qk_b, nullptr, pCk, 1);

    combine_kernel<<<MROWS, 256>>>(qq_mb, qk_mb);

    dim3 fg(32, 32);
    flash_kernel<<<fg, 256, FLASH_SMEM_BYTES>>>(w);

    norm_w_kernel<<<(NBH*(size_t)SEQ*SEQ)/(4*256), 256>>>(w);

    sgemm_kernel<<<gg, 256>>>(pAtt, Wo, bo, x, pRes, 0);
    ln_kernel<<<MROWS, 256>>>(ln_g, ln_b, y);
}

// round 4
// speedup vs baseline: 1.3634x; 1.3634x over previous
#include <cuda_runtime.h>
#include <cuda_bf16.h>
#include <cstdint>
#include <math.h>

#define MROWS 4096
#define DMODEL 1024
#define NH 16
#define HD 64
#define QD 16
#define SEQ 2048
#define NBH 32
#define AD 80
#define KS 68   // smem row stride (floats) for K/P/V tiles in flash

// ---------------- scratch ----------------
__device__ float g_Q[MROWS*DMODEL];
__device__ float g_K[MROWS*DMODEL];
__device__ float g_V[MROWS*DMODEL];
__device__ float g_Cq[MROWS*DMODEL];
__device__ float g_Ck[MROWS*DMODEL];
__device__ float g_att[MROWS*DMODEL];
__device__ float g_res[MROWS*DMODEL];
__device__ float g_Qa[NBH*SEQ*AD];
__device__ float g_Kt[NBH*AD*SEQ];
__device__ float g_Va[NBH*SEQ*HD];
__device__ float g_probs_q[MROWS*QD];
__device__ float g_probs_k[MROWS*QD];
__device__ float g_fw_q[MROWS];
__device__ float g_fw_k[MROWS];
__device__ float g_m[NBH*SEQ];
__device__ float g_l[NBH*SEQ];
__device__ float g_mt[NBH*SEQ*32];
__device__ float g_M[4*256];

// bf16 split buffers
__device__ __nv_bfloat16 g_xhi[MROWS*DMODEL];
__device__ __nv_bfloat16 g_xlo[MROWS*DMODEL];
__device__ __nv_bfloat16 g_ahi[MROWS*DMODEL];
__device__ __nv_bfloat16 g_alo[MROWS*DMODEL];
__device__ __nv_bfloat16 g_Whi[6*DMODEL*DMODEL];   // [widx][n][k]
__device__ __nv_bfloat16 g_Wlo[6*DMODEL*DMODEL];

// ---------------- helpers ----------------
__device__ __forceinline__ uint32_t smem_u32(const void* p) {
    uint32_t a;
    asm("{ .reg .u64 t; cvta.to.shared.u64 t, %1; cvt.u32.u64 %0, t; }" : "=r"(a) : "l"(p));
    return a;
}
__device__ __forceinline__ void cp16(uint32_t dst, const void* src) {
    asm volatile("cp.async.cg.shared.global [%0], [%1], 16;\n" :: "r"(dst), "l"(src));
}
__device__ __forceinline__ void ldsm4(uint32_t* r, uint32_t addr) {
    asm volatile("ldmatrix.sync.aligned.m8n8.x4.shared.b16 {%0,%1,%2,%3}, [%4];"
        : "=r"(r[0]), "=r"(r[1]), "=r"(r[2]), "=r"(r[3]) : "r"(addr));
}
__device__ __forceinline__ void ldsm2(uint32_t* r, uint32_t addr) {
    asm volatile("ldmatrix.sync.aligned.m8n8.x2.shared.b16 {%0,%1}, [%2];"
        : "=r"(r[0]), "=r"(r[1]) : "r"(addr));
}
__device__ __forceinline__ void mma16816(float* d, const uint32_t* a, const uint32_t* b) {
    asm volatile("mma.sync.aligned.m16n8k16.row.col.f32.bf16.bf16.f32 "
        "{%0,%1,%2,%3}, {%4,%5,%6,%7}, {%8,%9}, {%0,%1,%2,%3};"
        : "+f"(d[0]), "+f"(d[1]), "+f"(d[2]), "+f"(d[3])
        : "r"(a[0]), "r"(a[1]), "r"(a[2]), "r"(a[3]), "r"(b[0]), "r"(b[1]));
}

// ---------------- conversions ----------------
__global__ __launch_bounds__(256) void aconv_kernel(const float* __restrict__ a,
    __nv_bfloat16* __restrict__ hi, __nv_bfloat16* __restrict__ lo)
{
    size_t i = ((size_t)blockIdx.x * 256 + threadIdx.x) * 4;
    float4 v = *(const float4*)&a[i];
    float vv[4] = {v.x, v.y, v.z, v.w};
    ushort4 h, l;
    unsigned short* hp = &h.x; unsigned short* lp = &l.x;
#pragma unroll
    for (int j = 0; j < 4; j++) {
        __nv_bfloat16 hb = __float2bfloat16(vv[j]);
        __nv_bfloat16 lb = __float2bfloat16(vv[j] - __bfloat162float(hb));
        hp[j] = __bfloat16_as_ushort(hb);
        lp[j] = __bfloat16_as_ushort(lb);
    }
    *(ushort4*)&hi[i] = h;
    *(ushort4*)&lo[i] = l;
}

// W [k][n] f32 -> hi/lo [n][k] bf16
__global__ __launch_bounds__(256) void wconv_kernel(const float* __restrict__ W,
    __nv_bfloat16* __restrict__ hi, __nv_bfloat16* __restrict__ lo)
{
    __shared__ float tile[32][33];
    int bx = blockIdx.x * 32;  // n block
    int by = blockIdx.y * 32;  // k block
    int tx = threadIdx.x, ty = threadIdx.y;   // 32 x 8
#pragma unroll
    for (int i = 0; i < 32; i += 8)
        tile[ty + i][tx] = W[(size_t)(by + ty + i) * 1024 + bx + tx];
    __syncthreads();
#pragma unroll
    for (int i = 0; i < 32; i += 8) {
        int n = bx + ty + i, k = by + tx;
        float v = tile[tx][ty + i];
        __nv_bfloat16 hb = __float2bfloat16(v);
        hi[(size_t)n * 1024 + k] = hb;
        lo[(size_t)n * 1024 + k] = __float2bfloat16(v - __bfloat162float(hb));
    }
}

// ---------------- mma.sync split-bf16 GEMM ----------------
// out[4096x1024] = A@W^T (+bias)(+resid)(tanh). A hi/lo [m][k], B hi/lo [n][k].
// CTA tile 128x128, k-chunk 32, double-buffered cp.async.
// smem per stage (bf16 elems): Ahi[128][40] Alo Bhi[128][40] Blo
#define SROW 40
#define MAT_E (128*SROW)          // 5120 elems
#define SST_E (4*MAT_E)           // 20480 elems per stage
#define GEMM_SMEM (2*SST_E*2)     // bytes = 81920

__device__ __forceinline__ void load_chunk_mm(uint32_t sb, int t, int m0, int n0, int k0,
    const __nv_bfloat16* Ahi, const __nv_bfloat16* Alo,
    const __nv_bfloat16* Bhi, const __nv_bfloat16* Blo)
{
    // each matrix: 128 rows x 32 bf16 = 512 x 16B, 256 threads -> 2 iters
#pragma unroll
    for (int i = 0; i < 2; i++) {
        int cid = i * 256 + t;
        int row = cid >> 2, c = cid & 3;
        uint32_t off = (uint32_t)(row * (SROW*2) + c * 16);
        cp16(sb + off,              (const char*)(Ahi + (size_t)(m0 + row) * 1024 + k0) + c * 16);
        cp16(sb + MAT_E*2 + off,    (const char*)(Alo + (size_t)(m0 + row) * 1024 + k0) + c * 16);
        cp16(sb + 2*MAT_E*2 + off,  (const char*)(Bhi + (size_t)(n0 + row) * 1024 + k0) + c * 16);
        cp16(sb + 3*MAT_E*2 + off,  (const char*)(Blo + (size_t)(n0 + row) * 1024 + k0) + c * 16);
    }
    asm volatile("cp.async.commit_group;\n" ::: "memory");
}

__global__ __launch_bounds__(256) void mma_gemm_kernel(
    const __nv_bfloat16* __restrict__ Ahi, const __nv_bfloat16* __restrict__ Alo,
    const __nv_bfloat16* __restrict__ Bhi, const __nv_bfloat16* __restrict__ Blo,
    const float* __restrict__ bias, const float* __restrict__ resid,
    float* __restrict__ out, int do_tanh)
{
    extern __shared__ char smem[];
    uint32_t sb = smem_u32(smem);
    int t = threadIdx.x;
    int warp = t >> 5, lane = t & 31;
    int wm = warp & 1, wn = warp >> 1;      // 2 x 4 warps, warp tile 64x32
    int m0 = blockIdx.x * 128, n0 = blockIdx.y * 128;

    float acc[4][4][4];
#pragma unroll
    for (int a = 0; a < 4; a++)
#pragma unroll
        for (int b = 0; b < 4; b++)
#pragma unroll
            for (int c = 0; c < 4; c++) acc[a][b][c] = 0.f;

    // ldmatrix lane address components
    int aq = lane >> 3;
    int arow = (aq & 1) * 8 + (lane & 7);
    int akoff = (aq >> 1) * 8;
    int brow = lane & 7;
    int bkoff = ((lane >> 3) & 1) * 8;

    load_chunk_mm(sb, t, m0, n0, 0, Ahi, Alo, Bhi, Blo);

#pragma unroll 1
    for (int c = 0; c < 32; c++) {
        if (c < 31)
            load_chunk_mm(sb + ((c + 1) & 1) * SST_E * 2, t, m0, n0, (c + 1) * 32, Ahi, Alo, Bhi, Blo);
        if (c < 31) asm volatile("cp.async.wait_group 1;\n" ::: "memory");
        else        asm volatile("cp.async.wait_group 0;\n" ::: "memory");
        __syncthreads();

        uint32_t st = sb + (c & 1) * SST_E * 2;
#pragma unroll
        for (int k16 = 0; k16 < 2; k16++) {
            int kb = k16 * 16;
            uint32_t ah[4][4], al[4][4];
#pragma unroll
            for (int mt = 0; mt < 4; mt++) {
                uint32_t aaddr = st + (uint32_t)(((wm*64 + mt*16 + arow) * SROW + kb + akoff) * 2);
                ldsm4(ah[mt], aaddr);
                ldsm4(al[mt], aaddr + MAT_E*2);
            }
#pragma unroll
            for (int nt = 0; nt < 4; nt++) {
                uint32_t baddr = st + 2*MAT_E*2 +
                    (uint32_t)(((wn*32 + nt*8 + brow) * SROW + kb + bkoff) * 2);
                uint32_t bh[2], bl[2];
                ldsm2(bh, baddr);
                ldsm2(bl, baddr + MAT_E*2);
#pragma unroll
                for (int mt = 0; mt < 4; mt++) {
                    mma16816(acc[mt][nt], ah[mt], bh);
                    mma16816(acc[mt][nt], ah[mt], bl);
                    mma16816(acc[mt][nt], al[mt], bh);
                }
            }
        }
        __syncthreads();
    }

    // epilogue straight from registers
    int rin = lane >> 2, cin = (lane & 3) * 2;
#pragma unroll
    for (int mt = 0; mt < 4; mt++) {
#pragma unroll
        for (int nt = 0; nt < 4; nt++) {
            int n = n0 + wn*32 + nt*8 + cin;
            float b0 = bias[n], b1 = bias[n + 1];
#pragma unroll
            for (int half = 0; half < 2; half++) {
                int m = m0 + wm*64 + mt*16 + rin + half*8;
                float v0 = acc[mt][nt][half*2 + 0] + b0;
                float v1 = acc[mt][nt][half*2 + 1] + b1;
                if (resid) {
                    const float* rr = resid + (size_t)m * 1024 + n;
                    v0 += rr[0]; v1 += rr[1];
                }
                if (do_tanh) { v0 = tanhf(v0); v1 = tanhf(v1); }
                float2 vv = make_float2(v0, v1);
                *(float2*)&out[(size_t)m * 1024 + n] = vv;
            }
        }
    }
}

// ---------------- prep: M = qw @ em ----------------
__global__ void prep_m_kernel(const float* __restrict__ qqr, const float* __restrict__ qqi,
                              const float* __restrict__ qkr, const float* __restrict__ qki,
                              const float* __restrict__ qqem, const float* __restrict__ qkem)
{
    int t = threadIdx.x;
    int u = t >> 4, v = t & 15;
    float a = 0.f, b = 0.f, c = 0.f, d = 0.f;
#pragma unroll
    for (int w = 0; w < 16; w++) {
        float e1 = qqem[w*16+v], e2 = qkem[w*16+v];
        a += qqr[u*16+w]*e1;
        b += qqi[u*16+w]*e1;
        c += qkr[u*16+w]*e2;
        d += qki[u*16+w]*e2;
    }
    g_M[t] = a; g_M[256+t] = b; g_M[512+t] = c; g_M[768+t] = d;
}

// ---------------- quantum small path ----------------
__global__ __launch_bounds__(128) void quantum_kernel(
    const float* __restrict__ x, const float* __restrict__ sgq, const float* __restrict__ sgk)
{
    __shared__ float xs[1024];
    __shared__ float part[8][16];
    __shared__ float qss[16];
    __shared__ float prob_s[16];
    int i = blockIdx.x;
    int t = threadIdx.x;
#pragma unroll
    for (int c = 0; c < 2; c++)
        *(float4*)&xs[(t + c*128)*4] = *(const float4*)&x[(size_t)i*1024 + (t + c*128)*4];
    __syncthreads();
    int tt = t & 15, pp = t >> 4;
#pragma unroll 1
    for (int side = 0; side < 2; side++) {
        const float* sg = side ? sgk : sgq;
        float acc = 0.f;
        int base = pp * 128;
        for (int d = 0; d < 128; d++)
            acc += xs[base + d] * sg[(base + d)*16 + tt];
        part[pp][tt] = acc;
        __syncthreads();
        if (t < 16) {
            float q = 0.f;
#pragma unroll
            for (int p = 0; p < 8; p++) q += part[p][t];
            qss[t] = q;
        }
        __syncthreads();
        if (t < 16) {
            const float* Mr = g_M + side*512;
            const float* Mi = Mr + 256;
            float er = 0.f, ei = 0.f;
#pragma unroll
            for (int u = 0; u < 16; u++) {
                er += qss[u]*Mr[u*16+t];
                ei += qss[u]*Mi[u*16+t];
            }
            float pr = er*er + ei*ei;
            prob_s[t] = pr;
            (side ? g_probs_k : g_probs_q)[i*16 + t] = pr;
        }
        __syncthreads();
        if (t == 0) {
            float ms = 0.f;
#pragma unroll
            for (int u = 0; u < 16; u++) ms += prob_s[u];
            ms *= (1.f/16.f);
            (side ? g_fw_k : g_fw_q)[i] = 1.f/(1.f + __expf(-ms));
        }
        __syncthreads();
    }
}

// ---------------- combine: build Qa / Kt / Va ----------------
__global__ __launch_bounds__(256) void combine_kernel(
    const float* __restrict__ qq_mb, const float* __restrict__ qk_mb)
{
    int i = blockIdx.x;
    int b = i >> 11, s = i & 2047;
    int t = threadIdx.x;
    __shared__ float pqs[16], pks[16];
    if (t < 16) pqs[t] = g_probs_q[i*16 + t];
    else if (t < 32) pks[t-16] = g_probs_k[i*16 + (t-16)];
    __syncthreads();
    float fq = g_fw_q[i], fk = g_fw_k[i];
    int d0 = t * 4;
    float4 qv = *(const float4*)&g_Q [(size_t)i*1024 + d0];
    float4 kv = *(const float4*)&g_K [(size_t)i*1024 + d0];
    float4 vv = *(const float4*)&g_V [(size_t)i*1024 + d0];
    float4 cq = *(const float4*)&g_Cq[(size_t)i*1024 + d0];
    float4 ck = *(const float4*)&g_Ck[(size_t)i*1024 + d0];
    const float* qvp = (const float*)&qv;
    const float* kvp = (const float*)&kv;
    const float* cqp = (const float*)&cq;
    const float* ckp = (const float*)&ck;
    float outq[4], outk[4];
#pragma unroll
    for (int j = 0; j < 4; j++) {
        int d = d0 + j;
        float qmb = 0.f, kmb = 0.f;
#pragma unroll
        for (int u = 0; u < 16; u++) {
            qmb += pqs[u] * qq_mb[u*1024 + d];
            kmb += pks[u] * qk_mb[u*1024 + d];
        }
        float qq = fq*qmb + (1.f - fq)*cqp[j];
        float kq = fk*kmb + (1.f - fk)*ckp[j];
        outq[j] = (0.7f*qvp[j] + 0.3f*qq) * 0.125f;
        outk[j] =  0.7f*kvp[j] + 0.3f*kq;
    }
    int h = d0 >> 6, dh = d0 & 63;
    int bh = b*16 + h;
    *(float4*)&g_Qa[((size_t)bh*SEQ + s)*AD + dh] = make_float4(outq[0],outq[1],outq[2],outq[3]);
#pragma unroll
    for (int j = 0; j < 4; j++)
        g_Kt[((size_t)bh*AD + dh + j)*SEQ + s] = outk[j];
    *(float4*)&g_Va[((size_t)bh*SEQ + s)*HD + dh] = vv;
    int h2 = t >> 4, u = t & 15;
    int bh2 = b*16 + h2;
    g_Qa[((size_t)bh2*SEQ + s)*AD + 64 + u] = 0.1f * pqs[u];
    g_Kt[((size_t)bh2*AD + 64 + u)*SEQ + s] = pks[u];
}

// ---------------- flash attention ----------------
#define FLASH_SMEM_FLOATS (64*AD + AD*KS + 64*KS)
#define FLASH_SMEM_BYTES  (FLASH_SMEM_FLOATS * 4)

__global__ __launch_bounds__(256) void flash_kernel(float* __restrict__ w_out)
{
    extern __shared__ float sm[];
    float* Qs = sm;
    float* Ksm = Qs + 64*AD;
    float* Vs = Ksm + AD*KS;
    int qt = blockIdx.x, bh = blockIdx.y;
    int t = threadIdx.x;
    int ty = t >> 4, tx = t & 15;

    const float* Qg  = g_Qa + ((size_t)bh*SEQ + qt*64)*AD;
    const float* Ktg = g_Kt + (size_t)bh*AD*SEQ;
    const float* Vg  = g_Va + (size_t)bh*SEQ*HD;

    for (int idx = t; idx < 64*AD/4; idx += 256)
        *(float4*)&Qs[idx*4] = *(const float4*)&Qg[idx*4];

    float mrow[4], lrow[4], O[4][4];
#pragma unroll
    for (int ii = 0; ii < 4; ii++) {
        mrow[ii] = -1e30f; lrow[ii] = 0.f;
#pragma unroll
        for (int jj = 0; jj < 4; jj++) O[ii][jj] = 0.f;
    }

#pragma unroll 1
    for (int kt = 0; kt < 32; kt++) {
        __syncthreads();
        for (int idx = t; idx < AD*16; idx += 256) {
            int k = idx >> 4, n4 = idx & 15;
            *(float4*)&Ksm[k*KS + n4*4] = *(const float4*)&Ktg[(size_t)k*SEQ + kt*64 + n4*4];
        }
        for (int idx = t; idx < 64*16; idx += 256) {
            int j = idx >> 4, n4 = idx & 15;
            *(float4*)&Vs[j*KS + n4*4] = *(const float4*)&Vg[(size_t)(kt*64 + j)*HD + n4*4];
        }
        __syncthreads();

        float s[4][4];
#pragma unroll
        for (int ii = 0; ii < 4; ii++)
#pragma unroll
            for (int jj = 0; jj < 4; jj++) s[ii][jj] = 0.f;

#pragma unroll
        for (int k0 = 0; k0 < AD; k0 += 4) {
            float4 aa[4], bb[4];
#pragma unroll
            for (int ii = 0; ii < 4; ii++)
                aa[ii] = *(const float4*)&Qs[(ty*4+ii)*AD + k0];
#pragma unroll
            for (int c = 0; c < 4; c++)
                bb[c] = *(const float4*)&Ksm[(k0+c)*KS + tx*4];
#pragma unroll
            for (int ii = 0; ii < 4; ii++) {
                const float* av = (const float*)&aa[ii];
#pragma unroll
                for (int jj = 0; jj < 4; jj++) {
                    s[ii][jj] += av[0]*((const float*)&bb[0])[jj]
                               + av[1]*((const float*)&bb[1])[jj]
                               + av[2]*((const float*)&bb[2])[jj]
                               + av[3]*((const float*)&bb[3])[jj];
                }
            }
        }

#pragma unroll
        for (int ii = 0; ii < 4; ii++) {
            float mx = fmaxf(fmaxf(s[ii][0], s[ii][1]), fmaxf(s[ii][2], s[ii][3]));
#pragma unroll
            for (int off = 8; off; off >>= 1)
                mx = fmaxf(mx, __shfl_xor_sync(0xffffffffu, mx, off));
            float mn = fmaxf(mrow[ii], mx);
            float alpha = __expf(mrow[ii] - mn);
            mrow[ii] = mn;
            float rs = 0.f;
#pragma unroll
            for (int jj = 0; jj < 4; jj++) {
                float p = __expf(s[ii][jj] - mn);
                s[ii][jj] = p;
                rs += p;
            }
#pragma unroll
            for (int off = 8; off; off >>= 1)
                rs += __shfl_xor_sync(0xffffffffu, rs, off);
            lrow[ii] = lrow[ii]*alpha + rs;
#pragma unroll
            for (int jj = 0; jj < 4; jj++) O[ii][jj] *= alpha;
            if (tx == 0)
                g_mt[((size_t)bh*SEQ + qt*64 + ty*4 + ii)*32 + kt] = mn;
        }

        {
            float* wr = w_out + ((size_t)bh*SEQ + qt*64 + ty*4)*SEQ + (size_t)kt*64 + tx*4;
#pragma unroll
            for (int ii = 0; ii < 4; ii++)
                *(float4*)&wr[(size_t)ii*SEQ] =
                    make_float4(s[ii][0], s[ii][1], s[ii][2], s[ii][3]);
        }

        __syncthreads();
        {
            float* Ps = Ksm;
#pragma unroll
            for (int ii = 0; ii < 4; ii++)
                *(float4*)&Ps[(ty*4+ii)*KS + tx*4] =
                    make_float4(s[ii][0], s[ii][1], s[ii][2], s[ii][3]);
        }
        __syncthreads();

        {
            const float* Ps = Ksm;
#pragma unroll
            for (int j0 = 0; j0 < 64; j0 += 4) {
                float4 aa[4], bb[4];
#pragma unroll
                for (int ii = 0; ii < 4; ii++)
                    aa[ii] = *(const float4*)&Ps[(ty*4+ii)*KS + j0];
#pragma unroll
                for (int c = 0; c < 4; c++)
                    bb[c] = *(const float4*)&Vs[(j0+c)*KS + tx*4];
#pragma unroll
                for (int ii = 0; ii < 4; ii++) {
                    const float* av = (const float*)&aa[ii];
#pragma unroll
                    for (int jj = 0; jj < 4; jj++) {
                        O[ii][jj] += av[0]*((const float*)&bb[0])[jj]
                                   + av[1]*((const float*)&bb[1])[jj]
                                   + av[2]*((const float*)&bb[2])[jj]
                                   + av[3]*((const float*)&bb[3])[jj];
                    }
                }
            }
        }
    }

    int b = bh >> 4, h = bh & 15;
#pragma unroll
    for (int ii = 0; ii < 4; ii++) {
        int row = qt*64 + ty*4 + ii;
        float inv = 1.f / lrow[ii];
        *(float4*)&g_att[((size_t)b*SEQ + row)*1024 + h*64 + tx*4] =
            make_float4(O[ii][0]*inv, O[ii][1]*inv, O[ii][2]*inv, O[ii][3]*inv);
        if (tx == 0) {
            g_m[(size_t)bh*SEQ + row] = mrow[ii];
            g_l[(size_t)bh*SEQ + row] = lrow[ii];
        }
    }
}

// ---------------- normalize w ----------------
__global__ __launch_bounds__(256) void norm_w_kernel(float* __restrict__ w)
{
    size_t idx = (size_t)blockIdx.x * 256 + threadIdx.x;
    size_t e0 = idx * 4;
    size_t row = e0 >> 11;
    int kt = (int)((e0 & 2047) >> 6);
    float f = __expf(g_mt[row*32 + kt] - g_m[row]) / g_l[row];
    float4 v = *(float4*)&w[e0];
    v.x *= f; v.y *= f; v.z *= f; v.w *= f;
    *(float4*)&w[e0] = v;
}

// ---------------- layernorm ----------------
__global__ __launch_bounds__(256) void ln_kernel(const float* __restrict__ gam,
    const float* __restrict__ bet, float* __restrict__ y)
{
    int i = blockIdx.x, t = threadIdx.x;
    float4 v = *(const float4*)&g_res[(size_t)i*1024 + t*4];
    float s  = v.x + v.y + v.z + v.w;
    float ss = v.x*v.x + v.y*v.y + v.z*v.z + v.w*v.w;
#pragma unroll
    for (int off = 16; off; off >>= 1) {
        s  += __shfl_xor_sync(0xffffffffu, s,  off);
        ss += __shfl_xor_sync(0xffffffffu, ss, off);
    }
    __shared__ float as[8], ass[8];
    if ((t & 31) == 0) { as[t >> 5] = s; ass[t >> 5] = ss; }
    __syncthreads();
    float S = 0.f, SS = 0.f;
#pragma unroll
    for (int u = 0; u < 8; u++) { S += as[u]; SS += ass[u]; }
    float mu  = S * (1.f/1024.f);
    float var = SS * (1.f/1024.f) - mu*mu;
    float inv = rsqrtf(var + 1e-5f);
    float4 gg = *(const float4*)&gam[t*4];
    float4 bb = *(const float4*)&bet[t*4];
    float4 o;
    o.x = (v.x - mu)*inv*gg.x + bb.x;
    o.y = (v.y - mu)*inv*gg.y + bb.y;
    o.z = (v.z - mu)*inv*gg.z + bb.z;
    o.w = (v.w - mu)*inv*gg.w + bb.w;
    *(float4*)&y[(size_t)i*1024 + t*4] = o;
}

// ---------------- launch ----------------
extern "C" void kernel_launch(void* const* d_in, const int* in_sizes, int n_in,
                              void* d_out, int out_size)
{
    const float* x       = (const float*)d_in[0];
    const float* Wq      = (const float*)d_in[1];
    const float* bq      = (const float*)d_in[2];
    const float* Wk      = (const float*)d_in[3];
    const float* bk      = (const float*)d_in[4];
    const float* Wv      = (const float*)d_in[5];
    const float* bv      = (const float*)d_in[6];
    const float* Wo      = (const float*)d_in[7];
    const float* bo      = (const float*)d_in[8];
    const float* ln_g    = (const float*)d_in[9];
    const float* ln_b    = (const float*)d_in[10];
    const float* qq_W    = (const float*)d_in[11];
    const float* qq_b    = (const float*)d_in[12];
    const float* qq_qw_r = (const float*)d_in[13];
    const float* qq_qw_i = (const float*)d_in[14];
    const float* qq_sg   = (const float*)d_in[15];
    const float* qq_em   = (const float*)d_in[16];
    const float* qq_mb   = (const float*)d_in[17];
    const float* qk_W    = (const float*)d_in[18];
    const float* qk_b    = (const float*)d_in[19];
    const float* qk_qw_r = (const float*)d_in[20];
    const float* qk_qw_i = (const float*)d_in[21];
    const float* qk_sg   = (const float*)d_in[22];
    const float* qk_em   = (const float*)d_in[23];
    const float* qk_mb   = (const float*)d_in[24];

    float* y = (float*)d_out;
    float* w = y + (size_t)MROWS*DMODEL;

    float *pQ, *pK, *pV, *pCq, *pCk, *pAtt, *pRes;
    cudaGetSymbolAddress((void**)&pQ,   g_Q);
    cudaGetSymbolAddress((void**)&pK,   g_K);
    cudaGetSymbolAddress((void**)&pV,   g_V);
    cudaGetSymbolAddress((void**)&pCq,  g_Cq);
    cudaGetSymbolAddress((void**)&pCk,  g_Ck);
    cudaGetSymbolAddress((void**)&pAtt, g_att);
    cudaGetSymbolAddress((void**)&pRes, g_res);
    __nv_bfloat16 *pXh, *pXl, *pAh, *pAl, *pWh, *pWl;
    cudaGetSymbolAddress((void**)&pXh, g_xhi);
    cudaGetSymbolAddress((void**)&pXl, g_xlo);
    cudaGetSymbolAddress((void**)&pAh, g_ahi);
    cudaGetSymbolAddress((void**)&pAl, g_alo);
    cudaGetSymbolAddress((void**)&pWh, g_Whi);
    cudaGetSymbolAddress((void**)&pWl, g_Wlo);

    cudaFuncSetAttribute(flash_kernel,
        cudaFuncAttributeMaxDynamicSharedMemorySize, FLASH_SMEM_BYTES);
    cudaFuncSetAttribute(mma_gemm_kernel,
        cudaFuncAttributeMaxDynamicSharedMemorySize, GEMM_SMEM);

    prep_m_kernel<<<1, 256>>>(qq_qw_r, qq_qw_i, qk_qw_r, qk_qw_i, qq_em, qk_em);
    quantum_kernel<<<MROWS, 128>>>(x, qq_sg, qk_sg);

    // convert inputs
    aconv_kernel<<<MROWS*DMODEL/(256*4), 256>>>(x, pXh, pXl);
    dim3 wg(32, 32), wb(32, 8);
    const size_t WSZ = (size_t)DMODEL*DMODEL;
    wconv_kernel<<<wg, wb>>>(Wq,   pWh + 0*WSZ, pWl + 0*WSZ);
    wconv_kernel<<<wg, wb>>>(Wk,   pWh + 1*WSZ, pWl + 1*WSZ);
    wconv_kernel<<<wg, wb>>>(Wv,   pWh + 2*WSZ, pWl + 2*WSZ);
    wconv_kernel<<<wg, wb>>>(qq_W, pWh + 3*WSZ, pWl + 3*WSZ);
    wconv_kernel<<<wg, wb>>>(qk_W, pWh + 4*WSZ, pWl + 4*WSZ);
    wconv_kernel<<<wg, wb>>>(Wo,   pWh + 5*WSZ, pWl + 5*WSZ);

    // tensor-core GEMMs (128x128 tiles)
    dim3 gg(32, 8);
    mma_gemm_kernel<<<gg, 256, GEMM_SMEM>>>(pXh, pXl, pWh + 0*WSZ, pWl + 0*WSZ, bq,   nullptr, pQ,  0);
    mma_gemm_kernel<<<gg, 256, GEMM_SMEM>>>(pXh, pXl, pWh + 1*WSZ, pWl + 1*WSZ, bk,   nullptr, pK,  0);
    mma_gemm_kernel<<<gg, 256, GEMM_SMEM>>>(pXh, pXl, pWh + 2*WSZ, pWl + 2*WSZ, bv,   nullptr, pV,  0);
    mma_gemm_kernel<<<gg, 256, GEMM_SMEM>>>(pXh, pXl, pWh + 3*WSZ, pWl + 3*WSZ, qq_b, nullptr, pCq, 1);
    mma_gemm_kernel<<<gg, 256, GEMM_SMEM>>>(pXh, pXl, pWh + 4*WSZ, pWl + 4*WSZ, qk_b, nullptr, pCk, 1);

    combine_kernel<<<MROWS, 256>>>(qq_mb, qk_mb);

    dim3 fg(32, 32);
    flash_kernel<<<fg, 256, FLASH_SMEM_BYTES>>>(w);

    norm_w_kernel<<<(NBH*(size_t)SEQ*SEQ)/(4*256), 256>>>(w);

    // output projection: att @ Wo + bo + x
    aconv_kernel<<<MROWS*DMODEL/(256*4), 256>>>(pAtt, pAh, pAl);
    mma_gemm_kernel<<<gg, 256, GEMM_SMEM>>>(pAh, pAl, pWh + 5*WSZ, pWl + 5*WSZ, bo, x, pRes, 0);

    ln_kernel<<<MROWS, 256>>>(ln_g, ln_b, y);
}

// round 5
// speedup vs baseline: 2.2565x; 1.6550x over previous
#include <cuda_runtime.h>
#include <cuda_bf16.h>
#include <cstdint>
#include <math.h>

#define MROWS 4096
#define DMODEL 1024
#define NH 16
#define HD 64
#define QD 16
#define SEQ 2048
#define NBH 32
#define AD 80

// ---------------- scratch ----------------
__device__ float g_Q[MROWS*DMODEL];
__device__ float g_K[MROWS*DMODEL];
__device__ float g_V[MROWS*DMODEL];
__device__ float g_Cq[MROWS*DMODEL];
__device__ float g_Ck[MROWS*DMODEL];
__device__ float g_att[MROWS*DMODEL];
__device__ float g_res[MROWS*DMODEL];
__device__ float g_Va[NBH*SEQ*HD];
__device__ float g_probs_q[MROWS*QD];
__device__ float g_probs_k[MROWS*QD];
__device__ float g_fw_q[MROWS];
__device__ float g_fw_k[MROWS];
__device__ float g_m[NBH*SEQ];
__device__ float g_l[NBH*SEQ];
__device__ float g_mt[NBH*SEQ*16];    // running max snapshot per 128-key tile
__device__ float g_M[4*256];

// bf16 split buffers
__device__ __nv_bfloat16 g_xhi[MROWS*DMODEL];
__device__ __nv_bfloat16 g_xlo[MROWS*DMODEL];
__device__ __nv_bfloat16 g_ahi[MROWS*DMODEL];
__device__ __nv_bfloat16 g_alo[MROWS*DMODEL];
__device__ __nv_bfloat16 g_Whi[6*DMODEL*DMODEL];   // [widx][n][k]
__device__ __nv_bfloat16 g_Wlo[6*DMODEL*DMODEL];
// flash operands (bf16 hi/lo)
__device__ __nv_bfloat16 g_Qah[NBH*SEQ*AD];   // [bh][s][80] = [0.125*Qf, 0.1*qp]
__device__ __nv_bfloat16 g_Qal[NBH*SEQ*AD];
__device__ __nv_bfloat16 g_Kah[NBH*SEQ*AD];   // [bh][s][80] = [Kf, kp]
__device__ __nv_bfloat16 g_Kal[NBH*SEQ*AD];
__device__ __nv_bfloat16 g_Vth[NBH*HD*SEQ];   // [bh][d][s]
__device__ __nv_bfloat16 g_Vtl[NBH*HD*SEQ];

// ---------------- helpers ----------------
__device__ __forceinline__ uint32_t smem_u32(const void* p) {
    uint32_t a;
    asm("{ .reg .u64 t; cvta.to.shared.u64 t, %1; cvt.u32.u64 %0, t; }" : "=r"(a) : "l"(p));
    return a;
}
__device__ __forceinline__ void cp16(uint32_t dst, const void* src) {
    asm volatile("cp.async.cg.shared.global [%0], [%1], 16;\n" :: "r"(dst), "l"(src));
}
__device__ __forceinline__ void ldsm4(uint32_t* r, uint32_t addr) {
    asm volatile("ldmatrix.sync.aligned.m8n8.x4.shared.b16 {%0,%1,%2,%3}, [%4];"
        : "=r"(r[0]), "=r"(r[1]), "=r"(r[2]), "=r"(r[3]) : "r"(addr));
}
__device__ __forceinline__ void ldsm2(uint32_t* r, uint32_t addr) {
    asm volatile("ldmatrix.sync.aligned.m8n8.x2.shared.b16 {%0,%1}, [%2];"
        : "=r"(r[0]), "=r"(r[1]) : "r"(addr));
}
__device__ __forceinline__ void mma16816(float* d, const uint32_t* a, const uint32_t* b) {
    asm volatile("mma.sync.aligned.m16n8k16.row.col.f32.bf16.bf16.f32 "
        "{%0,%1,%2,%3}, {%4,%5,%6,%7}, {%8,%9}, {%0,%1,%2,%3};"
        : "+f"(d[0]), "+f"(d[1]), "+f"(d[2]), "+f"(d[3])
        : "r"(a[0]), "r"(a[1]), "r"(a[2]), "r"(a[3]), "r"(b[0]), "r"(b[1]));
}

// ---------------- conversions ----------------
__global__ __launch_bounds__(256) void aconv_kernel(const float* __restrict__ a,
    __nv_bfloat16* __restrict__ hi, __nv_bfloat16* __restrict__ lo)
{
    size_t i = ((size_t)blockIdx.x * 256 + threadIdx.x) * 4;
    float4 v = *(const float4*)&a[i];
    float vv[4] = {v.x, v.y, v.z, v.w};
    ushort4 h, l;
    unsigned short* hp = &h.x; unsigned short* lp = &l.x;
#pragma unroll
    for (int j = 0; j < 4; j++) {
        __nv_bfloat16 hb = __float2bfloat16(vv[j]);
        __nv_bfloat16 lb = __float2bfloat16(vv[j] - __bfloat162float(hb));
        hp[j] = __bfloat16_as_ushort(hb);
        lp[j] = __bfloat16_as_ushort(lb);
    }
    *(ushort4*)&hi[i] = h;
    *(ushort4*)&lo[i] = l;
}

// W [k][n] f32 -> hi/lo [n][k] bf16
__global__ __launch_bounds__(256) void wconv_kernel(const float* __restrict__ W,
    __nv_bfloat16* __restrict__ hi, __nv_bfloat16* __restrict__ lo)
{
    __shared__ float tile[32][33];
    int bx = blockIdx.x * 32;
    int by = blockIdx.y * 32;
    int tx = threadIdx.x, ty = threadIdx.y;
#pragma unroll
    for (int i = 0; i < 32; i += 8)
        tile[ty + i][tx] = W[(size_t)(by + ty + i) * 1024 + bx + tx];
    __syncthreads();
#pragma unroll
    for (int i = 0; i < 32; i += 8) {
        int n = bx + ty + i, k = by + tx;
        float v = tile[tx][ty + i];
        __nv_bfloat16 hb = __float2bfloat16(v);
        hi[(size_t)n * 1024 + k] = hb;
        lo[(size_t)n * 1024 + k] = __float2bfloat16(v - __bfloat162float(hb));
    }
}

// ---------------- mma.sync split-bf16 GEMM (verified round 4) ----------------
#define SROW 40
#define MAT_E (128*SROW)
#define SST_E (4*MAT_E)
#define GEMM_SMEM (2*SST_E*2)

__device__ __forceinline__ void load_chunk_mm(uint32_t sb, int t, int m0, int n0, int k0,
    const __nv_bfloat16* Ahi, const __nv_bfloat16* Alo,
    const __nv_bfloat16* Bhi, const __nv_bfloat16* Blo)
{
#pragma unroll
    for (int i = 0; i < 2; i++) {
        int cid = i * 256 + t;
        int row = cid >> 2, c = cid & 3;
        uint32_t off = (uint32_t)(row * (SROW*2) + c * 16);
        cp16(sb + off,              (const char*)(Ahi + (size_t)(m0 + row) * 1024 + k0) + c * 16);
        cp16(sb + MAT_E*2 + off,    (const char*)(Alo + (size_t)(m0 + row) * 1024 + k0) + c * 16);
        cp16(sb + 2*MAT_E*2 + off,  (const char*)(Bhi + (size_t)(n0 + row) * 1024 + k0) + c * 16);
        cp16(sb + 3*MAT_E*2 + off,  (const char*)(Blo + (size_t)(n0 + row) * 1024 + k0) + c * 16);
    }
    asm volatile("cp.async.commit_group;\n" ::: "memory");
}

__global__ __launch_bounds__(256) void mma_gemm_kernel(
    const __nv_bfloat16* __restrict__ Ahi, const __nv_bfloat16* __restrict__ Alo,
    const __nv_bfloat16* __restrict__ Bhi, const __nv_bfloat16* __restrict__ Blo,
    const float* __restrict__ bias, const float* __restrict__ resid,
    float* __restrict__ out, int do_tanh)
{
    extern __shared__ char smem[];
    uint32_t sb = smem_u32(smem);
    int t = threadIdx.x;
    int warp = t >> 5, lane = t & 31;
    int wm = warp & 1, wn = warp >> 1;
    int m0 = blockIdx.x * 128, n0 = blockIdx.y * 128;

    float acc[4][4][4];
#pragma unroll
    for (int a = 0; a < 4; a++)
#pragma unroll
        for (int b = 0; b < 4; b++)
#pragma unroll
            for (int c = 0; c < 4; c++) acc[a][b][c] = 0.f;

    int aq = lane >> 3;
    int arow = (aq & 1) * 8 + (lane & 7);
    int akoff = (aq >> 1) * 8;
    int brow = lane & 7;
    int bkoff = ((lane >> 3) & 1) * 8;

    load_chunk_mm(sb, t, m0, n0, 0, Ahi, Alo, Bhi, Blo);

#pragma unroll 1
    for (int c = 0; c < 32; c++) {
        if (c < 31)
            load_chunk_mm(sb + ((c + 1) & 1) * SST_E * 2, t, m0, n0, (c + 1) * 32, Ahi, Alo, Bhi, Blo);
        if (c < 31) asm volatile("cp.async.wait_group 1;\n" ::: "memory");
        else        asm volatile("cp.async.wait_group 0;\n" ::: "memory");
        __syncthreads();

        uint32_t st = sb + (c & 1) * SST_E * 2;
#pragma unroll
        for (int k16 = 0; k16 < 2; k16++) {
            int kb = k16 * 16;
            uint32_t ah[4][4], al[4][4];
#pragma unroll
            for (int mt = 0; mt < 4; mt++) {
                uint32_t aaddr = st + (uint32_t)(((wm*64 + mt*16 + arow) * SROW + kb + akoff) * 2);
                ldsm4(ah[mt], aaddr);
                ldsm4(al[mt], aaddr + MAT_E*2);
            }
#pragma unroll
            for (int nt = 0; nt < 4; nt++) {
                uint32_t baddr = st + 2*MAT_E*2 +
                    (uint32_t)(((wn*32 + nt*8 + brow) * SROW + kb + bkoff) * 2);
                uint32_t bh[2], bl[2];
                ldsm2(bh, baddr);
                ldsm2(bl, baddr + MAT_E*2);
#pragma unroll
                for (int mt = 0; mt < 4; mt++) {
                    mma16816(acc[mt][nt], ah[mt], bh);
                    mma16816(acc[mt][nt], ah[mt], bl);
                    mma16816(acc[mt][nt], al[mt], bh);
                }
            }
        }
        __syncthreads();
    }

    int rin = lane >> 2, cin = (lane & 3) * 2;
#pragma unroll
    for (int mt = 0; mt < 4; mt++) {
#pragma unroll
        for (int nt = 0; nt < 4; nt++) {
            int n = n0 + wn*32 + nt*8 + cin;
            float b0 = bias[n], b1 = bias[n + 1];
#pragma unroll
            for (int half = 0; half < 2; half++) {
                int m = m0 + wm*64 + mt*16 + rin + half*8;
                float v0 = acc[mt][nt][half*2 + 0] + b0;
                float v1 = acc[mt][nt][half*2 + 1] + b1;
                if (resid) {
                    const float* rr = resid + (size_t)m * 1024 + n;
                    v0 += rr[0]; v1 += rr[1];
                }
                if (do_tanh) { v0 = tanhf(v0); v1 = tanhf(v1); }
                *(float2*)&out[(size_t)m * 1024 + n] = make_float2(v0, v1);
            }
        }
    }
}

// ---------------- prep: M = qw @ em ----------------
__global__ void prep_m_kernel(const float* __restrict__ qqr, const float* __restrict__ qqi,
                              const float* __restrict__ qkr, const float* __restrict__ qki,
                              const float* __restrict__ qqem, const float* __restrict__ qkem)
{
    int t = threadIdx.x;
    int u = t >> 4, v = t & 15;
    float a = 0.f, b = 0.f, c = 0.f, d = 0.f;
#pragma unroll
    for (int w = 0; w < 16; w++) {
        float e1 = qqem[w*16+v], e2 = qkem[w*16+v];
        a += qqr[u*16+w]*e1;
        b += qqi[u*16+w]*e1;
        c += qkr[u*16+w]*e2;
        d += qki[u*16+w]*e2;
    }
    g_M[t] = a; g_M[256+t] = b; g_M[512+t] = c; g_M[768+t] = d;
}

// ---------------- quantum small path ----------------
__global__ __launch_bounds__(128) void quantum_kernel(
    const float* __restrict__ x, const float* __restrict__ sgq, const float* __restrict__ sgk)
{
    __shared__ float xs[1024];
    __shared__ float part[8][16];
    __shared__ float qss[16];
    __shared__ float prob_s[16];
    int i = blockIdx.x;
    int t = threadIdx.x;
#pragma unroll
    for (int c = 0; c < 2; c++)
        *(float4*)&xs[(t + c*128)*4] = *(const float4*)&x[(size_t)i*1024 + (t + c*128)*4];
    __syncthreads();
    int tt = t & 15, pp = t >> 4;
#pragma unroll 1
    for (int side = 0; side < 2; side++) {
        const float* sg = side ? sgk : sgq;
        float acc = 0.f;
        int base = pp * 128;
        for (int d = 0; d < 128; d++)
            acc += xs[base + d] * sg[(base + d)*16 + tt];
        part[pp][tt] = acc;
        __syncthreads();
        if (t < 16) {
            float q = 0.f;
#pragma unroll
            for (int p = 0; p < 8; p++) q += part[p][t];
            qss[t] = q;
        }
        __syncthreads();
        if (t < 16) {
            const float* Mr = g_M + side*512;
            const float* Mi = Mr + 256;
            float er = 0.f, ei = 0.f;
#pragma unroll
            for (int u = 0; u < 16; u++) {
                er += qss[u]*Mr[u*16+t];
                ei += qss[u]*Mi[u*16+t];
            }
            float pr = er*er + ei*ei;
            prob_s[t] = pr;
            (side ? g_probs_k : g_probs_q)[i*16 + t] = pr;
        }
        __syncthreads();
        if (t == 0) {
            float ms = 0.f;
#pragma unroll
            for (int u = 0; u < 16; u++) ms += prob_s[u];
            ms *= (1.f/16.f);
            (side ? g_fw_k : g_fw_q)[i] = 1.f/(1.f + __expf(-ms));
        }
        __syncthreads();
    }
}

// ---------------- combine: build Qa / Ka (bf16 hi/lo) and Va ----------------
__global__ __launch_bounds__(256) void combine_kernel(
    const float* __restrict__ qq_mb, const float* __restrict__ qk_mb)
{
    int i = blockIdx.x;
    int b = i >> 11, s = i & 2047;
    int t = threadIdx.x;
    __shared__ float pqs[16], pks[16];
    if (t < 16) pqs[t] = g_probs_q[i*16 + t];
    else if (t < 32) pks[t-16] = g_probs_k[i*16 + (t-16)];
    __syncthreads();
    float fq = g_fw_q[i], fk = g_fw_k[i];
    int d0 = t * 4;
    float4 qv = *(const float4*)&g_Q [(size_t)i*1024 + d0];
    float4 kv = *(const float4*)&g_K [(size_t)i*1024 + d0];
    float4 vv = *(const float4*)&g_V [(size_t)i*1024 + d0];
    float4 cq = *(const float4*)&g_Cq[(size_t)i*1024 + d0];
    float4 ck = *(const float4*)&g_Ck[(size_t)i*1024 + d0];
    const float* qvp = (const float*)&qv;
    const float* kvp = (const float*)&kv;
    const float* cqp = (const float*)&cq;
    const float* ckp = (const float*)&ck;
    ushort4 qh4, ql4, kh4, kl4;
    unsigned short* qhp = &qh4.x; unsigned short* qlp = &ql4.x;
    unsigned short* khp = &kh4.x; unsigned short* klp = &kl4.x;
#pragma unroll
    for (int j = 0; j < 4; j++) {
        int d = d0 + j;
        float qmb = 0.f, kmb = 0.f;
#pragma unroll
        for (int u = 0; u < 16; u++) {
            qmb += pqs[u] * qq_mb[u*1024 + d];
            kmb += pks[u] * qk_mb[u*1024 + d];
        }
        float qq = fq*qmb + (1.f - fq)*cqp[j];
        float kq = fk*kmb + (1.f - fk)*ckp[j];
        float oq = (0.7f*qvp[j] + 0.3f*qq) * 0.125f;
        float ok =  0.7f*kvp[j] + 0.3f*kq;
        __nv_bfloat16 hb = __float2bfloat16(oq);
        qhp[j] = __bfloat16_as_ushort(hb);
        qlp[j] = __bfloat16_as_ushort(__float2bfloat16(oq - __bfloat162float(hb)));
        hb = __float2bfloat16(ok);
        khp[j] = __bfloat16_as_ushort(hb);
        klp[j] = __bfloat16_as_ushort(__float2bfloat16(ok - __bfloat162float(hb)));
    }
    int h = d0 >> 6, dh = d0 & 63;
    int bh = b*16 + h;
    size_t qb = ((size_t)bh*SEQ + s)*AD + dh;
    *(ushort4*)&g_Qah[qb] = qh4;
    *(ushort4*)&g_Qal[qb] = ql4;
    *(ushort4*)&g_Kah[qb] = kh4;
    *(ushort4*)&g_Kal[qb] = kl4;
    *(float4*)&g_Va[((size_t)bh*SEQ + s)*HD + dh] = vv;
    // interference tails
    int h2 = t >> 4, u = t & 15;
    int bh2 = b*16 + h2;
    size_t tb = ((size_t)bh2*SEQ + s)*AD + 64 + u;
    float tv = 0.1f * pqs[u];
    __nv_bfloat16 th = __float2bfloat16(tv);
    g_Qah[tb] = th;
    g_Qal[tb] = __float2bfloat16(tv - __bfloat162float(th));
    float tk = pks[u];
    th = __float2bfloat16(tk);
    g_Kah[tb] = th;
    g_Kal[tb] = __float2bfloat16(tk - __bfloat162float(th));
}

// ---------------- V transpose: Va [bh][s][64] f32 -> Vt hi/lo [bh][d][s] bf16 ----------------
__global__ __launch_bounds__(256) void vtrans_kernel()
{
    __shared__ float tile[64][65];
    int s0 = blockIdx.x * 64, bh = blockIdx.y;
    int t = threadIdx.x;
    int r = t >> 2, c4 = (t & 3) * 16;
    const float* src = g_Va + ((size_t)bh*SEQ + s0 + r)*HD + c4;
#pragma unroll
    for (int j = 0; j < 16; j += 4) {
        float4 v = *(const float4*)&src[j];
        tile[r][c4 + j + 0] = v.x;
        tile[r][c4 + j + 1] = v.y;
        tile[r][c4 + j + 2] = v.z;
        tile[r][c4 + j + 3] = v.w;
    }
    __syncthreads();
    int d = t >> 2, sc = (t & 3) * 16;
    ushort4 ho[4], lo[4];
#pragma unroll
    for (int j = 0; j < 16; j++) {
        float v = tile[sc + j][d];
        __nv_bfloat16 hb = __float2bfloat16(v);
        (&ho[j >> 2].x)[j & 3] = __bfloat16_as_ushort(hb);
        (&lo[j >> 2].x)[j & 3] = __bfloat16_as_ushort(__float2bfloat16(v - __bfloat162float(hb)));
    }
    size_t base = ((size_t)bh*HD + d)*SEQ + s0 + sc;
#pragma unroll
    for (int j = 0; j < 4; j++) {
        *(ushort4*)&g_Vth[base + j*4] = ho[j];
        *(ushort4*)&g_Vtl[base + j*4] = lo[j];
    }
}

// ---------------- flash attention with mma.sync ----------------
// smem byte offsets
#define QLOB 11264
#define ST0B 22528
#define STAGEB 79872
#define KLOB 22528
#define VTHB 45056
#define VTLB 62464
#define PHIB 182272
#define PLOB 199680
#define REDB 217088
#define FLASH2_SMEM 218112

__device__ __forceinline__ void load_q_f(uint32_t sb, int t, int bh, int qt)
{
    const char* qh = (const char*)(g_Qah + ((size_t)bh*SEQ + qt*64)*AD);
    const char* ql = (const char*)(g_Qal + ((size_t)bh*SEQ + qt*64)*AD);
#pragma unroll 1
    for (int i = t; i < 640; i += 256) {
        int row = i / 10, c = i % 10;
        uint32_t off = (uint32_t)(row*176 + c*16);
        cp16(sb + off, qh + (size_t)row*160 + c*16);
        cp16(sb + QLOB + off, ql + (size_t)row*160 + c*16);
    }
}

__device__ __forceinline__ void load_kv_f(uint32_t stb, int t, int bh, int k0)
{
    const char* kh = (const char*)(g_Kah + ((size_t)bh*SEQ + k0)*AD);
    const char* kl = (const char*)(g_Kal + ((size_t)bh*SEQ + k0)*AD);
#pragma unroll 1
    for (int i = t; i < 1280; i += 256) {
        int row = i / 10, c = i % 10;
        uint32_t off = (uint32_t)(row*176 + c*16);
        cp16(stb + off, kh + (size_t)row*160 + c*16);
        cp16(stb + KLOB + off, kl + (size_t)row*160 + c*16);
    }
    const __nv_bfloat16* vh = g_Vth + (size_t)bh*HD*SEQ + k0;
    const __nv_bfloat16* vl = g_Vtl + (size_t)bh*HD*SEQ + k0;
#pragma unroll 1
    for (int i = t; i < 1024; i += 256) {
        int d = i >> 4, c = i & 15;
        uint32_t off = (uint32_t)(d*272 + c*16);
        cp16(stb + VTHB + off, (const char*)(vh + (size_t)d*SEQ) + c*16);
        cp16(stb + VTLB + off, (const char*)(vl + (size_t)d*SEQ) + c*16);
    }
    asm volatile("cp.async.commit_group;\n" ::: "memory");
}

__global__ __launch_bounds__(256) void flash_mma_kernel(float* __restrict__ w_out)
{
    extern __shared__ char smem[];
    uint32_t sb = smem_u32(smem);
    float* redm = (float*)(smem + REDB);      // [2][64]
    float* reds = redm + 128;                 // [2][64]
    __nv_bfloat162* Pph = (__nv_bfloat162*)(smem + PHIB);
    __nv_bfloat162* Ppl = (__nv_bfloat162*)(smem + PLOB);

    int qt = blockIdx.x, bh = blockIdx.y;
    int t = threadIdx.x;
    int warp = t >> 5, lane = t & 31;
    int wm = warp & 3, wn = warp >> 2;       // 4 m-strips x 2 n-halves

    int aq = lane >> 3;
    int arow = (aq & 1) * 8 + (lane & 7);
    int akoff = (aq >> 1) * 8;
    int b4n = (lane >> 4) * 8 + (lane & 7);
    int b4k = ((lane >> 3) & 1) * 8;
    int rin = lane >> 2, cin = (lane & 3) * 2;

    load_q_f(sb, t, bh, qt);
    load_kv_f(sb + ST0B, t, bh, 0);
    load_kv_f(sb + ST0B + STAGEB, t, bh, 128);

    float m_run0 = -1e30f, m_run1 = -1e30f;
    float l_run0 = 0.f, l_run1 = 0.f;
    float O[4][4];
#pragma unroll
    for (int a = 0; a < 4; a++)
#pragma unroll
        for (int b = 0; b < 4; b++) O[a][b] = 0.f;
    uint32_t qfh[5][4], qfl[5][4];

    int r0 = wm*16 + rin, r1 = r0 + 8;

#pragma unroll 1
    for (int kt = 0; kt < 16; kt++) {
        if (kt < 15) asm volatile("cp.async.wait_group 1;\n" ::: "memory");
        else         asm volatile("cp.async.wait_group 0;\n" ::: "memory");
        __syncthreads();
        uint32_t st = sb + ST0B + (kt & 1) * STAGEB;

        if (kt == 0) {
#pragma unroll
            for (int ks = 0; ks < 5; ks++) {
                uint32_t qaddr = sb + (uint32_t)(((wm*16 + arow)*88 + ks*16 + akoff) * 2);
                ldsm4(qfh[ks], qaddr);
                ldsm4(qfl[ks], qaddr + QLOB);
            }
        }

        // ---- S = Q @ K^T ----
        float sacc[8][4];
#pragma unroll
        for (int a = 0; a < 8; a++)
#pragma unroll
            for (int b = 0; b < 4; b++) sacc[a][b] = 0.f;
#pragma unroll
        for (int ks = 0; ks < 5; ks++) {
            int kb = ks * 16;
#pragma unroll
            for (int p = 0; p < 4; p++) {
                uint32_t kaddr = st + (uint32_t)(((wn*64 + p*16 + b4n)*88 + kb + b4k) * 2);
                uint32_t kh4[4], kl4[4];
                ldsm4(kh4, kaddr);
                ldsm4(kl4, kaddr + KLOB);
                mma16816(sacc[2*p],   qfh[ks], kh4);
                mma16816(sacc[2*p+1], qfh[ks], kh4+2);
                mma16816(sacc[2*p],   qfh[ks], kl4);
                mma16816(sacc[2*p+1], qfh[ks], kl4+2);
                mma16816(sacc[2*p],   qfl[ks], kh4);
                mma16816(sacc[2*p+1], qfl[ks], kh4+2);
            }
        }

        // ---- online softmax ----
        float lm0 = -1e30f, lm1 = -1e30f;
#pragma unroll
        for (int nt = 0; nt < 8; nt++) {
            lm0 = fmaxf(lm0, fmaxf(sacc[nt][0], sacc[nt][1]));
            lm1 = fmaxf(lm1, fmaxf(sacc[nt][2], sacc[nt][3]));
        }
        lm0 = fmaxf(lm0, __shfl_xor_sync(0xffffffffu, lm0, 1));
        lm0 = fmaxf(lm0, __shfl_xor_sync(0xffffffffu, lm0, 2));
        lm1 = fmaxf(lm1, __shfl_xor_sync(0xffffffffu, lm1, 1));
        lm1 = fmaxf(lm1, __shfl_xor_sync(0xffffffffu, lm1, 2));
        if ((lane & 3) == 0) {
            redm[wn*64 + r0] = lm0;
            redm[wn*64 + r1] = lm1;
        }
        __syncthreads();
        float mn0 = fmaxf(m_run0, fmaxf(redm[r0], redm[64 + r0]));
        float mn1 = fmaxf(m_run1, fmaxf(redm[r1], redm[64 + r1]));
        float al0 = __expf(m_run0 - mn0);
        float al1 = __expf(m_run1 - mn1);
        m_run0 = mn0; m_run1 = mn1;

        float ls0 = 0.f, ls1 = 0.f;
        size_t wrow0 = ((size_t)bh*SEQ + qt*64 + r0) * SEQ + (size_t)kt*128 + wn*64 + cin;
        size_t wrow1 = wrow0 + (size_t)8 * SEQ;
        int pc = wn*32 + (cin >> 1);   // bf162 col index base
#pragma unroll
        for (int nt = 0; nt < 8; nt++) {
            float p0 = __expf(sacc[nt][0] - mn0);
            float p1 = __expf(sacc[nt][1] - mn0);
            float p2 = __expf(sacc[nt][2] - mn1);
            float p3 = __expf(sacc[nt][3] - mn1);
            ls0 += p0 + p1; ls1 += p2 + p3;
            *(float2*)&w_out[wrow0 + nt*8] = make_float2(p0, p1);
            *(float2*)&w_out[wrow1 + nt*8] = make_float2(p2, p3);
            __nv_bfloat16 h0 = __float2bfloat16(p0), h1 = __float2bfloat16(p1);
            __nv_bfloat16 h2 = __float2bfloat16(p2), h3 = __float2bfloat16(p3);
            __nv_bfloat162 hv0; hv0.x = h0; hv0.y = h1;
            __nv_bfloat162 hv1; hv1.x = h2; hv1.y = h3;
            __nv_bfloat162 lv0;
            lv0.x = __float2bfloat16(p0 - __bfloat162float(h0));
            lv0.y = __float2bfloat16(p1 - __bfloat162float(h1));
            __nv_bfloat162 lv1;
            lv1.x = __float2bfloat16(p2 - __bfloat162float(h2));
            lv1.y = __float2bfloat16(p3 - __bfloat162float(h3));
            Pph[r0*68 + pc + nt*4] = hv0;
            Pph[r1*68 + pc + nt*4] = hv1;
            Ppl[r0*68 + pc + nt*4] = lv0;
            Ppl[r1*68 + pc + nt*4] = lv1;
        }
        ls0 += __shfl_xor_sync(0xffffffffu, ls0, 1);
        ls0 += __shfl_xor_sync(0xffffffffu, ls0, 2);
        ls1 += __shfl_xor_sync(0xffffffffu, ls1, 1);
        ls1 += __shfl_xor_sync(0xffffffffu, ls1, 2);
        if ((lane & 3) == 0) {
            reds[wn*64 + r0] = ls0;
            reds[wn*64 + r1] = ls1;
        }
        if (wn == 0 && (lane & 3) == 0) {
            g_mt[((size_t)bh*SEQ + qt*64 + r0)*16 + kt] = mn0;
            g_mt[((size_t)bh*SEQ + qt*64 + r1)*16 + kt] = mn1;
        }
#pragma unroll
        for (int nt = 0; nt < 4; nt++) {
            O[nt][0] *= al0; O[nt][1] *= al0;
            O[nt][2] *= al1; O[nt][3] *= al1;
        }
        __syncthreads();
        l_run0 = l_run0*al0 + reds[r0] + reds[64 + r0];
        l_run1 = l_run1*al1 + reds[r1] + reds[64 + r1];

        // ---- O += P @ V ----
#pragma unroll
        for (int ks = 0; ks < 8; ks++) {
            int kb = ks * 16;
            uint32_t paddr = sb + PHIB + (uint32_t)(((wm*16 + arow)*136 + kb + akoff) * 2);
            uint32_t pf[4], pfl[4];
            ldsm4(pf, paddr);
            ldsm4(pfl, paddr + (PLOB - PHIB));
#pragma unroll
            for (int p = 0; p < 2; p++) {
                uint32_t vaddr = st + VTHB + (uint32_t)(((wn*32 + p*16 + b4n)*136 + kb + b4k) * 2);
                uint32_t vh4[4], vl4[4];
                ldsm4(vh4, vaddr);
                ldsm4(vl4, vaddr + (VTLB - VTHB));
                mma16816(O[2*p],   pf, vh4);
                mma16816(O[2*p+1], pf, vh4+2);
                mma16816(O[2*p],   pf, vl4);
                mma16816(O[2*p+1], pf, vl4+2);
                mma16816(O[2*p],   pfl, vh4);
                mma16816(O[2*p+1], pfl, vh4+2);
            }
        }
        __syncthreads();
        if (kt + 2 < 16) load_kv_f(st, t, bh, (kt + 2) * 128);
    }

    // ---- epilogue ----
    float inv0 = 1.f / l_run0, inv1 = 1.f / l_run1;
    int b = bh >> 4, h = bh & 15;
    int rg0 = qt*64 + r0;
#pragma unroll
    for (int nt = 0; nt < 4; nt++) {
        int d = h*64 + wn*32 + nt*8 + cin;
        *(float2*)&g_att[((size_t)b*SEQ + rg0)*1024 + d] = make_float2(O[nt][0]*inv0, O[nt][1]*inv0);
        *(float2*)&g_att[((size_t)b*SEQ + rg0 + 8)*1024 + d] = make_float2(O[nt][2]*inv1, O[nt][3]*inv1);
    }
    if (wn == 0 && (lane & 3) == 0) {
        g_m[(size_t)bh*SEQ + rg0] = m_run0;
        g_l[(size_t)bh*SEQ + rg0] = l_run0;
        g_m[(size_t)bh*SEQ + rg0 + 8] = m_run1;
        g_l[(size_t)bh*SEQ + rg0 + 8] = l_run1;
    }
}

// ---------------- normalize w ----------------
__global__ __launch_bounds__(256) void norm_w_kernel(float* __restrict__ w)
{
    size_t idx = (size_t)blockIdx.x * 256 + threadIdx.x;
    size_t e0 = idx * 4;
    size_t row = e0 >> 11;
    int kt = (int)((e0 & 2047) >> 7);
    float f = __expf(g_mt[row*16 + kt] - g_m[row]) / g_l[row];
    float4 v = *(float4*)&w[e0];
    v.x *= f; v.y *= f; v.z *= f; v.w *= f;
    *(float4*)&w[e0] = v;
}

// ---------------- layernorm ----------------
__global__ __launch_bounds__(256) void ln_kernel(const float* __restrict__ gam,
    const float* __restrict__ bet, float* __restrict__ y)
{
    int i = blockIdx.x, t = threadIdx.x;
    float4 v = *(const float4*)&g_res[(size_t)i*1024 + t*4];
    float s  = v.x + v.y + v.z + v.w;
    float ss = v.x*v.x + v.y*v.y + v.z*v.z + v.w*v.w;
#pragma unroll
    for (int off = 16; off; off >>= 1) {
        s  += __shfl_xor_sync(0xffffffffu, s,  off);
        ss += __shfl_xor_sync(0xffffffffu, ss, off);
    }
    __shared__ float as[8], ass[8];
    if ((t & 31) == 0) { as[t >> 5] = s; ass[t >> 5] = ss; }
    __syncthreads();
    float S = 0.f, SS = 0.f;
#pragma unroll
    for (int u = 0; u < 8; u++) { S += as[u]; SS += ass[u]; }
    float mu  = S * (1.f/1024.f);
    float var = SS * (1.f/1024.f) - mu*mu;
    float inv = rsqrtf(var + 1e-5f);
    float4 gg = *(const float4*)&gam[t*4];
    float4 bb = *(const float4*)&bet[t*4];
    float4 o;
    o.x = (v.x - mu)*inv*gg.x + bb.x;
    o.y = (v.y - mu)*inv*gg.y + bb.y;
    o.z = (v.z - mu)*inv*gg.z + bb.z;
    o.w = (v.w - mu)*inv*gg.w + bb.w;
    *(float4*)&y[(size_t)i*1024 + t*4] = o;
}

// ---------------- launch ----------------
extern "C" void kernel_launch(void* const* d_in, const int* in_sizes, int n_in,
                              void* d_out, int out_size)
{
    const float* x       = (const float*)d_in[0];
    const float* Wq      = (const float*)d_in[1];
    const float* bq      = (const float*)d_in[2];
    const float* Wk      = (const float*)d_in[3];
    const float* bk      = (const float*)d_in[4];
    const float* Wv      = (const float*)d_in[5];
    const float* bv      = (const float*)d_in[6];
    const float* Wo      = (const float*)d_in[7];
    const float* bo      = (const float*)d_in[8];
    const float* ln_g    = (const float*)d_in[9];
    const float* ln_b    = (const float*)d_in[10];
    const float* qq_W    = (const float*)d_in[11];
    const float* qq_b    = (const float*)d_in[12];
    const float* qq_qw_r = (const float*)d_in[13];
    const float* qq_qw_i = (const float*)d_in[14];
    const float* qq_sg   = (const float*)d_in[15];
    const float* qq_em   = (const float*)d_in[16];
    const float* qq_mb   = (const float*)d_in[17];
    const float* qk_W    = (const float*)d_in[18];
    const float* qk_b    = (const float*)d_in[19];
    const float* qk_qw_r = (const float*)d_in[20];
    const float* qk_qw_i = (const float*)d_in[21];
    const float* qk_sg   = (const float*)d_in[22];
    const float* qk_em   = (const float*)d_in[23];
    const float* qk_mb   = (const float*)d_in[24];

    float* y = (float*)d_out;
    float* w = y + (size_t)MROWS*DMODEL;

    float *pQ, *pK, *pV, *pCq, *pCk, *pAtt, *pRes;
    cudaGetSymbolAddress((void**)&pQ,   g_Q);
    cudaGetSymbolAddress((void**)&pK,   g_K);
    cudaGetSymbolAddress((void**)&pV,   g_V);
    cudaGetSymbolAddress((void**)&pCq,  g_Cq);
    cudaGetSymbolAddress((void**)&pCk,  g_Ck);
    cudaGetSymbolAddress((void**)&pAtt, g_att);
    cudaGetSymbolAddress((void**)&pRes, g_res);
    __nv_bfloat16 *pXh, *pXl, *pAh, *pAl, *pWh, *pWl;
    cudaGetSymbolAddress((void**)&pXh, g_xhi);
    cudaGetSymbolAddress((void**)&pXl, g_xlo);
    cudaGetSymbolAddress((void**)&pAh, g_ahi);
    cudaGetSymbolAddress((void**)&pAl, g_alo);
    cudaGetSymbolAddress((void**)&pWh, g_Whi);
    cudaGetSymbolAddress((void**)&pWl, g_Wlo);

    cudaFuncSetAttribute(mma_gemm_kernel,
        cudaFuncAttributeMaxDynamicSharedMemorySize, GEMM_SMEM);
    cudaFuncSetAttribute(flash_mma_kernel,
        cudaFuncAttributeMaxDynamicSharedMemorySize, FLASH2_SMEM);

    prep_m_kernel<<<1, 256>>>(qq_qw_r, qq_qw_i, qk_qw_r, qk_qw_i, qq_em, qk_em);
    quantum_kernel<<<MROWS, 128>>>(x, qq_sg, qk_sg);

    aconv_kernel<<<MROWS*DMODEL/(256*4), 256>>>(x, pXh, pXl);
    dim3 wg(32, 32), wb(32, 8);
    const size_t WSZ = (size_t)DMODEL*DMODEL;
    wconv_kernel<<<wg, wb>>>(Wq,   pWh + 0*WSZ, pWl + 0*WSZ);
    wconv_kernel<<<wg, wb>>>(Wk,   pWh + 1*WSZ, pWl + 1*WSZ);
    wconv_kernel<<<wg, wb>>>(Wv,   pWh + 2*WSZ, pWl + 2*WSZ);
    wconv_kernel<<<wg, wb>>>(qq_W, pWh + 3*WSZ, pWl + 3*WSZ);
    wconv_kernel<<<wg, wb>>>(qk_W, pWh + 4*WSZ, pWl + 4*WSZ);
    wconv_kernel<<<wg, wb>>>(Wo,   pWh + 5*WSZ, pWl + 5*WSZ);

    dim3 gg(32, 8);
    mma_gemm_kernel<<<gg, 256, GEMM_SMEM>>>(pXh, pXl, pWh + 0*WSZ, pWl + 0*WSZ, bq,   nullptr, pQ,  0);
    mma_gemm_kernel<<<gg, 256, GEMM_SMEM>>>(pXh, pXl, pWh + 1*WSZ, pWl + 1*WSZ, bk,   nullptr, pK,  0);
    mma_gemm_kernel<<<gg, 256, GEMM_SMEM>>>(pXh, pXl, pWh + 2*WSZ, pWl + 2*WSZ, bv,   nullptr, pV,  0);
    mma_gemm_kernel<<<gg, 256, GEMM_SMEM>>>(pXh, pXl, pWh + 3*WSZ, pWl + 3*WSZ, qq_b, nullptr, pCq, 1);
    mma_gemm_kernel<<<gg, 256, GEMM_SMEM>>>(pXh, pXl, pWh + 4*WSZ, pWl + 4*WSZ, qk_b, nullptr, pCk, 1);

    combine_kernel<<<MROWS, 256>>>(qq_mb, qk_mb);
    vtrans_kernel<<<dim3(32, 32), 256>>>();

    flash_mma_kernel<<<dim3(32, 32), 256, FLASH2_SMEM>>>(w);

    norm_w_kernel<<<(NBH*(size_t)SEQ*SEQ)/(4*256), 256>>>(w);

    aconv_kernel<<<MROWS*DMODEL/(256*4), 256>>>(pAtt, pAh, pAl);
    mma_gemm_kernel<<<gg, 256, GEMM_SMEM>>>(pAh, pAl, pWh + 5*WSZ, pWl + 5*WSZ, bo, x, pRes, 0);

    ln_kernel<<<MROWS, 256>>>(ln_g, ln_b, y);
}

// round 6
// speedup vs baseline: 2.5039x; 1.1096x over previous
#include <cuda_runtime.h>
#include <cuda_bf16.h>
#include <cstdint>
#include <math.h>

#define MROWS 4096
#define DMODEL 1024
#define NH 16
#define HD 64
#define QD 16
#define SEQ 2048
#define NBH 32
#define AD 80

// ---------------- scratch ----------------
__device__ float g_Q[MROWS*DMODEL];
__device__ float g_K[MROWS*DMODEL];
__device__ float g_V[MROWS*DMODEL];
__device__ float g_Cq[MROWS*DMODEL];
__device__ float g_Ck[MROWS*DMODEL];
__device__ float g_att[MROWS*DMODEL];
__device__ float g_res[MROWS*DMODEL];
__device__ float g_Va[NBH*SEQ*HD];
__device__ float g_probs_q[MROWS*QD];
__device__ float g_probs_k[MROWS*QD];
__device__ float g_fw_q[MROWS];
__device__ float g_fw_k[MROWS];
__device__ float g_m[NBH*SEQ];
__device__ float g_l[NBH*SEQ];
__device__ float g_mt[NBH*SEQ*16];    // running max snapshot per 128-key tile
__device__ float g_M[4*256];

// bf16 split buffers
__device__ __nv_bfloat16 g_xhi[MROWS*DMODEL];
__device__ __nv_bfloat16 g_xlo[MROWS*DMODEL];
__device__ __nv_bfloat16 g_ahi[MROWS*DMODEL];
__device__ __nv_bfloat16 g_alo[MROWS*DMODEL];
__device__ __nv_bfloat16 g_Whi[6*DMODEL*DMODEL];   // [widx][n][k]
__device__ __nv_bfloat16 g_Wlo[6*DMODEL*DMODEL];
// flash operands
__device__ __nv_bfloat16 g_Qah[NBH*SEQ*AD];   // [bh][s][80] = [0.125*Qf, 0.1*qp]
__device__ __nv_bfloat16 g_Qal[NBH*SEQ*AD];
__device__ __nv_bfloat16 g_Kah[NBH*SEQ*AD];   // [bh][s][80] = [Kf, kp]
__device__ __nv_bfloat16 g_Kal[NBH*SEQ*AD];
__device__ __nv_bfloat16 g_Vth[NBH*HD*SEQ];   // [bh][d][s]

// ---------------- helpers ----------------
__device__ __forceinline__ uint32_t smem_u32(const void* p) {
    uint32_t a;
    asm("{ .reg .u64 t; cvta.to.shared.u64 t, %1; cvt.u32.u64 %0, t; }" : "=r"(a) : "l"(p));
    return a;
}
__device__ __forceinline__ void cp16(uint32_t dst, const void* src) {
    asm volatile("cp.async.cg.shared.global [%0], [%1], 16;\n" :: "r"(dst), "l"(src));
}
__device__ __forceinline__ void ldsm4(uint32_t* r, uint32_t addr) {
    asm volatile("ldmatrix.sync.aligned.m8n8.x4.shared.b16 {%0,%1,%2,%3}, [%4];"
        : "=r"(r[0]), "=r"(r[1]), "=r"(r[2]), "=r"(r[3]) : "r"(addr));
}
__device__ __forceinline__ void ldsm2(uint32_t* r, uint32_t addr) {
    asm volatile("ldmatrix.sync.aligned.m8n8.x2.shared.b16 {%0,%1}, [%2];"
        : "=r"(r[0]), "=r"(r[1]) : "r"(addr));
}
__device__ __forceinline__ void mma16816(float* d, const uint32_t* a, const uint32_t* b) {
    asm volatile("mma.sync.aligned.m16n8k16.row.col.f32.bf16.bf16.f32 "
        "{%0,%1,%2,%3}, {%4,%5,%6,%7}, {%8,%9}, {%0,%1,%2,%3};"
        : "+f"(d[0]), "+f"(d[1]), "+f"(d[2]), "+f"(d[3])
        : "r"(a[0]), "r"(a[1]), "r"(a[2]), "r"(a[3]), "r"(b[0]), "r"(b[1]));
}

// ---------------- conversions ----------------
__global__ __launch_bounds__(256) void aconv_kernel(const float* __restrict__ a,
    __nv_bfloat16* __restrict__ hi, __nv_bfloat16* __restrict__ lo)
{
    size_t i = ((size_t)blockIdx.x * 256 + threadIdx.x) * 4;
    float4 v = *(const float4*)&a[i];
    float vv[4] = {v.x, v.y, v.z, v.w};
    ushort4 h, l;
    unsigned short* hp = &h.x; unsigned short* lp = &l.x;
#pragma unroll
    for (int j = 0; j < 4; j++) {
        __nv_bfloat16 hb = __float2bfloat16(vv[j]);
        __nv_bfloat16 lb = __float2bfloat16(vv[j] - __bfloat162float(hb));
        hp[j] = __bfloat16_as_ushort(hb);
        lp[j] = __bfloat16_as_ushort(lb);
    }
    *(ushort4*)&hi[i] = h;
    *(ushort4*)&lo[i] = l;
}

// W [k][n] f32 -> hi/lo [n][k] bf16
__global__ __launch_bounds__(256) void wconv_kernel(const float* __restrict__ W,
    __nv_bfloat16* __restrict__ hi, __nv_bfloat16* __restrict__ lo)
{
    __shared__ float tile[32][33];
    int bx = blockIdx.x * 32;
    int by = blockIdx.y * 32;
    int tx = threadIdx.x, ty = threadIdx.y;
#pragma unroll
    for (int i = 0; i < 32; i += 8)
        tile[ty + i][tx] = W[(size_t)(by + ty + i) * 1024 + bx + tx];
    __syncthreads();
#pragma unroll
    for (int i = 0; i < 32; i += 8) {
        int n = bx + ty + i, k = by + tx;
        float v = tile[tx][ty + i];
        __nv_bfloat16 hb = __float2bfloat16(v);
        hi[(size_t)n * 1024 + k] = hb;
        lo[(size_t)n * 1024 + k] = __float2bfloat16(v - __bfloat162float(hb));
    }
}

// ---------------- mma.sync split-bf16 GEMM ----------------
#define SROW 40
#define MAT_E (128*SROW)
#define SST_E (4*MAT_E)
#define GEMM_SMEM (2*SST_E*2)

__device__ __forceinline__ void load_chunk_mm(uint32_t sb, int t, int m0, int n0, int k0,
    const __nv_bfloat16* Ahi, const __nv_bfloat16* Alo,
    const __nv_bfloat16* Bhi, const __nv_bfloat16* Blo)
{
#pragma unroll
    for (int i = 0; i < 2; i++) {
        int cid = i * 256 + t;
        int row = cid >> 2, c = cid & 3;
        uint32_t off = (uint32_t)(row * (SROW*2) + c * 16);
        cp16(sb + off,              (const char*)(Ahi + (size_t)(m0 + row) * 1024 + k0) + c * 16);
        cp16(sb + MAT_E*2 + off,    (const char*)(Alo + (size_t)(m0 + row) * 1024 + k0) + c * 16);
        cp16(sb + 2*MAT_E*2 + off,  (const char*)(Bhi + (size_t)(n0 + row) * 1024 + k0) + c * 16);
        cp16(sb + 3*MAT_E*2 + off,  (const char*)(Blo + (size_t)(n0 + row) * 1024 + k0) + c * 16);
    }
    asm volatile("cp.async.commit_group;\n" ::: "memory");
}

// shared GEMM body; s3: include A_hi*B_lo leg (full 3-MMA split)
__device__ __forceinline__ void gemm_body(
    uint32_t sb, int m0, int n0,
    const __nv_bfloat16* Ahi, const __nv_bfloat16* Alo,
    const __nv_bfloat16* Bhi, const __nv_bfloat16* Blo,
    const float* bias, const float* resid, float* out, int do_tanh, int s3)
{
    int t = threadIdx.x;
    int warp = t >> 5, lane = t & 31;
    int wm = warp & 1, wn = warp >> 1;

    float acc[4][4][4];
#pragma unroll
    for (int a = 0; a < 4; a++)
#pragma unroll
        for (int b = 0; b < 4; b++)
#pragma unroll
            for (int c = 0; c < 4; c++) acc[a][b][c] = 0.f;

    int aq = lane >> 3;
    int arow = (aq & 1) * 8 + (lane & 7);
    int akoff = (aq >> 1) * 8;
    int brow = lane & 7;
    int bkoff = ((lane >> 3) & 1) * 8;

    load_chunk_mm(sb, t, m0, n0, 0, Ahi, Alo, Bhi, Blo);

#pragma unroll 1
    for (int c = 0; c < 32; c++) {
        if (c < 31)
            load_chunk_mm(sb + ((c + 1) & 1) * SST_E * 2, t, m0, n0, (c + 1) * 32, Ahi, Alo, Bhi, Blo);
        if (c < 31) asm volatile("cp.async.wait_group 1;\n" ::: "memory");
        else        asm volatile("cp.async.wait_group 0;\n" ::: "memory");
        __syncthreads();

        uint32_t st = sb + (c & 1) * SST_E * 2;
#pragma unroll
        for (int k16 = 0; k16 < 2; k16++) {
            int kb = k16 * 16;
            uint32_t ah[4][4], al[4][4];
#pragma unroll
            for (int mt = 0; mt < 4; mt++) {
                uint32_t aaddr = st + (uint32_t)(((wm*64 + mt*16 + arow) * SROW + kb + akoff) * 2);
                ldsm4(ah[mt], aaddr);
                ldsm4(al[mt], aaddr + MAT_E*2);
            }
#pragma unroll
            for (int nt = 0; nt < 4; nt++) {
                uint32_t baddr = st + 2*MAT_E*2 +
                    (uint32_t)(((wn*32 + nt*8 + brow) * SROW + kb + bkoff) * 2);
                uint32_t bh[2], bl[2];
                ldsm2(bh, baddr);
                if (s3) ldsm2(bl, baddr + MAT_E*2);
#pragma unroll
                for (int mt = 0; mt < 4; mt++) {
                    mma16816(acc[mt][nt], ah[mt], bh);
                    if (s3) mma16816(acc[mt][nt], ah[mt], bl);
                    mma16816(acc[mt][nt], al[mt], bh);
                }
            }
        }
        __syncthreads();
    }

    int rin = lane >> 2, cin = (lane & 3) * 2;
#pragma unroll
    for (int mt = 0; mt < 4; mt++) {
#pragma unroll
        for (int nt = 0; nt < 4; nt++) {
            int n = n0 + wn*32 + nt*8 + cin;
            float b0 = bias[n], b1 = bias[n + 1];
#pragma unroll
            for (int half = 0; half < 2; half++) {
                int m = m0 + wm*64 + mt*16 + rin + half*8;
                float v0 = acc[mt][nt][half*2 + 0] + b0;
                float v1 = acc[mt][nt][half*2 + 1] + b1;
                if (resid) {
                    const float* rr = resid + (size_t)m * 1024 + n;
                    v0 += rr[0]; v1 += rr[1];
                }
                if (do_tanh) { v0 = tanhf(v0); v1 = tanhf(v1); }
                *(float2*)&out[(size_t)m * 1024 + n] = make_float2(v0, v1);
            }
        }
    }
}

struct GemmP5 {
    const __nv_bfloat16* Bh[5];
    const __nv_bfloat16* Bl[5];
    const float* bias[5];
    float* out[5];
    int tanh_f[5];
    int s3_f[5];
};

__global__ __launch_bounds__(256) void mma_gemm5_kernel(
    const __nv_bfloat16* __restrict__ Ah, const __nv_bfloat16* __restrict__ Al, GemmP5 P)
{
    extern __shared__ char smem[];
    uint32_t sb = smem_u32(smem);
    int z = blockIdx.z;
    gemm_body(sb, blockIdx.x * 128, blockIdx.y * 128,
              Ah, Al, P.Bh[z], P.Bl[z], P.bias[z], nullptr, P.out[z], P.tanh_f[z], P.s3_f[z]);
}

__global__ __launch_bounds__(256) void mma_gemm_kernel(
    const __nv_bfloat16* __restrict__ Ahi, const __nv_bfloat16* __restrict__ Alo,
    const __nv_bfloat16* __restrict__ Bhi, const __nv_bfloat16* __restrict__ Blo,
    const float* __restrict__ bias, const float* __restrict__ resid,
    float* __restrict__ out, int do_tanh)
{
    extern __shared__ char smem[];
    uint32_t sb = smem_u32(smem);
    gemm_body(sb, blockIdx.x * 128, blockIdx.y * 128,
              Ahi, Alo, Bhi, Blo, bias, resid, out, do_tanh, 1);
}

// ---------------- prep: M = qw @ em ----------------
__global__ void prep_m_kernel(const float* __restrict__ qqr, const float* __restrict__ qqi,
                              const float* __restrict__ qkr, const float* __restrict__ qki,
                              const float* __restrict__ qqem, const float* __restrict__ qkem)
{
    int t = threadIdx.x;
    int u = t >> 4, v = t & 15;
    float a = 0.f, b = 0.f, c = 0.f, d = 0.f;
#pragma unroll
    for (int w = 0; w < 16; w++) {
        float e1 = qqem[w*16+v], e2 = qkem[w*16+v];
        a += qqr[u*16+w]*e1;
        b += qqi[u*16+w]*e1;
        c += qkr[u*16+w]*e2;
        d += qki[u*16+w]*e2;
    }
    g_M[t] = a; g_M[256+t] = b; g_M[512+t] = c; g_M[768+t] = d;
}

// ---------------- quantum small path ----------------
__global__ __launch_bounds__(128) void quantum_kernel(
    const float* __restrict__ x, const float* __restrict__ sgq, const float* __restrict__ sgk)
{
    __shared__ float xs[1024];
    __shared__ float part[8][16];
    __shared__ float qss[16];
    __shared__ float prob_s[16];
    int i = blockIdx.x;
    int t = threadIdx.x;
#pragma unroll
    for (int c = 0; c < 2; c++)
        *(float4*)&xs[(t + c*128)*4] = *(const float4*)&x[(size_t)i*1024 + (t + c*128)*4];
    __syncthreads();
    int tt = t & 15, pp = t >> 4;
#pragma unroll 1
    for (int side = 0; side < 2; side++) {
        const float* sg = side ? sgk : sgq;
        float acc = 0.f;
        int base = pp * 128;
        for (int d = 0; d < 128; d++)
            acc += xs[base + d] * sg[(base + d)*16 + tt];
        part[pp][tt] = acc;
        __syncthreads();
        if (t < 16) {
            float q = 0.f;
#pragma unroll
            for (int p = 0; p < 8; p++) q += part[p][t];
            qss[t] = q;
        }
        __syncthreads();
        if (t < 16) {
            const float* Mr = g_M + side*512;
            const float* Mi = Mr + 256;
            float er = 0.f, ei = 0.f;
#pragma unroll
            for (int u = 0; u < 16; u++) {
                er += qss[u]*Mr[u*16+t];
                ei += qss[u]*Mi[u*16+t];
            }
            float pr = er*er + ei*ei;
            prob_s[t] = pr;
            (side ? g_probs_k : g_probs_q)[i*16 + t] = pr;
        }
        __syncthreads();
        if (t == 0) {
            float ms = 0.f;
#pragma unroll
            for (int u = 0; u < 16; u++) ms += prob_s[u];
            ms *= (1.f/16.f);
            (side ? g_fw_k : g_fw_q)[i] = 1.f/(1.f + __expf(-ms));
        }
        __syncthreads();
    }
}

// ---------------- combine ----------------
__global__ __launch_bounds__(256) void combine_kernel(
    const float* __restrict__ qq_mb, const float* __restrict__ qk_mb)
{
    int i = blockIdx.x;
    int b = i >> 11, s = i & 2047;
    int t = threadIdx.x;
    __shared__ float pqs[16], pks[16];
    if (t < 16) pqs[t] = g_probs_q[i*16 + t];
    else if (t < 32) pks[t-16] = g_probs_k[i*16 + (t-16)];
    __syncthreads();
    float fq = g_fw_q[i], fk = g_fw_k[i];
    int d0 = t * 4;
    float4 qv = *(const float4*)&g_Q [(size_t)i*1024 + d0];
    float4 kv = *(const float4*)&g_K [(size_t)i*1024 + d0];
    float4 vv = *(const float4*)&g_V [(size_t)i*1024 + d0];
    float4 cq = *(const float4*)&g_Cq[(size_t)i*1024 + d0];
    float4 ck = *(const float4*)&g_Ck[(size_t)i*1024 + d0];
    const float* qvp = (const float*)&qv;
    const float* kvp = (const float*)&kv;
    const float* cqp = (const float*)&cq;
    const float* ckp = (const float*)&ck;
    ushort4 qh4, ql4, kh4, kl4;
    unsigned short* qhp = &qh4.x; unsigned short* qlp = &ql4.x;
    unsigned short* khp = &kh4.x; unsigned short* klp = &kl4.x;
#pragma unroll
    for (int j = 0; j < 4; j++) {
        int d = d0 + j;
        float qmb = 0.f, kmb = 0.f;
#pragma unroll
        for (int u = 0; u < 16; u++) {
            qmb += pqs[u] * qq_mb[u*1024 + d];
            kmb += pks[u] * qk_mb[u*1024 + d];
        }
        float qq = fq*qmb + (1.f - fq)*cqp[j];
        float kq = fk*kmb + (1.f - fk)*ckp[j];
        float oq = (0.7f*qvp[j] + 0.3f*qq) * 0.125f;
        float ok =  0.7f*kvp[j] + 0.3f*kq;
        __nv_bfloat16 hb = __float2bfloat16(oq);
        qhp[j] = __bfloat16_as_ushort(hb);
        qlp[j] = __bfloat16_as_ushort(__float2bfloat16(oq - __bfloat162float(hb)));
        hb = __float2bfloat16(ok);
        khp[j] = __bfloat16_as_ushort(hb);
        klp[j] = __bfloat16_as_ushort(__float2bfloat16(ok - __bfloat162float(hb)));
    }
    int h = d0 >> 6, dh = d0 & 63;
    int bh = b*16 + h;
    size_t qb = ((size_t)bh*SEQ + s)*AD + dh;
    *(ushort4*)&g_Qah[qb] = qh4;
    *(ushort4*)&g_Qal[qb] = ql4;
    *(ushort4*)&g_Kah[qb] = kh4;
    *(ushort4*)&g_Kal[qb] = kl4;
    *(float4*)&g_Va[((size_t)bh*SEQ + s)*HD + dh] = vv;
    int h2 = t >> 4, u = t & 15;
    int bh2 = b*16 + h2;
    size_t tb = ((size_t)bh2*SEQ + s)*AD + 64 + u;
    float tv = 0.1f * pqs[u];
    __nv_bfloat16 th = __float2bfloat16(tv);
    g_Qah[tb] = th;
    g_Qal[tb] = __float2bfloat16(tv - __bfloat162float(th));
    float tk = pks[u];
    th = __float2bfloat16(tk);
    g_Kah[tb] = th;
    g_Kal[tb] = __float2bfloat16(tk - __bfloat162float(th));
}

// ---------------- V transpose: Va [bh][s][64] f32 -> Vth [bh][d][s] bf16 ----------------
__global__ __launch_bounds__(256) void vtrans_kernel()
{
    __shared__ float tile[64][65];
    int s0 = blockIdx.x * 64, bh = blockIdx.y;
    int t = threadIdx.x;
    int r = t >> 2, c4 = (t & 3) * 16;
    const float* src = g_Va + ((size_t)bh*SEQ + s0 + r)*HD + c4;
#pragma unroll
    for (int j = 0; j < 16; j += 4) {
        float4 v = *(const float4*)&src[j];
        tile[r][c4 + j + 0] = v.x;
        tile[r][c4 + j + 1] = v.y;
        tile[r][c4 + j + 2] = v.z;
        tile[r][c4 + j + 3] = v.w;
    }
    __syncthreads();
    int d = t >> 2, sc = (t & 3) * 16;
    ushort4 ho[4];
#pragma unroll
    for (int j = 0; j < 16; j++) {
        float v = tile[sc + j][d];
        (&ho[j >> 2].x)[j & 3] = __bfloat16_as_ushort(__float2bfloat16(v));
    }
    size_t base = ((size_t)bh*HD + d)*SEQ + s0 + sc;
#pragma unroll
    for (int j = 0; j < 4; j++)
        *(ushort4*)&g_Vth[base + j*4] = ho[j];
}

// ---------------- flash attention with mma.sync ----------------
// smem layout (bytes):
//  Qhi 0..11264, Qlo 11264..22528
//  stage s at ST0B + s*STAGEB: Khi(22528) Klo(+22528) Vth(+45056, 17408)
//  Phi at PHIB (17408), reductions at REDB (1024)
#define QLOB 11264
#define ST0B 22528
#define KLOB 22528
#define VTHB 45056
#define STAGEB 62464
#define PHIB 147456
#define REDB 164864
#define FLASH2_SMEM 165888

__device__ __forceinline__ void load_q_f(uint32_t sb, int t, int bh, int qt)
{
    const char* qh = (const char*)(g_Qah + ((size_t)bh*SEQ + qt*64)*AD);
    const char* ql = (const char*)(g_Qal + ((size_t)bh*SEQ + qt*64)*AD);
#pragma unroll 1
    for (int i = t; i < 640; i += 256) {
        int row = i / 10, c = i % 10;
        uint32_t off = (uint32_t)(row*176 + c*16);
        cp16(sb + off, qh + (size_t)row*160 + c*16);
        cp16(sb + QLOB + off, ql + (size_t)row*160 + c*16);
    }
}

__device__ __forceinline__ void load_kv_f(uint32_t stb, int t, int bh, int k0)
{
    const char* kh = (const char*)(g_Kah + ((size_t)bh*SEQ + k0)*AD);
    const char* kl = (const char*)(g_Kal + ((size_t)bh*SEQ + k0)*AD);
#pragma unroll 1
    for (int i = t; i < 1280; i += 256) {
        int row = i / 10, c = i % 10;
        uint32_t off = (uint32_t)(row*176 + c*16);
        cp16(stb + off, kh + (size_t)row*160 + c*16);
        cp16(stb + KLOB + off, kl + (size_t)row*160 + c*16);
    }
    const __nv_bfloat16* vh = g_Vth + (size_t)bh*HD*SEQ + k0;
#pragma unroll 1
    for (int i = t; i < 1024; i += 256) {
        int d = i >> 4, c = i & 15;
        uint32_t off = (uint32_t)(d*272 + c*16);
        cp16(stb + VTHB + off, (const char*)(vh + (size_t)d*SEQ) + c*16);
    }
    asm volatile("cp.async.commit_group;\n" ::: "memory");
}

__global__ __launch_bounds__(256) void flash_mma_kernel(float* __restrict__ w_out)
{
    extern __shared__ char smem[];
    uint32_t sb = smem_u32(smem);
    float* redm = (float*)(smem + REDB);      // [2][64]
    float* reds = redm + 128;                 // [2][64]
    __nv_bfloat162* Pph = (__nv_bfloat162*)(smem + PHIB);

    int qt = blockIdx.x, bh = blockIdx.y;
    int t = threadIdx.x;
    int warp = t >> 5, lane = t & 31;
    int wm = warp & 3, wn = warp >> 2;       // 4 m-strips x 2 n-halves

    int aq = lane >> 3;
    int arow = (aq & 1) * 8 + (lane & 7);
    int akoff = (aq >> 1) * 8;
    int b4n = (lane >> 4) * 8 + (lane & 7);
    int b4k = ((lane >> 3) & 1) * 8;
    int rin = lane >> 2, cin = (lane & 3) * 2;

    load_q_f(sb, t, bh, qt);
    load_kv_f(sb + ST0B, t, bh, 0);
    load_kv_f(sb + ST0B + STAGEB, t, bh, 128);

    float m_run0 = -1e30f, m_run1 = -1e30f;
    float l_run0 = 0.f, l_run1 = 0.f;
    float O[4][4];
#pragma unroll
    for (int a = 0; a < 4; a++)
#pragma unroll
        for (int b = 0; b < 4; b++) O[a][b] = 0.f;
    uint32_t qfh[5][4], qfl[5][4];

    int r0 = wm*16 + rin, r1 = r0 + 8;

#pragma unroll 1
    for (int kt = 0; kt < 16; kt++) {
        if (kt < 15) asm volatile("cp.async.wait_group 1;\n" ::: "memory");
        else         asm volatile("cp.async.wait_group 0;\n" ::: "memory");
        __syncthreads();
        uint32_t st = sb + ST0B + (kt & 1) * STAGEB;

        if (kt == 0) {
#pragma unroll
            for (int ks = 0; ks < 5; ks++) {
                uint32_t qaddr = sb + (uint32_t)(((wm*16 + arow)*88 + ks*16 + akoff) * 2);
                ldsm4(qfh[ks], qaddr);
                ldsm4(qfl[ks], qaddr + QLOB);
            }
        }

        // ---- S = Q @ K^T (3-MMA split) ----
        float sacc[8][4];
#pragma unroll
        for (int a = 0; a < 8; a++)
#pragma unroll
            for (int b = 0; b < 4; b++) sacc[a][b] = 0.f;
#pragma unroll
        for (int ks = 0; ks < 5; ks++) {
            int kb = ks * 16;
#pragma unroll
            for (int p = 0; p < 4; p++) {
                uint32_t kaddr = st + (uint32_t)(((wn*64 + p*16 + b4n)*88 + kb + b4k) * 2);
                uint32_t kh4[4], kl4[4];
                ldsm4(kh4, kaddr);
                ldsm4(kl4, kaddr + KLOB);
                mma16816(sacc[2*p],   qfh[ks], kh4);
                mma16816(sacc[2*p+1], qfh[ks], kh4+2);
                mma16816(sacc[2*p],   qfh[ks], kl4);
                mma16816(sacc[2*p+1], qfh[ks], kl4+2);
                mma16816(sacc[2*p],   qfl[ks], kh4);
                mma16816(sacc[2*p+1], qfl[ks], kh4+2);
            }
        }

        // ---- online softmax ----
        float lm0 = -1e30f, lm1 = -1e30f;
#pragma unroll
        for (int nt = 0; nt < 8; nt++) {
            lm0 = fmaxf(lm0, fmaxf(sacc[nt][0], sacc[nt][1]));
            lm1 = fmaxf(lm1, fmaxf(sacc[nt][2], sacc[nt][3]));
        }
        lm0 = fmaxf(lm0, __shfl_xor_sync(0xffffffffu, lm0, 1));
        lm0 = fmaxf(lm0, __shfl_xor_sync(0xffffffffu, lm0, 2));
        lm1 = fmaxf(lm1, __shfl_xor_sync(0xffffffffu, lm1, 1));
        lm1 = fmaxf(lm1, __shfl_xor_sync(0xffffffffu, lm1, 2));
        if ((lane & 3) == 0) {
            redm[wn*64 + r0] = lm0;
            redm[wn*64 + r1] = lm1;
        }
        __syncthreads();
        float mn0 = fmaxf(m_run0, fmaxf(redm[r0], redm[64 + r0]));
        float mn1 = fmaxf(m_run1, fmaxf(redm[r1], redm[64 + r1]));
        float al0 = __expf(m_run0 - mn0);
        float al1 = __expf(m_run1 - mn1);
        m_run0 = mn0; m_run1 = mn1;

        float ls0 = 0.f, ls1 = 0.f;
        size_t wrow0 = ((size_t)bh*SEQ + qt*64 + r0) * SEQ + (size_t)kt*128 + wn*64 + cin;
        size_t wrow1 = wrow0 + (size_t)8 * SEQ;
        int pc = wn*32 + (cin >> 1);
#pragma unroll
        for (int nt = 0; nt < 8; nt++) {
            float p0 = __expf(sacc[nt][0] - mn0);
            float p1 = __expf(sacc[nt][1] - mn0);
            float p2 = __expf(sacc[nt][2] - mn1);
            float p3 = __expf(sacc[nt][3] - mn1);
            ls0 += p0 + p1; ls1 += p2 + p3;
            *(float2*)&w_out[wrow0 + nt*8] = make_float2(p0, p1);
            *(float2*)&w_out[wrow1 + nt*8] = make_float2(p2, p3);
            __nv_bfloat162 hv0; hv0.x = __float2bfloat16(p0); hv0.y = __float2bfloat16(p1);
            __nv_bfloat162 hv1; hv1.x = __float2bfloat16(p2); hv1.y = __float2bfloat16(p3);
            Pph[r0*68 + pc + nt*4] = hv0;
            Pph[r1*68 + pc + nt*4] = hv1;
        }
        ls0 += __shfl_xor_sync(0xffffffffu, ls0, 1);
        ls0 += __shfl_xor_sync(0xffffffffu, ls0, 2);
        ls1 += __shfl_xor_sync(0xffffffffu, ls1, 1);
        ls1 += __shfl_xor_sync(0xffffffffu, ls1, 2);
        if ((lane & 3) == 0) {
            reds[wn*64 + r0] = ls0;
            reds[wn*64 + r1] = ls1;
        }
        if (wn == 0 && (lane & 3) == 0) {
            g_mt[((size_t)bh*SEQ + qt*64 + r0)*16 + kt] = mn0;
            g_mt[((size_t)bh*SEQ + qt*64 + r1)*16 + kt] = mn1;
        }
#pragma unroll
        for (int nt = 0; nt < 4; nt++) {
            O[nt][0] *= al0; O[nt][1] *= al0;
            O[nt][2] *= al1; O[nt][3] *= al1;
        }
        __syncthreads();
        l_run0 = l_run0*al0 + reds[r0] + reds[64 + r0];
        l_run1 = l_run1*al1 + reds[r1] + reds[64 + r1];

        // ---- O += P @ V (plain bf16) ----
#pragma unroll
        for (int ks = 0; ks < 8; ks++) {
            int kb = ks * 16;
            uint32_t paddr = sb + PHIB + (uint32_t)(((wm*16 + arow)*136 + kb + akoff) * 2);
            uint32_t pf[4];
            ldsm4(pf, paddr);
#pragma unroll
            for (int p = 0; p < 2; p++) {
                uint32_t vaddr = st + VTHB + (uint32_t)(((wn*32 + p*16 + b4n)*136 + kb + b4k) * 2);
                uint32_t vh4[4];
                ldsm4(vh4, vaddr);
                mma16816(O[2*p],   pf, vh4);
                mma16816(O[2*p+1], pf, vh4+2);
            }
        }
        __syncthreads();
        if (kt + 2 < 16) load_kv_f(st, t, bh, (kt + 2) * 128);
    }

    // ---- epilogue ----
    float inv0 = 1.f / l_run0, inv1 = 1.f / l_run1;
    int b = bh >> 4, h = bh & 15;
    int rg0 = qt*64 + r0;
#pragma unroll
    for (int nt = 0; nt < 4; nt++) {
        int d = h*64 + wn*32 + nt*8 + cin;
        *(float2*)&g_att[((size_t)b*SEQ + rg0)*1024 + d] = make_float2(O[nt][0]*inv0, O[nt][1]*inv0);
        *(float2*)&g_att[((size_t)b*SEQ + rg0 + 8)*1024 + d] = make_float2(O[nt][2]*inv1, O[nt][3]*inv1);
    }
    if (wn == 0 && (lane & 3) == 0) {
        g_m[(size_t)bh*SEQ + rg0] = m_run0;
        g_l[(size_t)bh*SEQ + rg0] = l_run0;
        g_m[(size_t)bh*SEQ + rg0 + 8] = m_run1;
        g_l[(size_t)bh*SEQ + rg0 + 8] = l_run1;
    }
}

// ---------------- normalize w ----------------
__global__ __launch_bounds__(256) void norm_w_kernel(float* __restrict__ w)
{
    size_t idx = (size_t)blockIdx.x * 256 + threadIdx.x;
    size_t e0 = idx * 4;
    size_t row = e0 >> 11;
    int kt = (int)((e0 & 2047) >> 7);
    float f = __expf(g_mt[row*16 + kt] - g_m[row]) / g_l[row];
    float4 v = *(float4*)&w[e0];
    v.x *= f; v.y *= f; v.z *= f; v.w *= f;
    *(float4*)&w[e0] = v;
}

// ---------------- layernorm ----------------
__global__ __launch_bounds__(256) void ln_kernel(const float* __restrict__ gam,
    const float* __restrict__ bet, float* __restrict__ y)
{
    int i = blockIdx.x, t = threadIdx.x;
    float4 v = *(const float4*)&g_res[(size_t)i*1024 + t*4];
    float s  = v.x + v.y + v.z + v.w;
    float ss = v.x*v.x + v.y*v.y + v.z*v.z + v.w*v.w;
#pragma unroll
    for (int off = 16; off; off >>= 1) {
        s  += __shfl_xor_sync(0xffffffffu, s,  off);
        ss += __shfl_xor_sync(0xffffffffu, ss, off);
    }
    __shared__ float as[8], ass[8];
    if ((t & 31) == 0) { as[t >> 5] = s; ass[t >> 5] = ss; }
    __syncthreads();
    float S = 0.f, SS = 0.f;
#pragma unroll
    for (int u = 0; u < 8; u++) { S += as[u]; SS += ass[u]; }
    float mu  = S * (1.f/1024.f);
    float var = SS * (1.f/1024.f) - mu*mu;
    float inv = rsqrtf(var + 1e-5f);
    float4 gg = *(const float4*)&gam[t*4];
    float4 bb = *(const float4*)&bet[t*4];
    float4 o;
    o.x = (v.x - mu)*inv*gg.x + bb.x;
    o.y = (v.y - mu)*inv*gg.y + bb.y;
    o.z = (v.z - mu)*inv*gg.z + bb.z;
    o.w = (v.w - mu)*inv*gg.w + bb.w;
    *(float4*)&y[(size_t)i*1024 + t*4] = o;
}

// ---------------- launch ----------------
extern "C" void kernel_launch(void* const* d_in, const int* in_sizes, int n_in,
                              void* d_out, int out_size)
{
    const float* x       = (const float*)d_in[0];
    const float* Wq      = (const float*)d_in[1];
    const float* bq      = (const float*)d_in[2];
    const float* Wk      = (const float*)d_in[3];
    const float* bk      = (const float*)d_in[4];
    const float* Wv      = (const float*)d_in[5];
    const float* bv      = (const float*)d_in[6];
    const float* Wo      = (const float*)d_in[7];
    const float* bo      = (const float*)d_in[8];
    const float* ln_g    = (const float*)d_in[9];
    const float* ln_b    = (const float*)d_in[10];
    const float* qq_W    = (const float*)d_in[11];
    const float* qq_b    = (const float*)d_in[12];
    const float* qq_qw_r = (const float*)d_in[13];
    const float* qq_qw_i = (const float*)d_in[14];
    const float* qq_sg   = (const float*)d_in[15];
    const float* qq_em   = (const float*)d_in[16];
    const float* qq_mb   = (const float*)d_in[17];
    const float* qk_W    = (const float*)d_in[18];
    const float* qk_b    = (const float*)d_in[19];
    const float* qk_qw_r = (const float*)d_in[20];
    const float* qk_qw_i = (const float*)d_in[21];
    const float* qk_sg   = (const float*)d_in[22];
    const float* qk_em   = (const float*)d_in[23];
    const float* qk_mb   = (const float*)d_in[24];

    float* y = (float*)d_out;
    float* w = y + (size_t)MROWS*DMODEL;

    float *pQ, *pK, *pV, *pCq, *pCk, *pAtt, *pRes;
    cudaGetSymbolAddress((void**)&pQ,   g_Q);
    cudaGetSymbolAddress((void**)&pK,   g_K);
    cudaGetSymbolAddress((void**)&pV,   g_V);
    cudaGetSymbolAddress((void**)&pCq,  g_Cq);
    cudaGetSymbolAddress((void**)&pCk,  g_Ck);
    cudaGetSymbolAddress((void**)&pAtt, g_att);
    cudaGetSymbolAddress((void**)&pRes, g_res);
    __nv_bfloat16 *pXh, *pXl, *pAh, *pAl, *pWh, *pWl;
    cudaGetSymbolAddress((void**)&pXh, g_xhi);
    cudaGetSymbolAddress((void**)&pXl, g_xlo);
    cudaGetSymbolAddress((void**)&pAh, g_ahi);
    cudaGetSymbolAddress((void**)&pAl, g_alo);
    cudaGetSymbolAddress((void**)&pWh, g_Whi);
    cudaGetSymbolAddress((void**)&pWl, g_Wlo);

    cudaFuncSetAttribute(mma_gemm_kernel,
        cudaFuncAttributeMaxDynamicSharedMemorySize, GEMM_SMEM);
    cudaFuncSetAttribute(mma_gemm5_kernel,
        cudaFuncAttributeMaxDynamicSharedMemorySize, GEMM_SMEM);
    cudaFuncSetAttribute(flash_mma_kernel,
        cudaFuncAttributeMaxDynamicSharedMemorySize, FLASH2_SMEM);

    prep_m_kernel<<<1, 256>>>(qq_qw_r, qq_qw_i, qk_qw_r, qk_qw_i, qq_em, qk_em);
    quantum_kernel<<<MROWS, 128>>>(x, qq_sg, qk_sg);

    aconv_kernel<<<MROWS*DMODEL/(256*4), 256>>>(x, pXh, pXl);
    dim3 wg(32, 32), wb(32, 8);
    const size_t WSZ = (size_t)DMODEL*DMODEL;
    wconv_kernel<<<wg, wb>>>(Wq,   pWh + 0*WSZ, pWl + 0*WSZ);
    wconv_kernel<<<wg, wb>>>(Wk,   pWh + 1*WSZ, pWl + 1*WSZ);
    wconv_kernel<<<wg, wb>>>(Wv,   pWh + 2*WSZ, pWl + 2*WSZ);
    wconv_kernel<<<wg, wb>>>(qq_W, pWh + 3*WSZ, pWl + 3*WSZ);
    wconv_kernel<<<wg, wb>>>(qk_W, pWh + 4*WSZ, pWl + 4*WSZ);
    wconv_kernel<<<wg, wb>>>(Wo,   pWh + 5*WSZ, pWl + 5*WSZ);

    // 5 forward GEMMs in one launch (z = which GEMM)
    GemmP5 P;
    P.Bh[0] = pWh + 0*WSZ; P.Bl[0] = pWl + 0*WSZ; P.bias[0] = bq;   P.out[0] = pQ;  P.tanh_f[0] = 0; P.s3_f[0] = 1;
    P.Bh[1] = pWh + 1*WSZ; P.Bl[1] = pWl + 1*WSZ; P.bias[1] = bk;   P.out[1] = pK;  P.tanh_f[1] = 0; P.s3_f[1] = 1;
    P.Bh[2] = pWh + 2*WSZ; P.Bl[2] = pWl + 2*WSZ; P.bias[2] = bv;   P.out[2] = pV;  P.tanh_f[2] = 0; P.s3_f[2] = 1;
    P.Bh[3] = pWh + 3*WSZ; P.Bl[3] = pWl + 3*WSZ; P.bias[3] = qq_b; P.out[3] = pCq; P.tanh_f[3] = 1; P.s3_f[3] = 0;
    P.Bh[4] = pWh + 4*WSZ; P.Bl[4] = pWl + 4*WSZ; P.bias[4] = qk_b; P.out[4] = pCk; P.tanh_f[4] = 1; P.s3_f[4] = 0;
    dim3 g5(32, 8, 5);
    mma_gemm5_kernel<<<g5, 256, GEMM_SMEM>>>(pXh, pXl, P);

    combine_kernel<<<MROWS, 256>>>(qq_mb, qk_mb);
    vtrans_kernel<<<dim3(32, 32), 256>>>();

    flash_mma_kernel<<<dim3(32, 32), 256, FLASH2_SMEM>>>(w);

    norm_w_kernel<<<(NBH*(size_t)SEQ*SEQ)/(4*256), 256>>>(w);

    aconv_kernel<<<MROWS*DMODEL/(256*4), 256>>>(pAtt, pAh, pAl);
    dim3 gg(32, 8);
    mma_gemm_kernel<<<gg, 256, GEMM_SMEM>>>(pAh, pAl, pWh + 5*WSZ, pWl + 5*WSZ, bo, x, pRes, 0);

    ln_kernel<<<MROWS, 256>>>(ln_g, ln_b, y);
}

// round 7
// speedup vs baseline: 3.0205x; 1.2063x over previous
#include <cuda_runtime.h>
#include <cuda_bf16.h>
#include <cstdint>
#include <math.h>

#define MROWS 4096
#define DMODEL 1024
#define NH 16
#define HD 64
#define QD 16
#define SEQ 2048
#define NBH 32
#define AD 80

// ---------------- scratch ----------------
__device__ float g_Q[MROWS*DMODEL];
__device__ float g_K[MROWS*DMODEL];
__device__ float g_V[MROWS*DMODEL];
__device__ float g_Cq[MROWS*DMODEL];
__device__ float g_Ck[MROWS*DMODEL];
__device__ float g_res[MROWS*DMODEL];
__device__ float g_Va[NBH*SEQ*HD];
__device__ float g_probs_q[MROWS*QD];
__device__ float g_probs_k[MROWS*QD];
__device__ float g_fw_q[MROWS];
__device__ float g_fw_k[MROWS];
__device__ float g_m[NBH*SEQ];
__device__ float g_l[NBH*SEQ];
__device__ float g_mt[NBH*SEQ*16];    // running max snapshot per 128-key tile
__device__ float g_M[4*256];

// bf16 buffers
__device__ __nv_bfloat16 g_xhi[MROWS*DMODEL];
__device__ __nv_bfloat16 g_xlo[MROWS*DMODEL];
__device__ __nv_bfloat16 g_ahi[MROWS*DMODEL];     // att hi (written by flash)
__device__ __nv_bfloat16 g_alo[MROWS*DMODEL];     // att lo
__device__ __nv_bfloat16 g_Whi[6*DMODEL*DMODEL];  // [widx][n][k]
// flash operands
__device__ __nv_bfloat16 g_Qah[NBH*SEQ*AD];   // [bh][s][80] = [0.125*Qf, 0.1*qp]
__device__ __nv_bfloat16 g_Qal[NBH*SEQ*AD];
__device__ __nv_bfloat16 g_Kah[NBH*SEQ*AD];   // [bh][s][80] = [Kf, kp]  (plain bf16)
__device__ __nv_bfloat16 g_Vth[NBH*HD*SEQ];   // [bh][d][s]

// ---------------- helpers ----------------
__device__ __forceinline__ uint32_t smem_u32(const void* p) {
    uint32_t a;
    asm("{ .reg .u64 t; cvta.to.shared.u64 t, %1; cvt.u32.u64 %0, t; }" : "=r"(a) : "l"(p));
    return a;
}
__device__ __forceinline__ void cp16(uint32_t dst, const void* src) {
    asm volatile("cp.async.cg.shared.global [%0], [%1], 16;\n" :: "r"(dst), "l"(src));
}
__device__ __forceinline__ void ldsm4(uint32_t* r, uint32_t addr) {
    asm volatile("ldmatrix.sync.aligned.m8n8.x4.shared.b16 {%0,%1,%2,%3}, [%4];"
        : "=r"(r[0]), "=r"(r[1]), "=r"(r[2]), "=r"(r[3]) : "r"(addr));
}
__device__ __forceinline__ void ldsm2(uint32_t* r, uint32_t addr) {
    asm volatile("ldmatrix.sync.aligned.m8n8.x2.shared.b16 {%0,%1}, [%2];"
        : "=r"(r[0]), "=r"(r[1]) : "r"(addr));
}
__device__ __forceinline__ void mma16816(float* d, const uint32_t* a, const uint32_t* b) {
    asm volatile("mma.sync.aligned.m16n8k16.row.col.f32.bf16.bf16.f32 "
        "{%0,%1,%2,%3}, {%4,%5,%6,%7}, {%8,%9}, {%0,%1,%2,%3};"
        : "+f"(d[0]), "+f"(d[1]), "+f"(d[2]), "+f"(d[3])
        : "r"(a[0]), "r"(a[1]), "r"(a[2]), "r"(a[3]), "r"(b[0]), "r"(b[1]));
}

// ---------------- conversions ----------------
__global__ __launch_bounds__(256) void aconv_kernel(const float* __restrict__ a,
    __nv_bfloat16* __restrict__ hi, __nv_bfloat16* __restrict__ lo)
{
    size_t i = ((size_t)blockIdx.x * 256 + threadIdx.x) * 4;
    float4 v = *(const float4*)&a[i];
    float vv[4] = {v.x, v.y, v.z, v.w};
    ushort4 h, l;
    unsigned short* hp = &h.x; unsigned short* lp = &l.x;
#pragma unroll
    for (int j = 0; j < 4; j++) {
        __nv_bfloat16 hb = __float2bfloat16(vv[j]);
        __nv_bfloat16 lb = __float2bfloat16(vv[j] - __bfloat162float(hb));
        hp[j] = __bfloat16_as_ushort(hb);
        lp[j] = __bfloat16_as_ushort(lb);
    }
    *(ushort4*)&hi[i] = h;
    *(ushort4*)&lo[i] = l;
}

// W [k][n] f32 -> hi [n][k] bf16 (plain bf16, no lo)
__global__ __launch_bounds__(256) void wconv_kernel(const float* __restrict__ W,
    __nv_bfloat16* __restrict__ hi)
{
    __shared__ float tile[32][33];
    int bx = blockIdx.x * 32;
    int by = blockIdx.y * 32;
    int tx = threadIdx.x, ty = threadIdx.y;
#pragma unroll
    for (int i = 0; i < 32; i += 8)
        tile[ty + i][tx] = W[(size_t)(by + ty + i) * 1024 + bx + tx];
    __syncthreads();
#pragma unroll
    for (int i = 0; i < 32; i += 8) {
        int n = bx + ty + i, k = by + tx;
        hi[(size_t)n * 1024 + k] = __float2bfloat16(tile[tx][ty + i]);
    }
}

// ---------------- mma.sync 2-leg split GEMM (A hi/lo x B bf16) ----------------
#define SROW 40
#define MAT_E (128*SROW)          // elems per matrix (5120)
#define SST_B (3*MAT_E*2)         // stage bytes: Ahi, Alo, Bh = 30720
#define GEMM_SMEM (2*SST_B)       // 61440

__device__ __forceinline__ void load_chunk_mm(uint32_t sb, int t, int m0, int n0, int k0,
    const __nv_bfloat16* Ahi, const __nv_bfloat16* Alo, const __nv_bfloat16* Bh)
{
#pragma unroll
    for (int i = 0; i < 2; i++) {
        int cid = i * 256 + t;
        int row = cid >> 2, c = cid & 3;
        uint32_t off = (uint32_t)(row * (SROW*2) + c * 16);
        cp16(sb + off,             (const char*)(Ahi + (size_t)(m0 + row) * 1024 + k0) + c * 16);
        cp16(sb + MAT_E*2 + off,   (const char*)(Alo + (size_t)(m0 + row) * 1024 + k0) + c * 16);
        cp16(sb + 2*MAT_E*2 + off, (const char*)(Bh  + (size_t)(n0 + row) * 1024 + k0) + c * 16);
    }
    asm volatile("cp.async.commit_group;\n" ::: "memory");
}

__device__ __forceinline__ void gemm_body(
    uint32_t sb, int m0, int n0,
    const __nv_bfloat16* Ahi, const __nv_bfloat16* Alo, const __nv_bfloat16* Bh,
    const float* bias, const float* resid, float* out, int do_tanh)
{
    int t = threadIdx.x;
    int warp = t >> 5, lane = t & 31;
    int wm = warp & 1, wn = warp >> 1;

    float acc[4][4][4];
#pragma unroll
    for (int a = 0; a < 4; a++)
#pragma unroll
        for (int b = 0; b < 4; b++)
#pragma unroll
            for (int c = 0; c < 4; c++) acc[a][b][c] = 0.f;

    int aq = lane >> 3;
    int arow = (aq & 1) * 8 + (lane & 7);
    int akoff = (aq >> 1) * 8;
    int brow = lane & 7;
    int bkoff = ((lane >> 3) & 1) * 8;

    load_chunk_mm(sb, t, m0, n0, 0, Ahi, Alo, Bh);

#pragma unroll 1
    for (int c = 0; c < 32; c++) {
        if (c < 31)
            load_chunk_mm(sb + ((c + 1) & 1) * SST_B, t, m0, n0, (c + 1) * 32, Ahi, Alo, Bh);
        if (c < 31) asm volatile("cp.async.wait_group 1;\n" ::: "memory");
        else        asm volatile("cp.async.wait_group 0;\n" ::: "memory");
        __syncthreads();

        uint32_t st = sb + (c & 1) * SST_B;
#pragma unroll
        for (int k16 = 0; k16 < 2; k16++) {
            int kb = k16 * 16;
            uint32_t ah[4][4], al[4][4];
#pragma unroll
            for (int mt = 0; mt < 4; mt++) {
                uint32_t aaddr = st + (uint32_t)(((wm*64 + mt*16 + arow) * SROW + kb + akoff) * 2);
                ldsm4(ah[mt], aaddr);
                ldsm4(al[mt], aaddr + MAT_E*2);
            }
#pragma unroll
            for (int nt = 0; nt < 4; nt++) {
                uint32_t baddr = st + 2*MAT_E*2 +
                    (uint32_t)(((wn*32 + nt*8 + brow) * SROW + kb + bkoff) * 2);
                uint32_t bh2[2];
                ldsm2(bh2, baddr);
#pragma unroll
                for (int mt = 0; mt < 4; mt++) {
                    mma16816(acc[mt][nt], ah[mt], bh2);
                    mma16816(acc[mt][nt], al[mt], bh2);
                }
            }
        }
        __syncthreads();
    }

    int rin = lane >> 2, cin = (lane & 3) * 2;
#pragma unroll
    for (int mt = 0; mt < 4; mt++) {
#pragma unroll
        for (int nt = 0; nt < 4; nt++) {
            int n = n0 + wn*32 + nt*8 + cin;
            float b0 = bias[n], b1 = bias[n + 1];
#pragma unroll
            for (int half = 0; half < 2; half++) {
                int m = m0 + wm*64 + mt*16 + rin + half*8;
                float v0 = acc[mt][nt][half*2 + 0] + b0;
                float v1 = acc[mt][nt][half*2 + 1] + b1;
                if (resid) {
                    const float* rr = resid + (size_t)m * 1024 + n;
                    v0 += rr[0]; v1 += rr[1];
                }
                if (do_tanh) { v0 = tanhf(v0); v1 = tanhf(v1); }
                *(float2*)&out[(size_t)m * 1024 + n] = make_float2(v0, v1);
            }
        }
    }
}

struct GemmP5 {
    const __nv_bfloat16* Bh[5];
    const float* bias[5];
    float* out[5];
    int tanh_f[5];
};

__global__ __launch_bounds__(256) void mma_gemm5_kernel(
    const __nv_bfloat16* __restrict__ Ah, const __nv_bfloat16* __restrict__ Al, GemmP5 P)
{
    extern __shared__ char smem[];
    uint32_t sb = smem_u32(smem);
    int z = blockIdx.z;
    gemm_body(sb, blockIdx.x * 128, blockIdx.y * 128,
              Ah, Al, P.Bh[z], P.bias[z], nullptr, P.out[z], P.tanh_f[z]);
}

__global__ __launch_bounds__(256) void mma_gemm_kernel(
    const __nv_bfloat16* __restrict__ Ahi, const __nv_bfloat16* __restrict__ Alo,
    const __nv_bfloat16* __restrict__ Bh,
    const float* __restrict__ bias, const float* __restrict__ resid,
    float* __restrict__ out, int do_tanh)
{
    extern __shared__ char smem[];
    uint32_t sb = smem_u32(smem);
    gemm_body(sb, blockIdx.x * 128, blockIdx.y * 128,
              Ahi, Alo, Bh, bias, resid, out, do_tanh);
}

// ---------------- prep: M = qw @ em ----------------
__global__ void prep_m_kernel(const float* __restrict__ qqr, const float* __restrict__ qqi,
                              const float* __restrict__ qkr, const float* __restrict__ qki,
                              const float* __restrict__ qqem, const float* __restrict__ qkem)
{
    int t = threadIdx.x;
    int u = t >> 4, v = t & 15;
    float a = 0.f, b = 0.f, c = 0.f, d = 0.f;
#pragma unroll
    for (int w = 0; w < 16; w++) {
        float e1 = qqem[w*16+v], e2 = qkem[w*16+v];
        a += qqr[u*16+w]*e1;
        b += qqi[u*16+w]*e1;
        c += qkr[u*16+w]*e2;
        d += qki[u*16+w]*e2;
    }
    g_M[t] = a; g_M[256+t] = b; g_M[512+t] = c; g_M[768+t] = d;
}

// ---------------- quantum small path ----------------
__global__ __launch_bounds__(128) void quantum_kernel(
    const float* __restrict__ x, const float* __restrict__ sgq, const float* __restrict__ sgk)
{
    __shared__ float xs[1024];
    __shared__ float part[8][16];
    __shared__ float qss[16];
    __shared__ float prob_s[16];
    int i = blockIdx.x;
    int t = threadIdx.x;
#pragma unroll
    for (int c = 0; c < 2; c++)
        *(float4*)&xs[(t + c*128)*4] = *(const float4*)&x[(size_t)i*1024 + (t + c*128)*4];
    __syncthreads();
    int tt = t & 15, pp = t >> 4;
#pragma unroll 1
    for (int side = 0; side < 2; side++) {
        const float* sg = side ? sgk : sgq;
        float acc = 0.f;
        int base = pp * 128;
        for (int d = 0; d < 128; d++)
            acc += xs[base + d] * sg[(base + d)*16 + tt];
        part[pp][tt] = acc;
        __syncthreads();
        if (t < 16) {
            float q = 0.f;
#pragma unroll
            for (int p = 0; p < 8; p++) q += part[p][t];
            qss[t] = q;
        }
        __syncthreads();
        if (t < 16) {
            const float* Mr = g_M + side*512;
            const float* Mi = Mr + 256;
            float er = 0.f, ei = 0.f;
#pragma unroll
            for (int u = 0; u < 16; u++) {
                er += qss[u]*Mr[u*16+t];
                ei += qss[u]*Mi[u*16+t];
            }
            float pr = er*er + ei*ei;
            prob_s[t] = pr;
            (side ? g_probs_k : g_probs_q)[i*16 + t] = pr;
        }
        __syncthreads();
        if (t == 0) {
            float ms = 0.f;
#pragma unroll
            for (int u = 0; u < 16; u++) ms += prob_s[u];
            ms *= (1.f/16.f);
            (side ? g_fw_k : g_fw_q)[i] = 1.f/(1.f + __expf(-ms));
        }
        __syncthreads();
    }
}

// ---------------- combine ----------------
__global__ __launch_bounds__(256) void combine_kernel(
    const float* __restrict__ qq_mb, const float* __restrict__ qk_mb)
{
    int i = blockIdx.x;
    int b = i >> 11, s = i & 2047;
    int t = threadIdx.x;
    __shared__ float pqs[16], pks[16];
    if (t < 16) pqs[t] = g_probs_q[i*16 + t];
    else if (t < 32) pks[t-16] = g_probs_k[i*16 + (t-16)];
    __syncthreads();
    float fq = g_fw_q[i], fk = g_fw_k[i];
    int d0 = t * 4;
    float4 qv = *(const float4*)&g_Q [(size_t)i*1024 + d0];
    float4 kv = *(const float4*)&g_K [(size_t)i*1024 + d0];
    float4 vv = *(const float4*)&g_V [(size_t)i*1024 + d0];
    float4 cq = *(const float4*)&g_Cq[(size_t)i*1024 + d0];
    float4 ck = *(const float4*)&g_Ck[(size_t)i*1024 + d0];
    const float* qvp = (const float*)&qv;
    const float* kvp = (const float*)&kv;
    const float* cqp = (const float*)&cq;
    const float* ckp = (const float*)&ck;
    ushort4 qh4, ql4, kh4;
    unsigned short* qhp = &qh4.x; unsigned short* qlp = &ql4.x;
    unsigned short* khp = &kh4.x;
#pragma unroll
    for (int j = 0; j < 4; j++) {
        int d = d0 + j;
        float qmb = 0.f, kmb = 0.f;
#pragma unroll
        for (int u = 0; u < 16; u++) {
            qmb += pqs[u] * qq_mb[u*1024 + d];
            kmb += pks[u] * qk_mb[u*1024 + d];
        }
        float qq = fq*qmb + (1.f - fq)*cqp[j];
        float kq = fk*kmb + (1.f - fk)*ckp[j];
        float oq = (0.7f*qvp[j] + 0.3f*qq) * 0.125f;
        float ok =  0.7f*kvp[j] + 0.3f*kq;
        __nv_bfloat16 hb = __float2bfloat16(oq);
        qhp[j] = __bfloat16_as_ushort(hb);
        qlp[j] = __bfloat16_as_ushort(__float2bfloat16(oq - __bfloat162float(hb)));
        khp[j] = __bfloat16_as_ushort(__float2bfloat16(ok));
    }
    int h = d0 >> 6, dh = d0 & 63;
    int bh = b*16 + h;
    size_t qb = ((size_t)bh*SEQ + s)*AD + dh;
    *(ushort4*)&g_Qah[qb] = qh4;
    *(ushort4*)&g_Qal[qb] = ql4;
    *(ushort4*)&g_Kah[qb] = kh4;
    *(float4*)&g_Va[((size_t)bh*SEQ + s)*HD + dh] = vv;
    int h2 = t >> 4, u = t & 15;
    int bh2 = b*16 + h2;
    size_t tb = ((size_t)bh2*SEQ + s)*AD + 64 + u;
    float tv = 0.1f * pqs[u];
    __nv_bfloat16 th = __float2bfloat16(tv);
    g_Qah[tb] = th;
    g_Qal[tb] = __float2bfloat16(tv - __bfloat162float(th));
    g_Kah[tb] = __float2bfloat16(pks[u]);
}

// ---------------- V transpose: Va [bh][s][64] f32 -> Vth [bh][d][s] bf16 ----------------
__global__ __launch_bounds__(256) void vtrans_kernel()
{
    __shared__ float tile[64][65];
    int s0 = blockIdx.x * 64, bh = blockIdx.y;
    int t = threadIdx.x;
    int r = t >> 2, c4 = (t & 3) * 16;
    const float* src = g_Va + ((size_t)bh*SEQ + s0 + r)*HD + c4;
#pragma unroll
    for (int j = 0; j < 16; j += 4) {
        float4 v = *(const float4*)&src[j];
        tile[r][c4 + j + 0] = v.x;
        tile[r][c4 + j + 1] = v.y;
        tile[r][c4 + j + 2] = v.z;
        tile[r][c4 + j + 3] = v.w;
    }
    __syncthreads();
    int d = t >> 2, sc = (t & 3) * 16;
    ushort4 ho[4];
#pragma unroll
    for (int j = 0; j < 16; j++) {
        float v = tile[sc + j][d];
        (&ho[j >> 2].x)[j & 3] = __bfloat16_as_ushort(__float2bfloat16(v));
    }
    size_t base = ((size_t)bh*HD + d)*SEQ + s0 + sc;
#pragma unroll
    for (int j = 0; j < 4; j++)
        *(ushort4*)&g_Vth[base + j*4] = ho[j];
}

// ---------------- flash attention with mma.sync ----------------
// smem layout (bytes):
//  Qhi 0..11264, Qlo 11264..22528
//  stage s at ST0B + s*STAGEB: K(22528) V(+22528, 17408); STAGEB=39936
//  Phi at PHIB(17408), reductions at REDB(1024)
#define QLOB 11264
#define ST0B 22528
#define VOFF 22528
#define STAGEB 39936
#define PHIB 102400
#define REDB 119808
#define FLASH2_SMEM 120832

__device__ __forceinline__ void load_q_f(uint32_t sb, int t, int bh, int qt)
{
    const char* qh = (const char*)(g_Qah + ((size_t)bh*SEQ + qt*64)*AD);
    const char* ql = (const char*)(g_Qal + ((size_t)bh*SEQ + qt*64)*AD);
#pragma unroll 1
    for (int i = t; i < 640; i += 256) {
        int row = i / 10, c = i % 10;
        uint32_t off = (uint32_t)(row*176 + c*16);
        cp16(sb + off, qh + (size_t)row*160 + c*16);
        cp16(sb + QLOB + off, ql + (size_t)row*160 + c*16);
    }
}

__device__ __forceinline__ void load_kv_f(uint32_t stb, int t, int bh, int k0)
{
    const char* kh = (const char*)(g_Kah + ((size_t)bh*SEQ + k0)*AD);
#pragma unroll 1
    for (int i = t; i < 1280; i += 256) {
        int row = i / 10, c = i % 10;
        cp16(stb + (uint32_t)(row*176 + c*16), kh + (size_t)row*160 + c*16);
    }
    const __nv_bfloat16* vh = g_Vth + (size_t)bh*HD*SEQ + k0;
#pragma unroll 1
    for (int i = t; i < 1024; i += 256) {
        int d = i >> 4, c = i & 15;
        cp16(stb + VOFF + (uint32_t)(d*272 + c*16), (const char*)(vh + (size_t)d*SEQ) + c*16);
    }
    asm volatile("cp.async.commit_group;\n" ::: "memory");
}

__global__ __launch_bounds__(256) void flash_mma_kernel(float* __restrict__ w_out)
{
    extern __shared__ char smem[];
    uint32_t sb = smem_u32(smem);
    float* redm = (float*)(smem + REDB);      // [2][64]
    float* reds = redm + 128;                 // [2][64]
    __nv_bfloat162* Pph = (__nv_bfloat162*)(smem + PHIB);

    int qt = blockIdx.x, bh = blockIdx.y;
    int t = threadIdx.x;
    int warp = t >> 5, lane = t & 31;
    int wm = warp & 3, wn = warp >> 2;       // 4 m-strips x 2 n-halves

    int aq = lane >> 3;
    int arow = (aq & 1) * 8 + (lane & 7);
    int akoff = (aq >> 1) * 8;
    int b4n = (lane >> 4) * 8 + (lane & 7);
    int b4k = ((lane >> 3) & 1) * 8;
    int rin = lane >> 2, cin = (lane & 3) * 2;

    load_q_f(sb, t, bh, qt);
    load_kv_f(sb + ST0B, t, bh, 0);
    load_kv_f(sb + ST0B + STAGEB, t, bh, 128);

    float m_run0 = -1e30f, m_run1 = -1e30f;
    float l_run0 = 0.f, l_run1 = 0.f;
    float O[4][4];
#pragma unroll
    for (int a = 0; a < 4; a++)
#pragma unroll
        for (int b = 0; b < 4; b++) O[a][b] = 0.f;
    uint32_t qfh[5][4], qfl[5][4];

    int r0 = wm*16 + rin, r1 = r0 + 8;

#pragma unroll 1
    for (int kt = 0; kt < 16; kt++) {
        if (kt < 15) asm volatile("cp.async.wait_group 1;\n" ::: "memory");
        else         asm volatile("cp.async.wait_group 0;\n" ::: "memory");
        __syncthreads();
        uint32_t st = sb + ST0B + (kt & 1) * STAGEB;

        if (kt == 0) {
#pragma unroll
            for (int ks = 0; ks < 5; ks++) {
                uint32_t qaddr = sb + (uint32_t)(((wm*16 + arow)*88 + ks*16 + akoff) * 2);
                ldsm4(qfh[ks], qaddr);
                ldsm4(qfl[ks], qaddr + QLOB);
            }
        }

        // ---- S = Q @ K^T (2-leg: Qhi*K + Qlo*K) ----
        float sacc[8][4];
#pragma unroll
        for (int a = 0; a < 8; a++)
#pragma unroll
            for (int b = 0; b < 4; b++) sacc[a][b] = 0.f;
#pragma unroll
        for (int ks = 0; ks < 5; ks++) {
            int kb = ks * 16;
#pragma unroll
            for (int p = 0; p < 4; p++) {
                uint32_t kaddr = st + (uint32_t)(((wn*64 + p*16 + b4n)*88 + kb + b4k) * 2);
                uint32_t kh4[4];
                ldsm4(kh4, kaddr);
                mma16816(sacc[2*p],   qfh[ks], kh4);
                mma16816(sacc[2*p+1], qfh[ks], kh4+2);
                mma16816(sacc[2*p],   qfl[ks], kh4);
                mma16816(sacc[2*p+1], qfl[ks], kh4+2);
            }
        }

        // ---- online softmax ----
        float lm0 = -1e30f, lm1 = -1e30f;
#pragma unroll
        for (int nt = 0; nt < 8; nt++) {
            lm0 = fmaxf(lm0, fmaxf(sacc[nt][0], sacc[nt][1]));
            lm1 = fmaxf(lm1, fmaxf(sacc[nt][2], sacc[nt][3]));
        }
        lm0 = fmaxf(lm0, __shfl_xor_sync(0xffffffffu, lm0, 1));
        lm0 = fmaxf(lm0, __shfl_xor_sync(0xffffffffu, lm0, 2));
        lm1 = fmaxf(lm1, __shfl_xor_sync(0xffffffffu, lm1, 1));
        lm1 = fmaxf(lm1, __shfl_xor_sync(0xffffffffu, lm1, 2));
        if ((lane & 3) == 0) {
            redm[wn*64 + r0] = lm0;
            redm[wn*64 + r1] = lm1;
        }
        __syncthreads();
        float mn0 = fmaxf(m_run0, fmaxf(redm[r0], redm[64 + r0]));
        float mn1 = fmaxf(m_run1, fmaxf(redm[r1], redm[64 + r1]));
        float al0 = __expf(m_run0 - mn0);
        float al1 = __expf(m_run1 - mn1);
        m_run0 = mn0; m_run1 = mn1;

        float ls0 = 0.f, ls1 = 0.f;
        size_t wrow0 = ((size_t)bh*SEQ + qt*64 + r0) * SEQ + (size_t)kt*128 + wn*64 + cin;
        size_t wrow1 = wrow0 + (size_t)8 * SEQ;
        int pc = wn*32 + (cin >> 1);
#pragma unroll
        for (int nt = 0; nt < 8; nt++) {
            float p0 = __expf(sacc[nt][0] - mn0);
            float p1 = __expf(sacc[nt][1] - mn0);
            float p2 = __expf(sacc[nt][2] - mn1);
            float p3 = __expf(sacc[nt][3] - mn1);
            ls0 += p0 + p1; ls1 += p2 + p3;
            *(float2*)&w_out[wrow0 + nt*8] = make_float2(p0, p1);
            *(float2*)&w_out[wrow1 + nt*8] = make_float2(p2, p3);
            __nv_bfloat162 hv0; hv0.x = __float2bfloat16(p0); hv0.y = __float2bfloat16(p1);
            __nv_bfloat162 hv1; hv1.x = __float2bfloat16(p2); hv1.y = __float2bfloat16(p3);
            Pph[r0*68 + pc + nt*4] = hv0;
            Pph[r1*68 + pc + nt*4] = hv1;
        }
        ls0 += __shfl_xor_sync(0xffffffffu, ls0, 1);
        ls0 += __shfl_xor_sync(0xffffffffu, ls0, 2);
        ls1 += __shfl_xor_sync(0xffffffffu, ls1, 1);
        ls1 += __shfl_xor_sync(0xffffffffu, ls1, 2);
        if ((lane & 3) == 0) {
            reds[wn*64 + r0] = ls0;
            reds[wn*64 + r1] = ls1;
        }
        if (wn == 0 && (lane & 3) == 0) {
            g_mt[((size_t)bh*SEQ + qt*64 + r0)*16 + kt] = mn0;
            g_mt[((size_t)bh*SEQ + qt*64 + r1)*16 + kt] = mn1;
        }
#pragma unroll
        for (int nt = 0; nt < 4; nt++) {
            O[nt][0] *= al0; O[nt][1] *= al0;
            O[nt][2] *= al1; O[nt][3] *= al1;
        }
        __syncthreads();
        l_run0 = l_run0*al0 + reds[r0] + reds[64 + r0];
        l_run1 = l_run1*al1 + reds[r1] + reds[64 + r1];

        // ---- O += P @ V (bf16) ----
#pragma unroll
        for (int ks = 0; ks < 8; ks++) {
            int kb = ks * 16;
            uint32_t paddr = sb + PHIB + (uint32_t)(((wm*16 + arow)*136 + kb + akoff) * 2);
            uint32_t pf[4];
            ldsm4(pf, paddr);
#pragma unroll
            for (int p = 0; p < 2; p++) {
                uint32_t vaddr = st + VOFF + (uint32_t)(((wn*32 + p*16 + b4n)*136 + kb + b4k) * 2);
                uint32_t vh4[4];
                ldsm4(vh4, vaddr);
                mma16816(O[2*p],   pf, vh4);
                mma16816(O[2*p+1], pf, vh4+2);
            }
        }
        __syncthreads();
        if (kt + 2 < 16) load_kv_f(st, t, bh, (kt + 2) * 128);
    }

    // ---- epilogue: write att as bf16 hi/lo directly ----
    float inv0 = 1.f / l_run0, inv1 = 1.f / l_run1;
    int b = bh >> 4, h = bh & 15;
    int rg0 = qt*64 + r0;
#pragma unroll
    for (int nt = 0; nt < 4; nt++) {
        int d = h*64 + wn*32 + nt*8 + cin;
        float o0 = O[nt][0]*inv0, o1 = O[nt][1]*inv0;
        float o2 = O[nt][2]*inv1, o3 = O[nt][3]*inv1;
        size_t i0 = ((size_t)b*SEQ + rg0)*1024 + d;
        size_t i1 = ((size_t)b*SEQ + rg0 + 8)*1024 + d;
        __nv_bfloat162 h0; h0.x = __float2bfloat16(o0); h0.y = __float2bfloat16(o1);
        __nv_bfloat162 h1; h1.x = __float2bfloat16(o2); h1.y = __float2bfloat16(o3);
        __nv_bfloat162 l0;
        l0.x = __float2bfloat16(o0 - __bfloat162float(h0.x));
        l0.y = __float2bfloat16(o1 - __bfloat162float(h0.y));
        __nv_bfloat162 l1;
        l1.x = __float2bfloat16(o2 - __bfloat162float(h1.x));
        l1.y = __float2bfloat16(o3 - __bfloat162float(h1.y));
        *(__nv_bfloat162*)&g_ahi[i0] = h0;
        *(__nv_bfloat162*)&g_ahi[i1] = h1;
        *(__nv_bfloat162*)&g_alo[i0] = l0;
        *(__nv_bfloat162*)&g_alo[i1] = l1;
    }
    if (wn == 0 && (lane & 3) == 0) {
        g_m[(size_t)bh*SEQ + rg0] = m_run0;
        g_l[(size_t)bh*SEQ + rg0] = l_run0;
        g_m[(size_t)bh*SEQ + rg0 + 8] = m_run1;
        g_l[(size_t)bh*SEQ + rg0 + 8] = l_run1;
    }
}

// ---------------- normalize w ----------------
__global__ __launch_bounds__(256) void norm_w_kernel(float* __restrict__ w)
{
    size_t idx = (size_t)blockIdx.x * 256 + threadIdx.x;
    size_t e0 = idx * 4;
    size_t row = e0 >> 11;
    int kt = (int)((e0 & 2047) >> 7);
    float f = __expf(g_mt[row*16 + kt] - g_m[row]) / g_l[row];
    float4 v = *(float4*)&w[e0];
    v.x *= f; v.y *= f; v.z *= f; v.w *= f;
    *(float4*)&w[e0] = v;
}

// ---------------- layernorm ----------------
__global__ __launch_bounds__(256) void ln_kernel(const float* __restrict__ gam,
    const float* __restrict__ bet, float* __restrict__ y)
{
    int i = blockIdx.x, t = threadIdx.x;
    float4 v = *(const float4*)&g_res[(size_t)i*1024 + t*4];
    float s  = v.x + v.y + v.z + v.w;
    float ss = v.x*v.x + v.y*v.y + v.z*v.z + v.w*v.w;
#pragma unroll
    for (int off = 16; off; off >>= 1) {
        s  += __shfl_xor_sync(0xffffffffu, s,  off);
        ss += __shfl_xor_sync(0xffffffffu, ss, off);
    }
    __shared__ float as[8], ass[8];
    if ((t & 31) == 0) { as[t >> 5] = s; ass[t >> 5] = ss; }
    __syncthreads();
    float S = 0.f, SS = 0.f;
#pragma unroll
    for (int u = 0; u < 8; u++) { S += as[u]; SS += ass[u]; }
    float mu  = S * (1.f/1024.f);
    float var = SS * (1.f/1024.f) - mu*mu;
    float inv = rsqrtf(var + 1e-5f);
    float4 gg = *(const float4*)&gam[t*4];
    float4 bb = *(const float4*)&bet[t*4];
    float4 o;
    o.x = (v.x - mu)*inv*gg.x + bb.x;
    o.y = (v.y - mu)*inv*gg.y + bb.y;
    o.z = (v.z - mu)*inv*gg.z + bb.z;
    o.w = (v.w - mu)*inv*gg.w + bb.w;
    *(float4*)&y[(size_t)i*1024 + t*4] = o;
}

// ---------------- launch ----------------
extern "C" void kernel_launch(void* const* d_in, const int* in_sizes, int n_in,
                              void* d_out, int out_size)
{
    const float* x       = (const float*)d_in[0];
    const float* Wq      = (const float*)d_in[1];
    const float* bq      = (const float*)d_in[2];
    const float* Wk      = (const float*)d_in[3];
    const float* bk      = (const float*)d_in[4];
    const float* Wv      = (const float*)d_in[5];
    const float* bv      = (const float*)d_in[6];
    const float* Wo      = (const float*)d_in[7];
    const float* bo      = (const float*)d_in[8];
    const float* ln_g    = (const float*)d_in[9];
    const float* ln_b    = (const float*)d_in[10];
    const float* qq_W    = (const float*)d_in[11];
    const float* qq_b    = (const float*)d_in[12];
    const float* qq_qw_r = (const float*)d_in[13];
    const float* qq_qw_i = (const float*)d_in[14];
    const float* qq_sg   = (const float*)d_in[15];
    const float* qq_em   = (const float*)d_in[16];
    const float* qq_mb   = (const float*)d_in[17];
    const float* qk_W    = (const float*)d_in[18];
    const float* qk_b    = (const float*)d_in[19];
    const float* qk_qw_r = (const float*)d_in[20];
    const float* qk_qw_i = (const float*)d_in[21];
    const float* qk_sg   = (const float*)d_in[22];
    const float* qk_em   = (const float*)d_in[23];
    const float* qk_mb   = (const float*)d_in[24];

    float* y = (float*)d_out;
    float* w = y + (size_t)MROWS*DMODEL;

    float *pQ, *pK, *pV, *pCq, *pCk, *pRes;
    cudaGetSymbolAddress((void**)&pQ,   g_Q);
    cudaGetSymbolAddress((void**)&pK,   g_K);
    cudaGetSymbolAddress((void**)&pV,   g_V);
    cudaGetSymbolAddress((void**)&pCq,  g_Cq);
    cudaGetSymbolAddress((void**)&pCk,  g_Ck);
    cudaGetSymbolAddress((void**)&pRes, g_res);
    __nv_bfloat16 *pXh, *pXl, *pAh, *pAl, *pWh;
    cudaGetSymbolAddress((void**)&pXh, g_xhi);
    cudaGetSymbolAddress((void**)&pXl, g_xlo);
    cudaGetSymbolAddress((void**)&pAh, g_ahi);
    cudaGetSymbolAddress((void**)&pAl, g_alo);
    cudaGetSymbolAddress((void**)&pWh, g_Whi);

    cudaFuncSetAttribute(mma_gemm_kernel,
        cudaFuncAttributeMaxDynamicSharedMemorySize, GEMM_SMEM);
    cudaFuncSetAttribute(mma_gemm5_kernel,
        cudaFuncAttributeMaxDynamicSharedMemorySize, GEMM_SMEM);
    cudaFuncSetAttribute(flash_mma_kernel,
        cudaFuncAttributeMaxDynamicSharedMemorySize, FLASH2_SMEM);

    prep_m_kernel<<<1, 256>>>(qq_qw_r, qq_qw_i, qk_qw_r, qk_qw_i, qq_em, qk_em);
    quantum_kernel<<<MROWS, 128>>>(x, qq_sg, qk_sg);

    aconv_kernel<<<MROWS*DMODEL/(256*4), 256>>>(x, pXh, pXl);
    dim3 wg(32, 32), wb(32, 8);
    const size_t WSZ = (size_t)DMODEL*DMODEL;
    wconv_kernel<<<wg, wb>>>(Wq,   pWh + 0*WSZ);
    wconv_kernel<<<wg, wb>>>(Wk,   pWh + 1*WSZ);
    wconv_kernel<<<wg, wb>>>(Wv,   pWh + 2*WSZ);
    wconv_kernel<<<wg, wb>>>(qq_W, pWh + 3*WSZ);
    wconv_kernel<<<wg, wb>>>(qk_W, pWh + 4*WSZ);
    wconv_kernel<<<wg, wb>>>(Wo,   pWh + 5*WSZ);

    // 5 forward GEMMs in one launch
    GemmP5 P;
    P.Bh[0] = pWh + 0*WSZ; P.bias[0] = bq;   P.out[0] = pQ;  P.tanh_f[0] = 0;
    P.Bh[1] = pWh + 1*WSZ; P.bias[1] = bk;   P.out[1] = pK;  P.tanh_f[1] = 0;
    P.Bh[2] = pWh + 2*WSZ; P.bias[2] = bv;   P.out[2] = pV;  P.tanh_f[2] = 0;
    P.Bh[3] = pWh + 3*WSZ; P.bias[3] = qq_b; P.out[3] = pCq; P.tanh_f[3] = 1;
    P.Bh[4] = pWh + 4*WSZ; P.bias[4] = qk_b; P.out[4] = pCk; P.tanh_f[4] = 1;
    dim3 g5(32, 8, 5);
    mma_gemm5_kernel<<<g5, 256, GEMM_SMEM>>>(pXh, pXl, P);

    combine_kernel<<<MROWS, 256>>>(qq_mb, qk_mb);
    vtrans_kernel<<<dim3(32, 32), 256>>>();

    flash_mma_kernel<<<dim3(32, 32), 256, FLASH2_SMEM>>>(w);

    norm_w_kernel<<<(NBH*(size_t)SEQ*SEQ)/(4*256), 256>>>(w);

    // output projection: att @ Wo + bo + x  (att hi/lo came straight from flash)
    dim3 gg(32, 8);
    mma_gemm_kernel<<<gg, 256, GEMM_SMEM>>>(pAh, pAl, pWh + 5*WSZ, bo, x, pRes, 0);

    ln_kernel<<<MROWS, 256>>>(ln_g, ln_b, y);
}

// round 8
// speedup vs baseline: 3.0931x; 1.0240x over previous
#include <cuda_runtime.h>
#include <cuda_bf16.h>
#include <cstdint>
#include <math.h>

#define MROWS 4096
#define DMODEL 1024
#define NH 16
#define HD 64
#define QD 16
#define SEQ 2048
#define NBH 32
#define AD 80

// ---------------- scratch ----------------
__device__ float g_Q[MROWS*DMODEL];
__device__ float g_K[MROWS*DMODEL];
__device__ float g_V[MROWS*DMODEL];
__device__ float g_Cq[MROWS*DMODEL];
__device__ float g_Ck[MROWS*DMODEL];
__device__ float g_res[MROWS*DMODEL];
__device__ float g_Va[NBH*SEQ*HD];
__device__ float g_probs_q[MROWS*QD];
__device__ float g_probs_k[MROWS*QD];
__device__ float g_fw_q[MROWS];
__device__ float g_fw_k[MROWS];
__device__ float g_m[NBH*SEQ];
__device__ float g_l[NBH*SEQ];
__device__ float g_mt[NBH*SEQ*16];    // running max snapshot per 128-key tile
__device__ float g_M[4*256];

// bf16 buffers
__device__ __nv_bfloat16 g_xhi[MROWS*DMODEL];
__device__ __nv_bfloat16 g_xlo[MROWS*DMODEL];
__device__ __nv_bfloat16 g_ahi[MROWS*DMODEL];     // att hi (written by flash)
__device__ __nv_bfloat16 g_alo[MROWS*DMODEL];     // att lo
__device__ __nv_bfloat16 g_Whi[6*DMODEL*DMODEL];  // [widx][n][k]
// flash operands
__device__ __nv_bfloat16 g_Qah[NBH*SEQ*AD];   // [bh][s][80] = [0.125*Qf, 0.1*qp]
__device__ __nv_bfloat16 g_Qal[NBH*SEQ*AD];
__device__ __nv_bfloat16 g_Kah[NBH*SEQ*AD];   // [bh][s][80] = [Kf, kp]  (plain bf16)
__device__ __nv_bfloat16 g_Vth[NBH*HD*SEQ];   // [bh][d][s]

// ---------------- helpers ----------------
__device__ __forceinline__ uint32_t smem_u32(const void* p) {
    uint32_t a;
    asm("{ .reg .u64 t; cvta.to.shared.u64 t, %1; cvt.u32.u64 %0, t; }" : "=r"(a) : "l"(p));
    return a;
}
__device__ __forceinline__ void cp16(uint32_t dst, const void* src) {
    asm volatile("cp.async.cg.shared.global [%0], [%1], 16;\n" :: "r"(dst), "l"(src));
}
__device__ __forceinline__ void ldsm4(uint32_t* r, uint32_t addr) {
    asm volatile("ldmatrix.sync.aligned.m8n8.x4.shared.b16 {%0,%1,%2,%3}, [%4];"
        : "=r"(r[0]), "=r"(r[1]), "=r"(r[2]), "=r"(r[3]) : "r"(addr));
}
__device__ __forceinline__ void ldsm2(uint32_t* r, uint32_t addr) {
    asm volatile("ldmatrix.sync.aligned.m8n8.x2.shared.b16 {%0,%1}, [%2];"
        : "=r"(r[0]), "=r"(r[1]) : "r"(addr));
}
__device__ __forceinline__ void mma16816(float* d, const uint32_t* a, const uint32_t* b) {
    asm volatile("mma.sync.aligned.m16n8k16.row.col.f32.bf16.bf16.f32 "
        "{%0,%1,%2,%3}, {%4,%5,%6,%7}, {%8,%9}, {%0,%1,%2,%3};"
        : "+f"(d[0]), "+f"(d[1]), "+f"(d[2]), "+f"(d[3])
        : "r"(a[0]), "r"(a[1]), "r"(a[2]), "r"(a[3]), "r"(b[0]), "r"(b[1]));
}

// ---------------- conversions ----------------
__global__ __launch_bounds__(256) void aconv_kernel(const float* __restrict__ a,
    __nv_bfloat16* __restrict__ hi, __nv_bfloat16* __restrict__ lo)
{
    size_t i = ((size_t)blockIdx.x * 256 + threadIdx.x) * 4;
    float4 v = *(const float4*)&a[i];
    float vv[4] = {v.x, v.y, v.z, v.w};
    ushort4 h, l;
    unsigned short* hp = &h.x; unsigned short* lp = &l.x;
#pragma unroll
    for (int j = 0; j < 4; j++) {
        __nv_bfloat16 hb = __float2bfloat16(vv[j]);
        __nv_bfloat16 lb = __float2bfloat16(vv[j] - __bfloat162float(hb));
        hp[j] = __bfloat16_as_ushort(hb);
        lp[j] = __bfloat16_as_ushort(lb);
    }
    *(ushort4*)&hi[i] = h;
    *(ushort4*)&lo[i] = l;
}

// 6 weight transposes+converts in one launch: W [k][n] f32 -> hi [n][k] bf16
struct WconvP { const float* W[6]; };
__global__ __launch_bounds__(256) void wconv6_kernel(WconvP P, __nv_bfloat16* __restrict__ hi_base)
{
    __shared__ float tile[32][33];
    const float* W = P.W[blockIdx.z];
    __nv_bfloat16* hi = hi_base + (size_t)blockIdx.z * DMODEL * DMODEL;
    int bx = blockIdx.x * 32;
    int by = blockIdx.y * 32;
    int tx = threadIdx.x, ty = threadIdx.y;
#pragma unroll
    for (int i = 0; i < 32; i += 8)
        tile[ty + i][tx] = W[(size_t)(by + ty + i) * 1024 + bx + tx];
    __syncthreads();
#pragma unroll
    for (int i = 0; i < 32; i += 8) {
        int n = bx + ty + i, k = by + tx;
        hi[(size_t)n * 1024 + k] = __float2bfloat16(tile[tx][ty + i]);
    }
}

// ---------------- mma.sync 2-leg split GEMM (A hi/lo x B bf16) ----------------
#define SROW 40
#define MAT_E (128*SROW)          // elems per matrix (5120)
#define SST_B (3*MAT_E*2)         // stage bytes: Ahi, Alo, Bh = 30720
#define GEMM_SMEM (2*SST_B)       // 61440

__device__ __forceinline__ void load_chunk_mm(uint32_t sb, int t, int m0, int n0, int k0,
    const __nv_bfloat16* Ahi, const __nv_bfloat16* Alo, const __nv_bfloat16* Bh)
{
#pragma unroll
    for (int i = 0; i < 2; i++) {
        int cid = i * 256 + t;
        int row = cid >> 2, c = cid & 3;
        uint32_t off = (uint32_t)(row * (SROW*2) + c * 16);
        cp16(sb + off,             (const char*)(Ahi + (size_t)(m0 + row) * 1024 + k0) + c * 16);
        cp16(sb + MAT_E*2 + off,   (const char*)(Alo + (size_t)(m0 + row) * 1024 + k0) + c * 16);
        cp16(sb + 2*MAT_E*2 + off, (const char*)(Bh  + (size_t)(n0 + row) * 1024 + k0) + c * 16);
    }
    asm volatile("cp.async.commit_group;\n" ::: "memory");
}

__device__ __forceinline__ void gemm_body(
    uint32_t sb, int m0, int n0,
    const __nv_bfloat16* Ahi, const __nv_bfloat16* Alo, const __nv_bfloat16* Bh,
    const float* bias, const float* resid, float* out, int do_tanh)
{
    int t = threadIdx.x;
    int warp = t >> 5, lane = t & 31;
    int wm = warp & 1, wn = warp >> 1;

    float acc[4][4][4];
#pragma unroll
    for (int a = 0; a < 4; a++)
#pragma unroll
        for (int b = 0; b < 4; b++)
#pragma unroll
            for (int c = 0; c < 4; c++) acc[a][b][c] = 0.f;

    int aq = lane >> 3;
    int arow = (aq & 1) * 8 + (lane & 7);
    int akoff = (aq >> 1) * 8;
    int brow = lane & 7;
    int bkoff = ((lane >> 3) & 1) * 8;

    load_chunk_mm(sb, t, m0, n0, 0, Ahi, Alo, Bh);

#pragma unroll 1
    for (int c = 0; c < 32; c++) {
        if (c < 31)
            load_chunk_mm(sb + ((c + 1) & 1) * SST_B, t, m0, n0, (c + 1) * 32, Ahi, Alo, Bh);
        if (c < 31) asm volatile("cp.async.wait_group 1;\n" ::: "memory");
        else        asm volatile("cp.async.wait_group 0;\n" ::: "memory");
        __syncthreads();

        uint32_t st = sb + (c & 1) * SST_B;
#pragma unroll
        for (int k16 = 0; k16 < 2; k16++) {
            int kb = k16 * 16;
            uint32_t ah[4][4], al[4][4];
#pragma unroll
            for (int mt = 0; mt < 4; mt++) {
                uint32_t aaddr = st + (uint32_t)(((wm*64 + mt*16 + arow) * SROW + kb + akoff) * 2);
                ldsm4(ah[mt], aaddr);
                ldsm4(al[mt], aaddr + MAT_E*2);
            }
#pragma unroll
            for (int nt = 0; nt < 4; nt++) {
                uint32_t baddr = st + 2*MAT_E*2 +
                    (uint32_t)(((wn*32 + nt*8 + brow) * SROW + kb + bkoff) * 2);
                uint32_t bh2[2];
                ldsm2(bh2, baddr);
#pragma unroll
                for (int mt = 0; mt < 4; mt++) {
                    mma16816(acc[mt][nt], ah[mt], bh2);
                    mma16816(acc[mt][nt], al[mt], bh2);
                }
            }
        }
        __syncthreads();
    }

    int rin = lane >> 2, cin = (lane & 3) * 2;
#pragma unroll
    for (int mt = 0; mt < 4; mt++) {
#pragma unroll
        for (int nt = 0; nt < 4; nt++) {
            int n = n0 + wn*32 + nt*8 + cin;
            float b0 = bias[n], b1 = bias[n + 1];
#pragma unroll
            for (int half = 0; half < 2; half++) {
                int m = m0 + wm*64 + mt*16 + rin + half*8;
                float v0 = acc[mt][nt][half*2 + 0] + b0;
                float v1 = acc[mt][nt][half*2 + 1] + b1;
                if (resid) {
                    const float* rr = resid + (size_t)m * 1024 + n;
                    v0 += rr[0]; v1 += rr[1];
                }
                if (do_tanh) { v0 = tanhf(v0); v1 = tanhf(v1); }
                *(float2*)&out[(size_t)m * 1024 + n] = make_float2(v0, v1);
            }
        }
    }
}

struct GemmP5 {
    const __nv_bfloat16* Bh[5];
    const float* bias[5];
    float* out[5];
    int tanh_f[5];
};

__global__ __launch_bounds__(256) void mma_gemm5_kernel(
    const __nv_bfloat16* __restrict__ Ah, const __nv_bfloat16* __restrict__ Al, GemmP5 P)
{
    extern __shared__ char smem[];
    uint32_t sb = smem_u32(smem);
    int z = blockIdx.z;
    gemm_body(sb, blockIdx.x * 128, blockIdx.y * 128,
              Ah, Al, P.Bh[z], P.bias[z], nullptr, P.out[z], P.tanh_f[z]);
}

__global__ __launch_bounds__(256) void mma_gemm_kernel(
    const __nv_bfloat16* __restrict__ Ahi, const __nv_bfloat16* __restrict__ Alo,
    const __nv_bfloat16* __restrict__ Bh,
    const float* __restrict__ bias, const float* __restrict__ resid,
    float* __restrict__ out, int do_tanh)
{
    extern __shared__ char smem[];
    uint32_t sb = smem_u32(smem);
    gemm_body(sb, blockIdx.x * 128, blockIdx.y * 128,
              Ahi, Alo, Bh, bias, resid, out, do_tanh);
}

// ---------------- prep: M = qw @ em ----------------
__global__ void prep_m_kernel(const float* __restrict__ qqr, const float* __restrict__ qqi,
                              const float* __restrict__ qkr, const float* __restrict__ qki,
                              const float* __restrict__ qqem, const float* __restrict__ qkem)
{
    int t = threadIdx.x;
    int u = t >> 4, v = t & 15;
    float a = 0.f, b = 0.f, c = 0.f, d = 0.f;
#pragma unroll
    for (int w = 0; w < 16; w++) {
        float e1 = qqem[w*16+v], e2 = qkem[w*16+v];
        a += qqr[u*16+w]*e1;
        b += qqi[u*16+w]*e1;
        c += qkr[u*16+w]*e2;
        d += qki[u*16+w]*e2;
    }
    g_M[t] = a; g_M[256+t] = b; g_M[512+t] = c; g_M[768+t] = d;
}

// ---------------- quantum small path ----------------
__global__ __launch_bounds__(128) void quantum_kernel(
    const float* __restrict__ x, const float* __restrict__ sgq, const float* __restrict__ sgk)
{
    __shared__ float xs[1024];
    __shared__ float part[8][16];
    __shared__ float qss[16];
    __shared__ float prob_s[16];
    int i = blockIdx.x;
    int t = threadIdx.x;
#pragma unroll
    for (int c = 0; c < 2; c++)
        *(float4*)&xs[(t + c*128)*4] = *(const float4*)&x[(size_t)i*1024 + (t + c*128)*4];
    __syncthreads();
    int tt = t & 15, pp = t >> 4;
#pragma unroll 1
    for (int side = 0; side < 2; side++) {
        const float* sg = side ? sgk : sgq;
        float acc = 0.f;
        int base = pp * 128;
        for (int d = 0; d < 128; d++)
            acc += xs[base + d] * sg[(base + d)*16 + tt];
        part[pp][tt] = acc;
        __syncthreads();
        if (t < 16) {
            float q = 0.f;
#pragma unroll
            for (int p = 0; p < 8; p++) q += part[p][t];
            qss[t] = q;
        }
        __syncthreads();
        if (t < 16) {
            const float* Mr = g_M + side*512;
            const float* Mi = Mr + 256;
            float er = 0.f, ei = 0.f;
#pragma unroll
            for (int u = 0; u < 16; u++) {
                er += qss[u]*Mr[u*16+t];
                ei += qss[u]*Mi[u*16+t];
            }
            float pr = er*er + ei*ei;
            prob_s[t] = pr;
            (side ? g_probs_k : g_probs_q)[i*16 + t] = pr;
        }
        __syncthreads();
        if (t == 0) {
            float ms = 0.f;
#pragma unroll
            for (int u = 0; u < 16; u++) ms += prob_s[u];
            ms *= (1.f/16.f);
            (side ? g_fw_k : g_fw_q)[i] = 1.f/(1.f + __expf(-ms));
        }
        __syncthreads();
    }
}

// ---------------- combine ----------------
__global__ __launch_bounds__(256) void combine_kernel(
    const float* __restrict__ qq_mb, const float* __restrict__ qk_mb)
{
    int i = blockIdx.x;
    int b = i >> 11, s = i & 2047;
    int t = threadIdx.x;
    __shared__ float pqs[16], pks[16];
    if (t < 16) pqs[t] = g_probs_q[i*16 + t];
    else if (t < 32) pks[t-16] = g_probs_k[i*16 + (t-16)];
    __syncthreads();
    float fq = g_fw_q[i], fk = g_fw_k[i];
    int d0 = t * 4;
    float4 qv = *(const float4*)&g_Q [(size_t)i*1024 + d0];
    float4 kv = *(const float4*)&g_K [(size_t)i*1024 + d0];
    float4 vv = *(const float4*)&g_V [(size_t)i*1024 + d0];
    float4 cq = *(const float4*)&g_Cq[(size_t)i*1024 + d0];
    float4 ck = *(const float4*)&g_Ck[(size_t)i*1024 + d0];
    const float* qvp = (const float*)&qv;
    const float* kvp = (const float*)&kv;
    const float* cqp = (const float*)&cq;
    const float* ckp = (const float*)&ck;
    ushort4 qh4, ql4, kh4;
    unsigned short* qhp = &qh4.x; unsigned short* qlp = &ql4.x;
    unsigned short* khp = &kh4.x;
#pragma unroll
    for (int j = 0; j < 4; j++) {
        int d = d0 + j;
        float qmb = 0.f, kmb = 0.f;
#pragma unroll
        for (int u = 0; u < 16; u++) {
            qmb += pqs[u] * qq_mb[u*1024 + d];
            kmb += pks[u] * qk_mb[u*1024 + d];
        }
        float qq = fq*qmb + (1.f - fq)*cqp[j];
        float kq = fk*kmb + (1.f - fk)*ckp[j];
        float oq = (0.7f*qvp[j] + 0.3f*qq) * 0.125f;
        float ok =  0.7f*kvp[j] + 0.3f*kq;
        __nv_bfloat16 hb = __float2bfloat16(oq);
        qhp[j] = __bfloat16_as_ushort(hb);
        qlp[j] = __bfloat16_as_ushort(__float2bfloat16(oq - __bfloat162float(hb)));
        khp[j] = __bfloat16_as_ushort(__float2bfloat16(ok));
    }
    int h = d0 >> 6, dh = d0 & 63;
    int bh = b*16 + h;
    size_t qb = ((size_t)bh*SEQ + s)*AD + dh;
    *(ushort4*)&g_Qah[qb] = qh4;
    *(ushort4*)&g_Qal[qb] = ql4;
    *(ushort4*)&g_Kah[qb] = kh4;
    *(float4*)&g_Va[((size_t)bh*SEQ + s)*HD + dh] = vv;
    int h2 = t >> 4, u = t & 15;
    int bh2 = b*16 + h2;
    size_t tb = ((size_t)bh2*SEQ + s)*AD + 64 + u;
    float tv = 0.1f * pqs[u];
    __nv_bfloat16 th = __float2bfloat16(tv);
    g_Qah[tb] = th;
    g_Qal[tb] = __float2bfloat16(tv - __bfloat162float(th));
    g_Kah[tb] = __float2bfloat16(pks[u]);
}

// ---------------- V transpose: Va [bh][s][64] f32 -> Vth [bh][d][s] bf16 ----------------
__global__ __launch_bounds__(256) void vtrans_kernel()
{
    __shared__ float tile[64][65];
    int s0 = blockIdx.x * 64, bh = blockIdx.y;
    int t = threadIdx.x;
    int r = t >> 2, c4 = (t & 3) * 16;
    const float* src = g_Va + ((size_t)bh*SEQ + s0 + r)*HD + c4;
#pragma unroll
    for (int j = 0; j < 16; j += 4) {
        float4 v = *(const float4*)&src[j];
        tile[r][c4 + j + 0] = v.x;
        tile[r][c4 + j + 1] = v.y;
        tile[r][c4 + j + 2] = v.z;
        tile[r][c4 + j + 3] = v.w;
    }
    __syncthreads();
    int d = t >> 2, sc = (t & 3) * 16;
    ushort4 ho[4];
#pragma unroll
    for (int j = 0; j < 16; j++) {
        float v = tile[sc + j][d];
        (&ho[j >> 2].x)[j & 3] = __bfloat16_as_ushort(__float2bfloat16(v));
    }
    size_t base = ((size_t)bh*HD + d)*SEQ + s0 + sc;
#pragma unroll
    for (int j = 0; j < 4; j++)
        *(ushort4*)&g_Vth[base + j*4] = ho[j];
}

// ---------------- flash attention with mma.sync ----------------
// smem layout (bytes):
//  Qhi 0..11264, Qlo 11264..22528
//  stage s at ST0B + s*STAGEB: K(22528) V(+22528, 17408); STAGEB=39936
//  P tile aliases the current stage's K region (safe: K reads all complete
//  before the redm __syncthreads; P written after it; stage reloaded only
//  after PV MMAs + the post-PV __syncthreads).
//  reductions at REDB(1024)
#define QLOB 11264
#define ST0B 22528
#define VOFF 22528
#define STAGEB 39936
#define REDB 102400
#define FLASH2_SMEM 103424

__device__ __forceinline__ void load_q_f(uint32_t sb, int t, int bh, int qt)
{
    const char* qh = (const char*)(g_Qah + ((size_t)bh*SEQ + qt*64)*AD);
    const char* ql = (const char*)(g_Qal + ((size_t)bh*SEQ + qt*64)*AD);
#pragma unroll 1
    for (int i = t; i < 640; i += 256) {
        int row = i / 10, c = i % 10;
        uint32_t off = (uint32_t)(row*176 + c*16);
        cp16(sb + off, qh + (size_t)row*160 + c*16);
        cp16(sb + QLOB + off, ql + (size_t)row*160 + c*16);
    }
}

__device__ __forceinline__ void load_kv_f(uint32_t stb, int t, int bh, int k0)
{
    const char* kh = (const char*)(g_Kah + ((size_t)bh*SEQ + k0)*AD);
#pragma unroll 1
    for (int i = t; i < 1280; i += 256) {
        int row = i / 10, c = i % 10;
        cp16(stb + (uint32_t)(row*176 + c*16), kh + (size_t)row*160 + c*16);
    }
    const __nv_bfloat16* vh = g_Vth + (size_t)bh*HD*SEQ + k0;
#pragma unroll 1
    for (int i = t; i < 1024; i += 256) {
        int d = i >> 4, c = i & 15;
        cp16(stb + VOFF + (uint32_t)(d*272 + c*16), (const char*)(vh + (size_t)d*SEQ) + c*16);
    }
    asm volatile("cp.async.commit_group;\n" ::: "memory");
}

__global__ __launch_bounds__(256, 2) void flash_mma_kernel(float* __restrict__ w_out)
{
    extern __shared__ char smem[];
    uint32_t sb = smem_u32(smem);
    float* redm = (float*)(smem + REDB);      // [2][64]
    float* reds = redm + 128;                 // [2][64]

    int qt = blockIdx.x, bh = blockIdx.y;
    int t = threadIdx.x;
    int warp = t >> 5, lane = t & 31;
    int wm = warp & 3, wn = warp >> 2;       // 4 m-strips x 2 n-halves

    int aq = lane >> 3;
    int arow = (aq & 1) * 8 + (lane & 7);
    int akoff = (aq >> 1) * 8;
    int b4n = (lane >> 4) * 8 + (lane & 7);
    int b4k = ((lane >> 3) & 1) * 8;
    int rin = lane >> 2, cin = (lane & 3) * 2;

    load_q_f(sb, t, bh, qt);
    load_kv_f(sb + ST0B, t, bh, 0);
    load_kv_f(sb + ST0B + STAGEB, t, bh, 128);

    float m_run0 = -1e30f, m_run1 = -1e30f;
    float l_run0 = 0.f, l_run1 = 0.f;
    float O[4][4];
#pragma unroll
    for (int a = 0; a < 4; a++)
#pragma unroll
        for (int b = 0; b < 4; b++) O[a][b] = 0.f;

    int r0 = wm*16 + rin, r1 = r0 + 8;

#pragma unroll 1
    for (int kt = 0; kt < 16; kt++) {
        if (kt < 15) asm volatile("cp.async.wait_group 1;\n" ::: "memory");
        else         asm volatile("cp.async.wait_group 0;\n" ::: "memory");
        __syncthreads();
        uint32_t stoff = (uint32_t)(ST0B + (kt & 1) * STAGEB);
        uint32_t st = sb + stoff;
        __nv_bfloat162* Pph = (__nv_bfloat162*)(smem + stoff);   // aliases K region

        // ---- S = Q @ K^T (2-leg: Qhi*K + Qlo*K) ----
        float sacc[8][4];
#pragma unroll
        for (int a = 0; a < 8; a++)
#pragma unroll
            for (int b = 0; b < 4; b++) sacc[a][b] = 0.f;
#pragma unroll
        for (int ks = 0; ks < 5; ks++) {
            int kb = ks * 16;
            uint32_t qaddr = sb + (uint32_t)(((wm*16 + arow)*88 + kb + akoff) * 2);
            uint32_t qfh[4], qfl[4];
            ldsm4(qfh, qaddr);
            ldsm4(qfl, qaddr + QLOB);
#pragma unroll
            for (int p = 0; p < 4; p++) {
                uint32_t kaddr = st + (uint32_t)(((wn*64 + p*16 + b4n)*88 + kb + b4k) * 2);
                uint32_t kh4[4];
                ldsm4(kh4, kaddr);
                mma16816(sacc[2*p],   qfh, kh4);
                mma16816(sacc[2*p+1], qfh, kh4+2);
                mma16816(sacc[2*p],   qfl, kh4);
                mma16816(sacc[2*p+1], qfl, kh4+2);
            }
        }

        // ---- online softmax ----
        float lm0 = -1e30f, lm1 = -1e30f;
#pragma unroll
        for (int nt = 0; nt < 8; nt++) {
            lm0 = fmaxf(lm0, fmaxf(sacc[nt][0], sacc[nt][1]));
            lm1 = fmaxf(lm1, fmaxf(sacc[nt][2], sacc[nt][3]));
        }
        lm0 = fmaxf(lm0, __shfl_xor_sync(0xffffffffu, lm0, 1));
        lm0 = fmaxf(lm0, __shfl_xor_sync(0xffffffffu, lm0, 2));
        lm1 = fmaxf(lm1, __shfl_xor_sync(0xffffffffu, lm1, 1));
        lm1 = fmaxf(lm1, __shfl_xor_sync(0xffffffffu, lm1, 2));
        if ((lane & 3) == 0) {
            redm[wn*64 + r0] = lm0;
            redm[wn*64 + r1] = lm1;
        }
        __syncthreads();   // also: all warps done reading K -> P may alias it
        float mn0 = fmaxf(m_run0, fmaxf(redm[r0], redm[64 + r0]));
        float mn1 = fmaxf(m_run1, fmaxf(redm[r1], redm[64 + r1]));
        float al0 = __expf(m_run0 - mn0);
        float al1 = __expf(m_run1 - mn1);
        m_run0 = mn0; m_run1 = mn1;

        float ls0 = 0.f, ls1 = 0.f;
        size_t wrow0 = ((size_t)bh*SEQ + qt*64 + r0) * SEQ + (size_t)kt*128 + wn*64 + cin;
        size_t wrow1 = wrow0 + (size_t)8 * SEQ;
        int pc = wn*32 + (cin >> 1);
#pragma unroll
        for (int nt = 0; nt < 8; nt++) {
            float p0 = __expf(sacc[nt][0] - mn0);
            float p1 = __expf(sacc[nt][1] - mn0);
            float p2 = __expf(sacc[nt][2] - mn1);
            float p3 = __expf(sacc[nt][3] - mn1);
            ls0 += p0 + p1; ls1 += p2 + p3;
            *(float2*)&w_out[wrow0 + nt*8] = make_float2(p0, p1);
            *(float2*)&w_out[wrow1 + nt*8] = make_float2(p2, p3);
            __nv_bfloat162 hv0; hv0.x = __float2bfloat16(p0); hv0.y = __float2bfloat16(p1);
            __nv_bfloat162 hv1; hv1.x = __float2bfloat16(p2); hv1.y = __float2bfloat16(p3);
            Pph[r0*68 + pc + nt*4] = hv0;
            Pph[r1*68 + pc + nt*4] = hv1;
        }
        ls0 += __shfl_xor_sync(0xffffffffu, ls0, 1);
        ls0 += __shfl_xor_sync(0xffffffffu, ls0, 2);
        ls1 += __shfl_xor_sync(0xffffffffu, ls1, 1);
        ls1 += __shfl_xor_sync(0xffffffffu, ls1, 2);
        if ((lane & 3) == 0) {
            reds[wn*64 + r0] = ls0;
            reds[wn*64 + r1] = ls1;
        }
        if (wn == 0 && (lane & 3) == 0) {
            g_mt[((size_t)bh*SEQ + qt*64 + r0)*16 + kt] = mn0;
            g_mt[((size_t)bh*SEQ + qt*64 + r1)*16 + kt] = mn1;
        }
#pragma unroll
        for (int nt = 0; nt < 4; nt++) {
            O[nt][0] *= al0; O[nt][1] *= al0;
            O[nt][2] *= al1; O[nt][3] *= al1;
        }
        __syncthreads();   // P fully written before PV reads
        l_run0 = l_run0*al0 + reds[r0] + reds[64 + r0];
        l_run1 = l_run1*al1 + reds[r1] + reds[64 + r1];

        // ---- O += P @ V (bf16) ----
#pragma unroll
        for (int ks = 0; ks < 8; ks++) {
            int kb = ks * 16;
            uint32_t paddr = st + (uint32_t)(((wm*16 + arow)*136 + kb + akoff) * 2);
            uint32_t pf[4];
            ldsm4(pf, paddr);
#pragma unroll
            for (int p = 0; p < 2; p++) {
                uint32_t vaddr = st + VOFF + (uint32_t)(((wn*32 + p*16 + b4n)*136 + kb + b4k) * 2);
                uint32_t vh4[4];
                ldsm4(vh4, vaddr);
                mma16816(O[2*p],   pf, vh4);
                mma16816(O[2*p+1], pf, vh4+2);
            }
        }
        __syncthreads();
        if (kt + 2 < 16) load_kv_f(st, t, bh, (kt + 2) * 128);
    }

    // ---- epilogue: write att as bf16 hi/lo directly ----
    float inv0 = 1.f / l_run0, inv1 = 1.f / l_run1;
    int b = bh >> 4, h = bh & 15;
    int rg0 = qt*64 + r0;
#pragma unroll
    for (int nt = 0; nt < 4; nt++) {
        int d = h*64 + wn*32 + nt*8 + cin;
        float o0 = O[nt][0]*inv0, o1 = O[nt][1]*inv0;
        float o2 = O[nt][2]*inv1, o3 = O[nt][3]*inv1;
        size_t i0 = ((size_t)b*SEQ + rg0)*1024 + d;
        size_t i1 = ((size_t)b*SEQ + rg0 + 8)*1024 + d;
        __nv_bfloat162 h0; h0.x = __float2bfloat16(o0); h0.y = __float2bfloat16(o1);
        __nv_bfloat162 h1; h1.x = __float2bfloat16(o2); h1.y = __float2bfloat16(o3);
        __nv_bfloat162 l0;
        l0.x = __float2bfloat16(o0 - __bfloat162float(h0.x));
        l0.y = __float2bfloat16(o1 - __bfloat162float(h0.y));
        __nv_bfloat162 l1;
        l1.x = __float2bfloat16(o2 - __bfloat162float(h1.x));
        l1.y = __float2bfloat16(o3 - __bfloat162float(h1.y));
        *(__nv_bfloat162*)&g_ahi[i0] = h0;
        *(__nv_bfloat162*)&g_ahi[i1] = h1;
        *(__nv_bfloat162*)&g_alo[i0] = l0;
        *(__nv_bfloat162*)&g_alo[i1] = l1;
    }
    if (wn == 0 && (lane & 3) == 0) {
        g_m[(size_t)bh*SEQ + rg0] = m_run0;
        g_l[(size_t)bh*SEQ + rg0] = l_run0;
        g_m[(size_t)bh*SEQ + rg0 + 8] = m_run1;
        g_l[(size_t)bh*SEQ + rg0 + 8] = l_run1;
    }
}

// ---------------- normalize w ----------------
__global__ __launch_bounds__(256) void norm_w_kernel(float* __restrict__ w)
{
    size_t idx = (size_t)blockIdx.x * 256 + threadIdx.x;
    size_t e0 = idx * 4;
    size_t row = e0 >> 11;
    int kt = (int)((e0 & 2047) >> 7);
    float f = __expf(g_mt[row*16 + kt] - g_m[row]) / g_l[row];
    float4 v = *(float4*)&w[e0];
    v.x *= f; v.y *= f; v.z *= f; v.w *= f;
    *(float4*)&w[e0] = v;
}

// ---------------- layernorm ----------------
__global__ __launch_bounds__(256) void ln_kernel(const float* __restrict__ gam,
    const float* __restrict__ bet, float* __restrict__ y)
{
    int i = blockIdx.x, t = threadIdx.x;
    float4 v = *(const float4*)&g_res[(size_t)i*1024 + t*4];
    float s  = v.x + v.y + v.z + v.w;
    float ss = v.x*v.x + v.y*v.y + v.z*v.z + v.w*v.w;
#pragma unroll
    for (int off = 16; off; off >>= 1) {
        s  += __shfl_xor_sync(0xffffffffu, s,  off);
        ss += __shfl_xor_sync(0xffffffffu, ss, off);
    }
    __shared__ float as[8], ass[8];
    if ((t & 31) == 0) { as[t >> 5] = s; ass[t >> 5] = ss; }
    __syncthreads();
    float S = 0.f, SS = 0.f;
#pragma unroll
    for (int u = 0; u < 8; u++) { S += as[u]; SS += ass[u]; }
    float mu  = S * (1.f/1024.f);
    float var = SS * (1.f/1024.f) - mu*mu;
    float inv = rsqrtf(var + 1e-5f);
    float4 gg = *(const float4*)&gam[t*4];
    float4 bb = *(const float4*)&bet[t*4];
    float4 o;
    o.x = (v.x - mu)*inv*gg.x + bb.x;
    o.y = (v.y - mu)*inv*gg.y + bb.y;
    o.z = (v.z - mu)*inv*gg.z + bb.z;
    o.w = (v.w - mu)*inv*gg.w + bb.w;
    *(float4*)&y[(size_t)i*1024 + t*4] = o;
}

// ---------------- launch ----------------
extern "C" void kernel_launch(void* const* d_in, const int* in_sizes, int n_in,
                              void* d_out, int out_size)
{
    const float* x       = (const float*)d_in[0];
    const float* Wq      = (const float*)d_in[1];
    const float* bq      = (const float*)d_in[2];
    const float* Wk      = (const float*)d_in[3];
    const float* bk      = (const float*)d_in[4];
    const float* Wv      = (const float*)d_in[5];
    const float* bv      = (const float*)d_in[6];
    const float* Wo      = (const float*)d_in[7];
    const float* bo      = (const float*)d_in[8];
    const float* ln_g    = (const float*)d_in[9];
    const float* ln_b    = (const float*)d_in[10];
    const float* qq_W    = (const float*)d_in[11];
    const float* qq_b    = (const float*)d_in[12];
    const float* qq_qw_r = (const float*)d_in[13];
    const float* qq_qw_i = (const float*)d_in[14];
    const float* qq_sg   = (const float*)d_in[15];
    const float* qq_em   = (const float*)d_in[16];
    const float* qq_mb   = (const float*)d_in[17];
    const float* qk_W    = (const float*)d_in[18];
    const float* qk_b    = (const float*)d_in[19];
    const float* qk_qw_r = (const float*)d_in[20];
    const float* qk_qw_i = (const float*)d_in[21];
    const float* qk_sg   = (const float*)d_in[22];
    const float* qk_em   = (const float*)d_in[23];
    const float* qk_mb   = (const float*)d_in[24];

    float* y = (float*)d_out;
    float* w = y + (size_t)MROWS*DMODEL;

    float *pQ, *pK, *pV, *pCq, *pCk, *pRes;
    cudaGetSymbolAddress((void**)&pQ,   g_Q);
    cudaGetSymbolAddress((void**)&pK,   g_K);
    cudaGetSymbolAddress((void**)&pV,   g_V);
    cudaGetSymbolAddress((void**)&pCq,  g_Cq);
    cudaGetSymbolAddress((void**)&pCk,  g_Ck);
    cudaGetSymbolAddress((void**)&pRes, g_res);
    __nv_bfloat16 *pXh, *pXl, *pAh, *pAl, *pWh;
    cudaGetSymbolAddress((void**)&pXh, g_xhi);
    cudaGetSymbolAddress((void**)&pXl, g_xlo);
    cudaGetSymbolAddress((void**)&pAh, g_ahi);
    cudaGetSymbolAddress((void**)&pAl, g_alo);
    cudaGetSymbolAddress((void**)&pWh, g_Whi);

    cudaFuncSetAttribute(mma_gemm_kernel,
        cudaFuncAttributeMaxDynamicSharedMemorySize, GEMM_SMEM);
    cudaFuncSetAttribute(mma_gemm5_kernel,
        cudaFuncAttributeMaxDynamicSharedMemorySize, GEMM_SMEM);
    cudaFuncSetAttribute(flash_mma_kernel,
        cudaFuncAttributeMaxDynamicSharedMemorySize, FLASH2_SMEM);

    prep_m_kernel<<<1, 256>>>(qq_qw_r, qq_qw_i, qk_qw_r, qk_qw_i, qq_em, qk_em);
    quantum_kernel<<<MROWS, 128>>>(x, qq_sg, qk_sg);

    aconv_kernel<<<MROWS*DMODEL/(256*4), 256>>>(x, pXh, pXl);
    WconvP WP;
    WP.W[0] = Wq; WP.W[1] = Wk; WP.W[2] = Wv;
    WP.W[3] = qq_W; WP.W[4] = qk_W; WP.W[5] = Wo;
    wconv6_kernel<<<dim3(32, 32, 6), dim3(32, 8)>>>(WP, pWh);

    // 5 forward GEMMs in one launch
    const size_t WSZ = (size_t)DMODEL*DMODEL;
    GemmP5 P;
    P.Bh[0] = pWh + 0*WSZ; P.bias[0] = bq;   P.out[0] = pQ;  P.tanh_f[0] = 0;
    P.Bh[1] = pWh + 1*WSZ; P.bias[1] = bk;   P.out[1] = pK;  P.tanh_f[1] = 0;
    P.Bh[2] = pWh + 2*WSZ; P.bias[2] = bv;   P.out[2] = pV;  P.tanh_f[2] = 0;
    P.Bh[3] = pWh + 3*WSZ; P.bias[3] = qq_b; P.out[3] = pCq; P.tanh_f[3] = 1;
    P.Bh[4] = pWh + 4*WSZ; P.bias[4] = qk_b; P.out[4] = pCk; P.tanh_f[4] = 1;
    dim3 g5(32, 8, 5);
    mma_gemm5_kernel<<<g5, 256, GEMM_SMEM>>>(pXh, pXl, P);

    combine_kernel<<<MROWS, 256>>>(qq_mb, qk_mb);
    vtrans_kernel<<<dim3(32, 32), 256>>>();

    flash_mma_kernel<<<dim3(32, 32), 256, FLASH2_SMEM>>>(w);

    norm_w_kernel<<<(NBH*(size_t)SEQ*SEQ)/(4*256), 256>>>(w);

    // output projection: att @ Wo + bo + x  (att hi/lo came straight from flash)
    dim3 gg(32, 8);
    mma_gemm_kernel<<<gg, 256, GEMM_SMEM>>>(pAh, pAl, pWh + 5*WSZ, bo, x, pRes, 0);

    ln_kernel<<<MROWS, 256>>>(ln_g, ln_b, y);
}

// round 11
// speedup vs baseline: 3.6816x; 1.1903x over previous
#include <cuda_runtime.h>
#include <cuda_fp16.h>
#include <cstdint>
#include <math.h>

#define MROWS 4096
#define DMODEL 1024
#define NH 16
#define HD 64
#define QD 16
#define SEQ 2048
#define NBH 32
#define AD 80

// ---------------- scratch ----------------
__device__ __align__(16) float g_Q[MROWS*DMODEL];
__device__ __align__(16) float g_K[MROWS*DMODEL];
__device__ __align__(16) float g_V[MROWS*DMODEL];
__device__ __align__(16) float g_Cq[MROWS*DMODEL];
__device__ __align__(16) float g_Ck[MROWS*DMODEL];
__device__ __align__(16) float g_res[MROWS*DMODEL];
__device__ __align__(16) float g_Va[NBH*SEQ*HD];
__device__ __align__(16) float g_probs_q[MROWS*QD];
__device__ __align__(16) float g_probs_k[MROWS*QD];
__device__ float g_fw_q[MROWS];
__device__ float g_fw_k[MROWS];
__device__ float g_m[NBH*SEQ];
__device__ float g_l[NBH*SEQ];
__device__ float g_mt[NBH*SEQ*16];    // running max snapshot per 128-key tile
__device__ float g_M[4*256];

// fp16 buffers (16B-aligned: used with uint4 stores / cp.async 16B)
__device__ __align__(16) __half g_xh[MROWS*DMODEL];        // x fp16
__device__ __align__(16) __half g_ah[MROWS*DMODEL];        // att fp16 (written by flash)
__device__ __align__(16) __half g_Wh[6*DMODEL*DMODEL];     // [widx][n][k] fp16
// flash operands
__device__ __align__(16) __half g_Qah[NBH*SEQ*AD];   // [bh][s][80] = [0.125*Qf, 0.1*qp]
__device__ __align__(16) __half g_Kah[NBH*SEQ*AD];   // [bh][s][80] = [Kf, kp]
__device__ __align__(16) __half g_Vth[NBH*HD*SEQ];   // [bh][d][s]

// ---------------- helpers ----------------
__device__ __forceinline__ uint32_t smem_u32(const void* p) {
    uint32_t a;
    asm("{ .reg .u64 t; cvta.to.shared.u64 t, %1; cvt.u32.u64 %0, t; }" : "=r"(a) : "l"(p));
    return a;
}
__device__ __forceinline__ void cp16(uint32_t dst, const void* src) {
    asm volatile("cp.async.cg.shared.global [%0], [%1], 16;\n" :: "r"(dst), "l"(src));
}
__device__ __forceinline__ void ldsm4(uint32_t* r, uint32_t addr) {
    asm volatile("ldmatrix.sync.aligned.m8n8.x4.shared.b16 {%0,%1,%2,%3}, [%4];"
        : "=r"(r[0]), "=r"(r[1]), "=r"(r[2]), "=r"(r[3]) : "r"(addr));
}
__device__ __forceinline__ void ldsm2(uint32_t* r, uint32_t addr) {
    asm volatile("ldmatrix.sync.aligned.m8n8.x2.shared.b16 {%0,%1}, [%2];"
        : "=r"(r[0]), "=r"(r[1]) : "r"(addr));
}
__device__ __forceinline__ void mma16816h(float* d, const uint32_t* a, const uint32_t* b) {
    asm volatile("mma.sync.aligned.m16n8k16.row.col.f32.f16.f16.f32 "
        "{%0,%1,%2,%3}, {%4,%5,%6,%7}, {%8,%9}, {%0,%1,%2,%3};"
        : "+f"(d[0]), "+f"(d[1]), "+f"(d[2]), "+f"(d[3])
        : "r"(a[0]), "r"(a[1]), "r"(a[2]), "r"(a[3]), "r"(b[0]), "r"(b[1]));
}

// ---------------- conversions ----------------
__global__ __launch_bounds__(256) void aconv_kernel(const float* __restrict__ a,
    __half* __restrict__ h)
{
    size_t i = ((size_t)blockIdx.x * 256 + threadIdx.x) * 8;
    float4 v0 = *(const float4*)&a[i];
    float4 v1 = *(const float4*)&a[i + 4];
    __half2 o[4];
    o[0] = __floats2half2_rn(v0.x, v0.y);
    o[1] = __floats2half2_rn(v0.z, v0.w);
    o[2] = __floats2half2_rn(v1.x, v1.y);
    o[3] = __floats2half2_rn(v1.z, v1.w);
    *(uint4*)&h[i] = *(uint4*)o;
}

// 6 weight transposes+converts in one launch: W [k][n] f32 -> [n][k] fp16
struct WconvP { const float* W[6]; };
__global__ __launch_bounds__(256) void wconv6_kernel(WconvP P, __half* __restrict__ h_base)
{
    __shared__ float tile[32][33];
    const float* W = P.W[blockIdx.z];
    __half* hh = h_base + (size_t)blockIdx.z * DMODEL * DMODEL;
    int bx = blockIdx.x * 32;
    int by = blockIdx.y * 32;
    int tx = threadIdx.x, ty = threadIdx.y;
#pragma unroll
    for (int i = 0; i < 32; i += 8)
        tile[ty + i][tx] = W[(size_t)(by + ty + i) * 1024 + bx + tx];
    __syncthreads();
#pragma unroll
    for (int i = 0; i < 32; i += 8) {
        int n = bx + ty + i, k = by + tx;
        hh[(size_t)n * 1024 + k] = __float2half_rn(tile[tx][ty + i]);
    }
}

// ---------------- mma.sync fp16 GEMM (A fp16 x B fp16, f32 accum) ----------------
#define SROW 40
#define MAT_E (128*SROW)          // elems per matrix (5120)
#define SST_B (2*MAT_E*2)         // stage bytes: A, B = 20480
#define GEMM_SMEM (2*SST_B)       // 40960

__device__ __forceinline__ void load_chunk_mm(uint32_t sb, int t, int m0, int n0, int k0,
    const __half* Ah, const __half* Bh)
{
#pragma unroll
    for (int i = 0; i < 2; i++) {
        int cid = i * 256 + t;
        int row = cid >> 2, c = cid & 3;
        uint32_t off = (uint32_t)(row * (SROW*2) + c * 16);
        cp16(sb + off,           (const char*)(Ah + (size_t)(m0 + row) * 1024 + k0) + c * 16);
        cp16(sb + MAT_E*2 + off, (const char*)(Bh + (size_t)(n0 + row) * 1024 + k0) + c * 16);
    }
    asm volatile("cp.async.commit_group;\n" ::: "memory");
}

__device__ __forceinline__ void gemm_body(
    uint32_t sb, int m0, int n0,
    const __half* Ah, const __half* Bh,
    const float* bias, const float* resid, float* out, int do_tanh)
{
    int t = threadIdx.x;
    int warp = t >> 5, lane = t & 31;
    int wm = warp & 1, wn = warp >> 1;

    float acc[4][4][4];
#pragma unroll
    for (int a = 0; a < 4; a++)
#pragma unroll
        for (int b = 0; b < 4; b++)
#pragma unroll
            for (int c = 0; c < 4; c++) acc[a][b][c] = 0.f;

    int aq = lane >> 3;
    int arow = (aq & 1) * 8 + (lane & 7);
    int akoff = (aq >> 1) * 8;
    int brow = lane & 7;
    int bkoff = ((lane >> 3) & 1) * 8;

    load_chunk_mm(sb, t, m0, n0, 0, Ah, Bh);

#pragma unroll 1
    for (int c = 0; c < 32; c++) {
        if (c < 31)
            load_chunk_mm(sb + ((c + 1) & 1) * SST_B, t, m0, n0, (c + 1) * 32, Ah, Bh);
        if (c < 31) asm volatile("cp.async.wait_group 1;\n" ::: "memory");
        else        asm volatile("cp.async.wait_group 0;\n" ::: "memory");
        __syncthreads();

        uint32_t st = sb + (c & 1) * SST_B;
#pragma unroll
        for (int k16 = 0; k16 < 2; k16++) {
            int kb = k16 * 16;
            uint32_t ah4[4][4];
#pragma unroll
            for (int mt = 0; mt < 4; mt++) {
                uint32_t aaddr = st + (uint32_t)(((wm*64 + mt*16 + arow) * SROW + kb + akoff) * 2);
                ldsm4(ah4[mt], aaddr);
            }
#pragma unroll
            for (int nt = 0; nt < 4; nt++) {
                uint32_t baddr = st + MAT_E*2 +
                    (uint32_t)(((wn*32 + nt*8 + brow) * SROW + kb + bkoff) * 2);
                uint32_t bh2[2];
                ldsm2(bh2, baddr);
#pragma unroll
                for (int mt = 0; mt < 4; mt++)
                    mma16816h(acc[mt][nt], ah4[mt], bh2);
            }
        }
        __syncthreads();
    }

    int rin = lane >> 2, cin = (lane & 3) * 2;
#pragma unroll
    for (int mt = 0; mt < 4; mt++) {
#pragma unroll
        for (int nt = 0; nt < 4; nt++) {
            int n = n0 + wn*32 + nt*8 + cin;
            float b0 = bias[n], b1 = bias[n + 1];
#pragma unroll
            for (int half_i = 0; half_i < 2; half_i++) {
                int m = m0 + wm*64 + mt*16 + rin + half_i*8;
                float v0 = acc[mt][nt][half_i*2 + 0] + b0;
                float v1 = acc[mt][nt][half_i*2 + 1] + b1;
                if (resid) {
                    const float* rr = resid + (size_t)m * 1024 + n;
                    v0 += rr[0]; v1 += rr[1];
                }
                if (do_tanh) { v0 = tanhf(v0); v1 = tanhf(v1); }
                *(float2*)&out[(size_t)m * 1024 + n] = make_float2(v0, v1);
            }
        }
    }
}

struct GemmP5 {
    const __half* Bh[5];
    const float* bias[5];
    float* out[5];
    int tanh_f[5];
};

__global__ __launch_bounds__(256) void mma_gemm5_kernel(
    const __half* __restrict__ Ah, GemmP5 P)
{
    extern __shared__ char smem[];
    uint32_t sb = smem_u32(smem);
    int z = blockIdx.z;
    gemm_body(sb, blockIdx.x * 128, blockIdx.y * 128,
              Ah, P.Bh[z], P.bias[z], nullptr, P.out[z], P.tanh_f[z]);
}

__global__ __launch_bounds__(256) void mma_gemm_kernel(
    const __half* __restrict__ Ah, const __half* __restrict__ Bh,
    const float* __restrict__ bias, const float* __restrict__ resid,
    float* __restrict__ out, int do_tanh)
{
    extern __shared__ char smem[];
    uint32_t sb = smem_u32(smem);
    gemm_body(sb, blockIdx.x * 128, blockIdx.y * 128,
              Ah, Bh, bias, resid, out, do_tanh);
}

// ---------------- prep: M = qw @ em ----------------
__global__ void prep_m_kernel(const float* __restrict__ qqr, const float* __restrict__ qqi,
                              const float* __restrict__ qkr, const float* __restrict__ qki,
                              const float* __restrict__ qqem, const float* __restrict__ qkem)
{
    int t = threadIdx.x;
    int u = t >> 4, v = t & 15;
    float a = 0.f, b = 0.f, c = 0.f, d = 0.f;
#pragma unroll
    for (int w = 0; w < 16; w++) {
        float e1 = qqem[w*16+v], e2 = qkem[w*16+v];
        a += qqr[u*16+w]*e1;
        b += qqi[u*16+w]*e1;
        c += qkr[u*16+w]*e2;
        d += qki[u*16+w]*e2;
    }
    g_M[t] = a; g_M[256+t] = b; g_M[512+t] = c; g_M[768+t] = d;
}

// ---------------- quantum small path ----------------
__global__ __launch_bounds__(128) void quantum_kernel(
    const float* __restrict__ x, const float* __restrict__ sgq, const float* __restrict__ sgk)
{
    __shared__ float xs[1024];
    __shared__ float part[8][16];
    __shared__ float qss[16];
    __shared__ float prob_s[16];
    int i = blockIdx.x;
    int t = threadIdx.x;
#pragma unroll
    for (int c = 0; c < 2; c++)
        *(float4*)&xs[(t + c*128)*4] = *(const float4*)&x[(size_t)i*1024 + (t + c*128)*4];
    __syncthreads();
    int tt = t & 15, pp = t >> 4;
#pragma unroll 1
    for (int side = 0; side < 2; side++) {
        const float* sg = side ? sgk : sgq;
        float acc = 0.f;
        int base = pp * 128;
        for (int d = 0; d < 128; d++)
            acc += xs[base + d] * sg[(base + d)*16 + tt];
        part[pp][tt] = acc;
        __syncthreads();
        if (t < 16) {
            float q = 0.f;
#pragma unroll
            for (int p = 0; p < 8; p++) q += part[p][t];
            qss[t] = q;
        }
        __syncthreads();
        if (t < 16) {
            const float* Mr = g_M + side*512;
            const float* Mi = Mr + 256;
            float er = 0.f, ei = 0.f;
#pragma unroll
            for (int u = 0; u < 16; u++) {
                er += qss[u]*Mr[u*16+t];
                ei += qss[u]*Mi[u*16+t];
            }
            float pr = er*er + ei*ei;
            prob_s[t] = pr;
            (side ? g_probs_k : g_probs_q)[i*16 + t] = pr;
        }
        __syncthreads();
        if (t == 0) {
            float ms = 0.f;
#pragma unroll
            for (int u = 0; u < 16; u++) ms += prob_s[u];
            ms *= (1.f/16.f);
            (side ? g_fw_k : g_fw_q)[i] = 1.f/(1.f + __expf(-ms));
        }
        __syncthreads();
    }
}

// ---------------- combine ----------------
__global__ __launch_bounds__(256) void combine_kernel(
    const float* __restrict__ qq_mb, const float* __restrict__ qk_mb)
{
    int i = blockIdx.x;
    int b = i >> 11, s = i & 2047;
    int t = threadIdx.x;
    __shared__ float pqs[16], pks[16];
    if (t < 16) pqs[t] = g_probs_q[i*16 + t];
    else if (t < 32) pks[t-16] = g_probs_k[i*16 + (t-16)];
    __syncthreads();
    float fq = g_fw_q[i], fk = g_fw_k[i];
    int d0 = t * 4;
    float4 qv = *(const float4*)&g_Q [(size_t)i*1024 + d0];
    float4 kv = *(const float4*)&g_K [(size_t)i*1024 + d0];
    float4 vv = *(const float4*)&g_V [(size_t)i*1024 + d0];
    float4 cq = *(const float4*)&g_Cq[(size_t)i*1024 + d0];
    float4 ck = *(const float4*)&g_Ck[(size_t)i*1024 + d0];
    const float* qvp = (const float*)&qv;
    const float* kvp = (const float*)&kv;
    const float* cqp = (const float*)&cq;
    const float* ckp = (const float*)&ck;
    ushort4 qh4, kh4;
    unsigned short* qhp = &qh4.x;
    unsigned short* khp = &kh4.x;
#pragma unroll
    for (int j = 0; j < 4; j++) {
        int d = d0 + j;
        float qmb = 0.f, kmb = 0.f;
#pragma unroll
        for (int u = 0; u < 16; u++) {
            qmb += pqs[u] * qq_mb[u*1024 + d];
            kmb += pks[u] * qk_mb[u*1024 + d];
        }
        float qq = fq*qmb + (1.f - fq)*cqp[j];
        float kq = fk*kmb + (1.f - fk)*ckp[j];
        float oq = (0.7f*qvp[j] + 0.3f*qq) * 0.125f;
        float ok =  0.7f*kvp[j] + 0.3f*kq;
        qhp[j] = __half_as_ushort(__float2half_rn(oq));
        khp[j] = __half_as_ushort(__float2half_rn(ok));
    }
    int h = d0 >> 6, dh = d0 & 63;
    int bh = b*16 + h;
    size_t qb = ((size_t)bh*SEQ + s)*AD + dh;
    *(ushort4*)&g_Qah[qb] = qh4;
    *(ushort4*)&g_Kah[qb] = kh4;
    *(float4*)&g_Va[((size_t)bh*SEQ + s)*HD + dh] = vv;
    int h2 = t >> 4, u = t & 15;
    int bh2 = b*16 + h2;
    size_t tb = ((size_t)bh2*SEQ + s)*AD + 64 + u;
    g_Qah[tb] = __float2half_rn(0.1f * pqs[u]);
    g_Kah[tb] = __float2half_rn(pks[u]);
}

// ---------------- V transpose: Va [bh][s][64] f32 -> Vth [bh][d][s] fp16 ----------------
__global__ __launch_bounds__(256) void vtrans_kernel()
{
    __shared__ float tile[64][65];
    int s0 = blockIdx.x * 64, bh = blockIdx.y;
    int t = threadIdx.x;
    int r = t >> 2, c4 = (t & 3) * 16;
    const float* src = g_Va + ((size_t)bh*SEQ + s0 + r)*HD + c4;
#pragma unroll
    for (int j = 0; j < 16; j += 4) {
        float4 v = *(const float4*)&src[j];
        tile[r][c4 + j + 0] = v.x;
        tile[r][c4 + j + 1] = v.y;
        tile[r][c4 + j + 2] = v.z;
        tile[r][c4 + j + 3] = v.w;
    }
    __syncthreads();
    int d = t >> 2, sc = (t & 3) * 16;
    ushort4 ho[4];
#pragma unroll
    for (int j = 0; j < 16; j++) {
        float v = tile[sc + j][d];
        (&ho[j >> 2].x)[j & 3] = __half_as_ushort(__float2half_rn(v));
    }
    size_t base = ((size_t)bh*HD + d)*SEQ + s0 + sc;
#pragma unroll
    for (int j = 0; j < 4; j++)
        *(ushort4*)&g_Vth[base + j*4] = ho[j];
}

// ---------------- flash attention (fp16 mma) ----------------
// smem layout (bytes):
//  Q 0..11264
//  stage s at ST0B + s*STAGEB: K(22528) V(+22528, 17408); STAGEB=39936
//  P tile aliases current stage's K region.
//  reductions at REDB(1024)
#define ST0B 11264
#define VOFF 22528
#define STAGEB 39936
#define REDB 91136
#define FLASH2_SMEM 92160

__device__ __forceinline__ void load_q_f(uint32_t sb, int t, int bh, int qt)
{
    const char* qh = (const char*)(g_Qah + ((size_t)bh*SEQ + qt*64)*AD);
#pragma unroll 1
    for (int i = t; i < 640; i += 256) {
        int row = i / 10, c = i % 10;
        cp16(sb + (uint32_t)(row*176 + c*16), qh + (size_t)row*160 + c*16);
    }
}

__device__ __forceinline__ void load_kv_f(uint32_t stb, int t, int bh, int k0)
{
    const char* kh = (const char*)(g_Kah + ((size_t)bh*SEQ + k0)*AD);
#pragma unroll 1
    for (int i = t; i < 1280; i += 256) {
        int row = i / 10, c = i % 10;
        cp16(stb + (uint32_t)(row*176 + c*16), kh + (size_t)row*160 + c*16);
    }
    const __half* vh = g_Vth + (size_t)bh*HD*SEQ + k0;
#pragma unroll 1
    for (int i = t; i < 1024; i += 256) {
        int d = i >> 4, c = i & 15;
        cp16(stb + VOFF + (uint32_t)(d*272 + c*16), (const char*)(vh + (size_t)d*SEQ) + c*16);
    }
    asm volatile("cp.async.commit_group;\n" ::: "memory");
}

__global__ __launch_bounds__(256, 2) void flash_mma_kernel(float* __restrict__ w_out)
{
    extern __shared__ char smem[];
    uint32_t sb = smem_u32(smem);
    float* redm = (float*)(smem + REDB);      // [2][64]
    float* reds = redm + 128;                 // [2][64]

    int qt = blockIdx.x, bh = blockIdx.y;
    int t = threadIdx.x;
    int warp = t >> 5, lane = t & 31;
    int wm = warp & 3, wn = warp >> 2;       // 4 m-strips x 2 n-halves

    int aq = lane >> 3;
    int arow = (aq & 1) * 8 + (lane & 7);
    int akoff = (aq >> 1) * 8;
    int b4n = (lane >> 4) * 8 + (lane & 7);
    int b4k = ((lane >> 3) & 1) * 8;
    int rin = lane >> 2, cin = (lane & 3) * 2;

    load_q_f(sb, t, bh, qt);
    load_kv_f(sb + ST0B, t, bh, 0);
    load_kv_f(sb + ST0B + STAGEB, t, bh, 128);

    float m_run0 = -1e30f, m_run1 = -1e30f;
    float l_run0 = 0.f, l_run1 = 0.f;
    float O[4][4];
#pragma unroll
    for (int a = 0; a < 4; a++)
#pragma unroll
        for (int b = 0; b < 4; b++) O[a][b] = 0.f;

    int r0 = wm*16 + rin, r1 = r0 + 8;

#pragma unroll 1
    for (int kt = 0; kt < 16; kt++) {
        if (kt < 15) asm volatile("cp.async.wait_group 1;\n" ::: "memory");
        else         asm volatile("cp.async.wait_group 0;\n" ::: "memory");
        __syncthreads();
        uint32_t stoff = (uint32_t)(ST0B + (kt & 1) * STAGEB);
        uint32_t st = sb + stoff;
        __half2* Pph = (__half2*)(smem + stoff);   // aliases K region

        // ---- S = Q @ K^T (fp16 single leg) ----
        float sacc[8][4];
#pragma unroll
        for (int a = 0; a < 8; a++)
#pragma unroll
            for (int b = 0; b < 4; b++) sacc[a][b] = 0.f;
#pragma unroll
        for (int ks = 0; ks < 5; ks++) {
            int kb = ks * 16;
            uint32_t qaddr = sb + (uint32_t)(((wm*16 + arow)*88 + kb + akoff) * 2);
            uint32_t qf[4];
            ldsm4(qf, qaddr);
#pragma unroll
            for (int p = 0; p < 4; p++) {
                uint32_t kaddr = st + (uint32_t)(((wn*64 + p*16 + b4n)*88 + kb + b4k) * 2);
                uint32_t kh4[4];
                ldsm4(kh4, kaddr);
                mma16816h(sacc[2*p],   qf, kh4);
                mma16816h(sacc[2*p+1], qf, kh4+2);
            }
        }

        // ---- online softmax ----
        float lm0 = -1e30f, lm1 = -1e30f;
#pragma unroll
        for (int nt = 0; nt < 8; nt++) {
            lm0 = fmaxf(lm0, fmaxf(sacc[nt][0], sacc[nt][1]));
            lm1 = fmaxf(lm1, fmaxf(sacc[nt][2], sacc[nt][3]));
        }
        lm0 = fmaxf(lm0, __shfl_xor_sync(0xffffffffu, lm0, 1));
        lm0 = fmaxf(lm0, __shfl_xor_sync(0xffffffffu, lm0, 2));
        lm1 = fmaxf(lm1, __shfl_xor_sync(0xffffffffu, lm1, 1));
        lm1 = fmaxf(lm1, __shfl_xor_sync(0xffffffffu, lm1, 2));
        if ((lane & 3) == 0) {
            redm[wn*64 + r0] = lm0;
            redm[wn*64 + r1] = lm1;
        }
        __syncthreads();   // all warps done reading K -> P may alias it
        float mn0 = fmaxf(m_run0, fmaxf(redm[r0], redm[64 + r0]));
        float mn1 = fmaxf(m_run1, fmaxf(redm[r1], redm[64 + r1]));
        float al0 = __expf(m_run0 - mn0);
        float al1 = __expf(m_run1 - mn1);
        m_run0 = mn0; m_run1 = mn1;

        float ls0 = 0.f, ls1 = 0.f;
        size_t wrow0 = ((size_t)bh*SEQ + qt*64 + r0) * SEQ + (size_t)kt*128 + wn*64 + cin;
        size_t wrow1 = wrow0 + (size_t)8 * SEQ;
        int pc = wn*32 + (cin >> 1);
#pragma unroll
        for (int nt = 0; nt < 8; nt++) {
            float p0 = __expf(sacc[nt][0] - mn0);
            float p1 = __expf(sacc[nt][1] - mn0);
            float p2 = __expf(sacc[nt][2] - mn1);
            float p3 = __expf(sacc[nt][3] - mn1);
            ls0 += p0 + p1; ls1 += p2 + p3;
            *(float2*)&w_out[wrow0 + nt*8] = make_float2(p0, p1);
            *(float2*)&w_out[wrow1 + nt*8] = make_float2(p2, p3);
            Pph[r0*68 + pc + nt*4] = __floats2half2_rn(p0, p1);
            Pph[r1*68 + pc + nt*4] = __floats2half2_rn(p2, p3);
        }
        ls0 += __shfl_xor_sync(0xffffffffu, ls0, 1);
        ls0 += __shfl_xor_sync(0xffffffffu, ls0, 2);
        ls1 += __shfl_xor_sync(0xffffffffu, ls1, 1);
        ls1 += __shfl_xor_sync(0xffffffffu, ls1, 2);
        if ((lane & 3) == 0) {
            reds[wn*64 + r0] = ls0;
            reds[wn*64 + r1] = ls1;
        }
        if (wn == 0 && (lane & 3) == 0) {
            g_mt[((size_t)bh*SEQ + qt*64 + r0)*16 + kt] = mn0;
            g_mt[((size_t)bh*SEQ + qt*64 + r1)*16 + kt] = mn1;
        }
#pragma unroll
        for (int nt = 0; nt < 4; nt++) {
            O[nt][0] *= al0; O[nt][1] *= al0;
            O[nt][2] *= al1; O[nt][3] *= al1;
        }
        __syncthreads();   // P fully written before PV reads
        l_run0 = l_run0*al0 + reds[r0] + reds[64 + r0];
        l_run1 = l_run1*al1 + reds[r1] + reds[64 + r1];

        // ---- O += P @ V (fp16) ----
#pragma unroll
        for (int ks = 0; ks < 8; ks++) {
            int kb = ks * 16;
            uint32_t paddr = st + (uint32_t)(((wm*16 + arow)*136 + kb + akoff) * 2);
            uint32_t pf[4];
            ldsm4(pf, paddr);
#pragma unroll
            for (int p = 0; p < 2; p++) {
                uint32_t vaddr = st + VOFF + (uint32_t)(((wn*32 + p*16 + b4n)*136 + kb + b4k) * 2);
                uint32_t vh4[4];
                ldsm4(vh4, vaddr);
                mma16816h(O[2*p],   pf, vh4);
                mma16816h(O[2*p+1], pf, vh4+2);
            }
        }
        __syncthreads();
        if (kt + 2 < 16) load_kv_f(st, t, bh, (kt + 2) * 128);
    }

    // ---- epilogue: write att as fp16 directly ----
    float inv0 = 1.f / l_run0, inv1 = 1.f / l_run1;
    int b = bh >> 4, h = bh & 15;
    int rg0 = qt*64 + r0;
#pragma unroll
    for (int nt = 0; nt < 4; nt++) {
        int d = h*64 + wn*32 + nt*8 + cin;
        size_t i0 = ((size_t)b*SEQ + rg0)*1024 + d;
        size_t i1 = ((size_t)b*SEQ + rg0 + 8)*1024 + d;
        *(__half2*)&g_ah[i0] = __floats2half2_rn(O[nt][0]*inv0, O[nt][1]*inv0);
        *(__half2*)&g_ah[i1] = __floats2half2_rn(O[nt][2]*inv1, O[nt][3]*inv1);
    }
    if (wn == 0 && (lane & 3) == 0) {
        g_m[(size_t)bh*SEQ + rg0] = m_run0;
        g_l[(size_t)bh*SEQ + rg0] = l_run0;
        g_m[(size_t)bh*SEQ + rg0 + 8] = m_run1;
        g_l[(size_t)bh*SEQ + rg0 + 8] = l_run1;
    }
}

// ---------------- normalize w ----------------
__global__ __launch_bounds__(256) void norm_w_kernel(float* __restrict__ w)
{
    size_t idx = (size_t)blockIdx.x * 256 + threadIdx.x;
    size_t e0 = idx * 4;
    size_t row = e0 >> 11;
    int kt = (int)((e0 & 2047) >> 7);
    float f = __expf(g_mt[row*16 + kt] - g_m[row]) / g_l[row];
    float4 v = *(float4*)&w[e0];
    v.x *= f; v.y *= f; v.z *= f; v.w *= f;
    *(float4*)&w[e0] = v;
}

// ---------------- layernorm ----------------
__global__ __launch_bounds__(256) void ln_kernel(const float* __restrict__ gam,
    const float* __restrict__ bet, float* __restrict__ y)
{
    int i = blockIdx.x, t = threadIdx.x;
    float4 v = *(const float4*)&g_res[(size_t)i*1024 + t*4];
    float s  = v.x + v.y + v.z + v.w;
    float ss = v.x*v.x + v.y*v.y + v.z*v.z + v.w*v.w;
#pragma unroll
    for (int off = 16; off; off >>= 1) {
        s  += __shfl_xor_sync(0xffffffffu, s,  off);
        ss += __shfl_xor_sync(0xffffffffu, ss, off);
    }
    __shared__ float as[8], ass[8];
    if ((t & 31) == 0) { as[t >> 5] = s; ass[t >> 5] = ss; }
    __syncthreads();
    float S = 0.f, SS = 0.f;
#pragma unroll
    for (int u = 0; u < 8; u++) { S += as[u]; SS += ass[u]; }
    float mu  = S * (1.f/1024.f);
    float var = SS * (1.f/1024.f) - mu*mu;
    float inv = rsqrtf(var + 1e-5f);
    float4 gg = *(const float4*)&gam[t*4];
    float4 bb = *(const float4*)&bet[t*4];
    float4 o;
    o.x = (v.x - mu)*inv*gg.x + bb.x;
    o.y = (v.y - mu)*inv*gg.y + bb.y;
    o.z = (v.z - mu)*inv*gg.z + bb.z;
    o.w = (v.w - mu)*inv*gg.w + bb.w;
    *(float4*)&y[(size_t)i*1024 + t*4] = o;
}

// ---------------- launch ----------------
extern "C" void kernel_launch(void* const* d_in, const int* in_sizes, int n_in,
                              void* d_out, int out_size)
{
    const float* x       = (const float*)d_in[0];
    const float* Wq      = (const float*)d_in[1];
    const float* bq      = (const float*)d_in[2];
    const float* Wk      = (const float*)d_in[3];
    const float* bk      = (const float*)d_in[4];
    const float* Wv      = (const float*)d_in[5];
    const float* bv      = (const float*)d_in[6];
    const float* Wo      = (const float*)d_in[7];
    const float* bo      = (const float*)d_in[8];
    const float* ln_g    = (const float*)d_in[9];
    const float* ln_b    = (const float*)d_in[10];
    const float* qq_W    = (const float*)d_in[11];
    const float* qq_b    = (const float*)d_in[12];
    const float* qq_qw_r = (const float*)d_in[13];
    const float* qq_qw_i = (const float*)d_in[14];
    const float* qq_sg   = (const float*)d_in[15];
    const float* qq_em   = (const float*)d_in[16];
    const float* qq_mb   = (const float*)d_in[17];
    const float* qk_W    = (const float*)d_in[18];
    const float* qk_b    = (const float*)d_in[19];
    const float* qk_qw_r = (const float*)d_in[20];
    const float* qk_qw_i = (const float*)d_in[21];
    const float* qk_sg   = (const float*)d_in[22];
    const float* qk_em   = (const float*)d_in[23];
    const float* qk_mb   = (const float*)d_in[24];

    float* y = (float*)d_out;
    float* w = y + (size_t)MROWS*DMODEL;

    float *pQ, *pK, *pV, *pCq, *pCk, *pRes;
    cudaGetSymbolAddress((void**)&pQ,   g_Q);
    cudaGetSymbolAddress((void**)&pK,   g_K);
    cudaGetSymbolAddress((void**)&pV,   g_V);
    cudaGetSymbolAddress((void**)&pCq,  g_Cq);
    cudaGetSymbolAddress((void**)&pCk,  g_Ck);
    cudaGetSymbolAddress((void**)&pRes, g_res);
    __half *pXh, *pAh, *pWh;
    cudaGetSymbolAddress((void**)&pXh, g_xh);
    cudaGetSymbolAddress((void**)&pAh, g_ah);
    cudaGetSymbolAddress((void**)&pWh, g_Wh);

    cudaFuncSetAttribute(mma_gemm_kernel,
        cudaFuncAttributeMaxDynamicSharedMemorySize, GEMM_SMEM);
    cudaFuncSetAttribute(mma_gemm5_kernel,
        cudaFuncAttributeMaxDynamicSharedMemorySize, GEMM_SMEM);
    cudaFuncSetAttribute(flash_mma_kernel,
        cudaFuncAttributeMaxDynamicSharedMemorySize, FLASH2_SMEM);

    prep_m_kernel<<<1, 256>>>(qq_qw_r, qq_qw_i, qk_qw_r, qk_qw_i, qq_em, qk_em);
    quantum_kernel<<<MROWS, 128>>>(x, qq_sg, qk_sg);

    aconv_kernel<<<MROWS*DMODEL/(256*8), 256>>>(x, pXh);
    WconvP WP;
    WP.W[0] = Wq; WP.W[1] = Wk; WP.W[2] = Wv;
    WP.W[3] = qq_W; WP.W[4] = qk_W; WP.W[5] = Wo;
    wconv6_kernel<<<dim3(32, 32, 6), dim3(32, 8)>>>(WP, pWh);

    // 5 forward GEMMs in one launch
    const size_t WSZ = (size_t)DMODEL*DMODEL;
    GemmP5 P;
    P.Bh[0] = pWh + 0*WSZ; P.bias[0] = bq;   P.out[0] = pQ;  P.tanh_f[0] = 0;
    P.Bh[1] = pWh + 1*WSZ; P.bias[1] = bk;   P.out[1] = pK;  P.tanh_f[1] = 0;
    P.Bh[2] = pWh + 2*WSZ; P.bias[2] = bv;   P.out[2] = pV;  P.tanh_f[2] = 0;
    P.Bh[3] = pWh + 3*WSZ; P.bias[3] = qq_b; P.out[3] = pCq; P.tanh_f[3] = 1;
    P.Bh[4] = pWh + 4*WSZ; P.bias[4] = qk_b; P.out[4] = pCk; P.tanh_f[4] = 1;
    dim3 g5(32, 8, 5);
    mma_gemm5_kernel<<<g5, 256, GEMM_SMEM>>>(pXh, P);

    combine_kernel<<<MROWS, 256>>>(qq_mb, qk_mb);
    vtrans_kernel<<<dim3(32, 32), 256>>>();

    flash_mma_kernel<<<dim3(32, 32), 256, FLASH2_SMEM>>>(w);

    norm_w_kernel<<<(NBH*(size_t)SEQ*SEQ)/(4*256), 256>>>(w);

    // output projection: att @ Wo + bo + x
    dim3 gg(32, 8);
    mma_gemm_kernel<<<gg, 256, GEMM_SMEM>>>(pAh, pWh + 5*WSZ, bo, x, pRes, 0);

    ln_kernel<<<MROWS, 256>>>(ln_g, ln_b, y);
}

// round 12
// speedup vs baseline: 3.7595x; 1.0212x over previous
#include <cuda_runtime.h>
#include <cuda_fp16.h>
#include <cstdint>
#include <math.h>

#define MROWS 4096
#define DMODEL 1024
#define NH 16
#define HD 64
#define QD 16
#define SEQ 2048
#define NBH 32
#define AD 80

// ---------------- scratch ----------------
__device__ __align__(16) float g_Q[MROWS*DMODEL];
__device__ __align__(16) float g_K[MROWS*DMODEL];
__device__ __align__(16) float g_V[MROWS*DMODEL];
__device__ __align__(16) float g_Cq[MROWS*DMODEL];
__device__ __align__(16) float g_Ck[MROWS*DMODEL];
__device__ __align__(16) float g_res[MROWS*DMODEL];
__device__ __align__(16) float g_Va[NBH*SEQ*HD];
__device__ __align__(16) float g_probs_q[MROWS*QD];
__device__ __align__(16) float g_probs_k[MROWS*QD];
__device__ float g_fw_q[MROWS];
__device__ float g_fw_k[MROWS];
__device__ float g_m[NBH*SEQ];
__device__ float g_l[NBH*SEQ];
__device__ float g_mt[NBH*SEQ*16];    // running max snapshot per 128-key tile
__device__ float g_M[4*256];

// fp16 buffers (16B-aligned for uint4/cp.async)
__device__ __align__(16) __half g_xh[MROWS*DMODEL];
__device__ __align__(16) __half g_ah[MROWS*DMODEL];
__device__ __align__(16) __half g_Wh[6*DMODEL*DMODEL];     // [widx][n][k]
__device__ __align__(16) __half g_Qah[NBH*SEQ*AD];
__device__ __align__(16) __half g_Kah[NBH*SEQ*AD];
__device__ __align__(16) __half g_Vth[NBH*HD*SEQ];         // [bh][d][s]

// ---------------- helpers ----------------
__device__ __forceinline__ uint32_t smem_u32(const void* p) {
    uint32_t a;
    asm("{ .reg .u64 t; cvta.to.shared.u64 t, %1; cvt.u32.u64 %0, t; }" : "=r"(a) : "l"(p));
    return a;
}
__device__ __forceinline__ void cp16(uint32_t dst, const void* src) {
    asm volatile("cp.async.cg.shared.global [%0], [%1], 16;\n" :: "r"(dst), "l"(src));
}
__device__ __forceinline__ void ldsm4(uint32_t* r, uint32_t addr) {
    asm volatile("ldmatrix.sync.aligned.m8n8.x4.shared.b16 {%0,%1,%2,%3}, [%4];"
        : "=r"(r[0]), "=r"(r[1]), "=r"(r[2]), "=r"(r[3]) : "r"(addr));
}
__device__ __forceinline__ void ldsm2(uint32_t* r, uint32_t addr) {
    asm volatile("ldmatrix.sync.aligned.m8n8.x2.shared.b16 {%0,%1}, [%2];"
        : "=r"(r[0]), "=r"(r[1]) : "r"(addr));
}
__device__ __forceinline__ void mma16816h(float* d, const uint32_t* a, const uint32_t* b) {
    asm volatile("mma.sync.aligned.m16n8k16.row.col.f32.f16.f16.f32 "
        "{%0,%1,%2,%3}, {%4,%5,%6,%7}, {%8,%9}, {%0,%1,%2,%3};"
        : "+f"(d[0]), "+f"(d[1]), "+f"(d[2]), "+f"(d[3])
        : "r"(a[0]), "r"(a[1]), "r"(a[2]), "r"(a[3]), "r"(b[0]), "r"(b[1]));
}

// ---------------- conversions ----------------
__global__ __launch_bounds__(256) void aconv_kernel(const float* __restrict__ a,
    __half* __restrict__ h)
{
    size_t i = ((size_t)blockIdx.x * 256 + threadIdx.x) * 8;
    float4 v0 = *(const float4*)&a[i];
    float4 v1 = *(const float4*)&a[i + 4];
    __half2 o[4];
    o[0] = __floats2half2_rn(v0.x, v0.y);
    o[1] = __floats2half2_rn(v0.z, v0.w);
    o[2] = __floats2half2_rn(v1.x, v1.y);
    o[3] = __floats2half2_rn(v1.z, v1.w);
    *(uint4*)&h[i] = *(uint4*)o;
}

struct WconvP { const float* W[6]; };
__global__ __launch_bounds__(256) void wconv6_kernel(WconvP P, __half* __restrict__ h_base)
{
    __shared__ float tile[32][33];
    const float* W = P.W[blockIdx.z];
    __half* hh = h_base + (size_t)blockIdx.z * DMODEL * DMODEL;
    int bx = blockIdx.x * 32;
    int by = blockIdx.y * 32;
    int tx = threadIdx.x, ty = threadIdx.y;
#pragma unroll
    for (int i = 0; i < 32; i += 8)
        tile[ty + i][tx] = W[(size_t)(by + ty + i) * 1024 + bx + tx];
    __syncthreads();
#pragma unroll
    for (int i = 0; i < 32; i += 8) {
        int n = bx + ty + i, k = by + tx;
        hh[(size_t)n * 1024 + k] = __float2half_rn(tile[tx][ty + i]);
    }
}

// ---------------- mma.sync fp16 GEMM ----------------
#define SROW 40
#define MAT_E (128*SROW)
#define SST_B (2*MAT_E*2)
#define GEMM_SMEM (2*SST_B)

__device__ __forceinline__ void load_chunk_mm(uint32_t sb, int t, int m0, int n0, int k0,
    const __half* Ah, const __half* Bh)
{
#pragma unroll
    for (int i = 0; i < 2; i++) {
        int cid = i * 256 + t;
        int row = cid >> 2, c = cid & 3;
        uint32_t off = (uint32_t)(row * (SROW*2) + c * 16);
        cp16(sb + off,           (const char*)(Ah + (size_t)(m0 + row) * 1024 + k0) + c * 16);
        cp16(sb + MAT_E*2 + off, (const char*)(Bh + (size_t)(n0 + row) * 1024 + k0) + c * 16);
    }
    asm volatile("cp.async.commit_group;\n" ::: "memory");
}

__device__ __forceinline__ void gemm_body(
    uint32_t sb, int m0, int n0,
    const __half* Ah, const __half* Bh,
    const float* bias, const float* resid, float* out, int do_tanh)
{
    int t = threadIdx.x;
    int warp = t >> 5, lane = t & 31;
    int wm = warp & 1, wn = warp >> 1;

    float acc[4][4][4];
#pragma unroll
    for (int a = 0; a < 4; a++)
#pragma unroll
        for (int b = 0; b < 4; b++)
#pragma unroll
            for (int c = 0; c < 4; c++) acc[a][b][c] = 0.f;

    int aq = lane >> 3;
    int arow = (aq & 1) * 8 + (lane & 7);
    int akoff = (aq >> 1) * 8;
    int brow = lane & 7;
    int bkoff = ((lane >> 3) & 1) * 8;

    load_chunk_mm(sb, t, m0, n0, 0, Ah, Bh);

#pragma unroll 1
    for (int c = 0; c < 32; c++) {
        if (c < 31)
            load_chunk_mm(sb + ((c + 1) & 1) * SST_B, t, m0, n0, (c + 1) * 32, Ah, Bh);
        if (c < 31) asm volatile("cp.async.wait_group 1;\n" ::: "memory");
        else        asm volatile("cp.async.wait_group 0;\n" ::: "memory");
        __syncthreads();

        uint32_t st = sb + (c & 1) * SST_B;
#pragma unroll
        for (int k16 = 0; k16 < 2; k16++) {
            int kb = k16 * 16;
            uint32_t ah4[4][4];
#pragma unroll
            for (int mt = 0; mt < 4; mt++) {
                uint32_t aaddr = st + (uint32_t)(((wm*64 + mt*16 + arow) * SROW + kb + akoff) * 2);
                ldsm4(ah4[mt], aaddr);
            }
#pragma unroll
            for (int nt = 0; nt < 4; nt++) {
                uint32_t baddr = st + MAT_E*2 +
                    (uint32_t)(((wn*32 + nt*8 + brow) * SROW + kb + bkoff) * 2);
                uint32_t bh2[2];
                ldsm2(bh2, baddr);
#pragma unroll
                for (int mt = 0; mt < 4; mt++)
                    mma16816h(acc[mt][nt], ah4[mt], bh2);
            }
        }
        __syncthreads();
    }

    int rin = lane >> 2, cin = (lane & 3) * 2;
#pragma unroll
    for (int mt = 0; mt < 4; mt++) {
#pragma unroll
        for (int nt = 0; nt < 4; nt++) {
            int n = n0 + wn*32 + nt*8 + cin;
            float b0 = bias[n], b1 = bias[n + 1];
#pragma unroll
            for (int half_i = 0; half_i < 2; half_i++) {
                int m = m0 + wm*64 + mt*16 + rin + half_i*8;
                float v0 = acc[mt][nt][half_i*2 + 0] + b0;
                float v1 = acc[mt][nt][half_i*2 + 1] + b1;
                if (resid) {
                    const float* rr = resid + (size_t)m * 1024 + n;
                    v0 += rr[0]; v1 += rr[1];
                }
                if (do_tanh) { v0 = tanhf(v0); v1 = tanhf(v1); }
                *(float2*)&out[(size_t)m * 1024 + n] = make_float2(v0, v1);
            }
        }
    }
}

struct GemmP5 {
    const __half* Bh[5];
    const float* bias[5];
    float* out[5];
    int tanh_f[5];
};

__global__ __launch_bounds__(256) void mma_gemm5_kernel(
    const __half* __restrict__ Ah, GemmP5 P)
{
    extern __shared__ char smem[];
    uint32_t sb = smem_u32(smem);
    int z = blockIdx.z;
    gemm_body(sb, blockIdx.x * 128, blockIdx.y * 128,
              Ah, P.Bh[z], P.bias[z], nullptr, P.out[z], P.tanh_f[z]);
}

__global__ __launch_bounds__(256) void mma_gemm_kernel(
    const __half* __restrict__ Ah, const __half* __restrict__ Bh,
    const float* __restrict__ bias, const float* __restrict__ resid,
    float* __restrict__ out, int do_tanh)
{
    extern __shared__ char smem[];
    uint32_t sb = smem_u32(smem);
    gemm_body(sb, blockIdx.x * 128, blockIdx.y * 128,
              Ah, Bh, bias, resid, out, do_tanh);
}

// ---------------- prep: M = qw @ em ----------------
__global__ void prep_m_kernel(const float* __restrict__ qqr, const float* __restrict__ qqi,
                              const float* __restrict__ qkr, const float* __restrict__ qki,
                              const float* __restrict__ qqem, const float* __restrict__ qkem)
{
    int t = threadIdx.x;
    int u = t >> 4, v = t & 15;
    float a = 0.f, b = 0.f, c = 0.f, d = 0.f;
#pragma unroll
    for (int w = 0; w < 16; w++) {
        float e1 = qqem[w*16+v], e2 = qkem[w*16+v];
        a += qqr[u*16+w]*e1;
        b += qqi[u*16+w]*e1;
        c += qkr[u*16+w]*e2;
        d += qki[u*16+w]*e2;
    }
    g_M[t] = a; g_M[256+t] = b; g_M[512+t] = c; g_M[768+t] = d;
}

// ---------------- quantum small path ----------------
__global__ __launch_bounds__(128) void quantum_kernel(
    const float* __restrict__ x, const float* __restrict__ sgq, const float* __restrict__ sgk)
{
    __shared__ float xs[1024];
    __shared__ float part[8][16];
    __shared__ float qss[16];
    __shared__ float prob_s[16];
    int i = blockIdx.x;
    int t = threadIdx.x;
#pragma unroll
    for (int c = 0; c < 2; c++)
        *(float4*)&xs[(t + c*128)*4] = *(const float4*)&x[(size_t)i*1024 + (t + c*128)*4];
    __syncthreads();
    int tt = t & 15, pp = t >> 4;
#pragma unroll 1
    for (int side = 0; side < 2; side++) {
        const float* sg = side ? sgk : sgq;
        float acc = 0.f;
        int base = pp * 128;
        for (int d = 0; d < 128; d++)
            acc += xs[base + d] * sg[(base + d)*16 + tt];
        part[pp][tt] = acc;
        __syncthreads();
        if (t < 16) {
            float q = 0.f;
#pragma unroll
            for (int p = 0; p < 8; p++) q += part[p][t];
            qss[t] = q;
        }
        __syncthreads();
        if (t < 16) {
            const float* Mr = g_M + side*512;
            const float* Mi = Mr + 256;
            float er = 0.f, ei = 0.f;
#pragma unroll
            for (int u = 0; u < 16; u++) {
                er += qss[u]*Mr[u*16+t];
                ei += qss[u]*Mi[u*16+t];
            }
            float pr = er*er + ei*ei;
            prob_s[t] = pr;
            (side ? g_probs_k : g_probs_q)[i*16 + t] = pr;
        }
        __syncthreads();
        if (t == 0) {
            float ms = 0.f;
#pragma unroll
            for (int u = 0; u < 16; u++) ms += prob_s[u];
            ms *= (1.f/16.f);
            (side ? g_fw_k : g_fw_q)[i] = 1.f/(1.f + __expf(-ms));
        }
        __syncthreads();
    }
}

// ---------------- combine ----------------
__global__ __launch_bounds__(256) void combine_kernel(
    const float* __restrict__ qq_mb, const float* __restrict__ qk_mb)
{
    int i = blockIdx.x;
    int b = i >> 11, s = i & 2047;
    int t = threadIdx.x;
    __shared__ float pqs[16], pks[16];
    if (t < 16) pqs[t] = g_probs_q[i*16 + t];
    else if (t < 32) pks[t-16] = g_probs_k[i*16 + (t-16)];
    __syncthreads();
    float fq = g_fw_q[i], fk = g_fw_k[i];
    int d0 = t * 4;
    float4 qv = *(const float4*)&g_Q [(size_t)i*1024 + d0];
    float4 kv = *(const float4*)&g_K [(size_t)i*1024 + d0];
    float4 vv = *(const float4*)&g_V [(size_t)i*1024 + d0];
    float4 cq = *(const float4*)&g_Cq[(size_t)i*1024 + d0];
    float4 ck = *(const float4*)&g_Ck[(size_t)i*1024 + d0];
    const float* qvp = (const float*)&qv;
    const float* kvp = (const float*)&kv;
    const float* cqp = (const float*)&cq;
    const float* ckp = (const float*)&ck;
    ushort4 qh4, kh4;
    unsigned short* qhp = &qh4.x;
    unsigned short* khp = &kh4.x;
#pragma unroll
    for (int j = 0; j < 4; j++) {
        int d = d0 + j;
        float qmb = 0.f, kmb = 0.f;
#pragma unroll
        for (int u = 0; u < 16; u++) {
            qmb += pqs[u] * qq_mb[u*1024 + d];
            kmb += pks[u] * qk_mb[u*1024 + d];
        }
        float qq = fq*qmb + (1.f - fq)*cqp[j];
        float kq = fk*kmb + (1.f - fk)*ckp[j];
        float oq = (0.7f*qvp[j] + 0.3f*qq) * 0.125f;
        float ok =  0.7f*kvp[j] + 0.3f*kq;
        qhp[j] = __half_as_ushort(__float2half_rn(oq));
        khp[j] = __half_as_ushort(__float2half_rn(ok));
    }
    int h = d0 >> 6, dh = d0 & 63;
    int bh = b*16 + h;
    size_t qb = ((size_t)bh*SEQ + s)*AD + dh;
    *(ushort4*)&g_Qah[qb] = qh4;
    *(ushort4*)&g_Kah[qb] = kh4;
    *(float4*)&g_Va[((size_t)bh*SEQ + s)*HD + dh] = vv;
    int h2 = t >> 4, u = t & 15;
    int bh2 = b*16 + h2;
    size_t tb = ((size_t)bh2*SEQ + s)*AD + 64 + u;
    g_Qah[tb] = __float2half_rn(0.1f * pqs[u]);
    g_Kah[tb] = __float2half_rn(pks[u]);
}

// ---------------- V transpose ----------------
__global__ __launch_bounds__(256) void vtrans_kernel()
{
    __shared__ float tile[64][65];
    int s0 = blockIdx.x * 64, bh = blockIdx.y;
    int t = threadIdx.x;
    int r = t >> 2, c4 = (t & 3) * 16;
    const float* src = g_Va + ((size_t)bh*SEQ + s0 + r)*HD + c4;
#pragma unroll
    for (int j = 0; j < 16; j += 4) {
        float4 v = *(const float4*)&src[j];
        tile[r][c4 + j + 0] = v.x;
        tile[r][c4 + j + 1] = v.y;
        tile[r][c4 + j + 2] = v.z;
        tile[r][c4 + j + 3] = v.w;
    }
    __syncthreads();
    int d = t >> 2, sc = (t & 3) * 16;
    ushort4 ho[4];
#pragma unroll
    for (int j = 0; j < 16; j++) {
        float v = tile[sc + j][d];
        (&ho[j >> 2].x)[j & 3] = __half_as_ushort(__float2half_rn(v));
    }
    size_t base = ((size_t)bh*HD + d)*SEQ + s0 + sc;
#pragma unroll
    for (int j = 0; j < 4; j++)
        *(ushort4*)&g_Vth[base + j*4] = ho[j];
}

// ---------------- flash attention (fp16 mma, P in registers) ----------------
// smem: Q 0..11264; stage s at ST0B+s*STAGEB: K(22528) V(17408); red at REDB.
// End-of-kernel O exchange reuses stage0 region (dead after last tile).
#define ST0B 11264
#define VOFF 22528
#define STAGEB 39936
#define REDB 91136
#define FLASH2_SMEM 92160

__device__ __forceinline__ void load_q_f(uint32_t sb, int t, int bh, int qt)
{
    const char* qh = (const char*)(g_Qah + ((size_t)bh*SEQ + qt*64)*AD);
#pragma unroll 1
    for (int i = t; i < 640; i += 256) {
        int row = i / 10, c = i % 10;
        cp16(sb + (uint32_t)(row*176 + c*16), qh + (size_t)row*160 + c*16);
    }
}

__device__ __forceinline__ void load_kv_f(uint32_t stb, int t, int bh, int k0)
{
    const char* kh = (const char*)(g_Kah + ((size_t)bh*SEQ + k0)*AD);
#pragma unroll 1
    for (int i = t; i < 1280; i += 256) {
        int row = i / 10, c = i % 10;
        cp16(stb + (uint32_t)(row*176 + c*16), kh + (size_t)row*160 + c*16);
    }
    const __half* vh = g_Vth + (size_t)bh*HD*SEQ + k0;
#pragma unroll 1
    for (int i = t; i < 1024; i += 256) {
        int d = i >> 4, c = i & 15;
        cp16(stb + VOFF + (uint32_t)(d*272 + c*16), (const char*)(vh + (size_t)d*SEQ) + c*16);
    }
    asm volatile("cp.async.commit_group;\n" ::: "memory");
}

__global__ __launch_bounds__(256, 2) void flash_mma_kernel(float* __restrict__ w_out)
{
    extern __shared__ char smem[];
    uint32_t sb = smem_u32(smem);
    float* redm = (float*)(smem + REDB);      // [2][64]
    float* reds = redm + 128;                 // [2][64]

    int qt = blockIdx.x, bh = blockIdx.y;
    int t = threadIdx.x;
    int warp = t >> 5, lane = t & 31;
    int wm = warp & 3, wn = warp >> 2;       // 4 m-strips x 2 key-halves

    int aq = lane >> 3;
    int arow = (aq & 1) * 8 + (lane & 7);
    int akoff = (aq >> 1) * 8;
    int b4n = (lane >> 4) * 8 + (lane & 7);
    int b4k = ((lane >> 3) & 1) * 8;
    int rin = lane >> 2, cin = (lane & 3) * 2;

    load_q_f(sb, t, bh, qt);
    load_kv_f(sb + ST0B, t, bh, 0);
    load_kv_f(sb + ST0B + STAGEB, t, bh, 128);

    float m_run0 = -1e30f, m_run1 = -1e30f;
    float l_run0 = 0.f, l_run1 = 0.f;
    // O: 8 n8-frags x 4 (16 rows x 64 cols, partial over this warp's 64 keys)
    float O[8][4];
#pragma unroll
    for (int a = 0; a < 8; a++)
#pragma unroll
        for (int b = 0; b < 4; b++) O[a][b] = 0.f;

    int r0 = wm*16 + rin, r1 = r0 + 8;

#pragma unroll 1
    for (int kt = 0; kt < 16; kt++) {
        if (kt < 15) asm volatile("cp.async.wait_group 1;\n" ::: "memory");
        else         asm volatile("cp.async.wait_group 0;\n" ::: "memory");
        __syncthreads();
        uint32_t st = sb + (uint32_t)(ST0B + (kt & 1) * STAGEB);

        // ---- S = Q @ K^T ----
        float sacc[8][4];
#pragma unroll
        for (int a = 0; a < 8; a++)
#pragma unroll
            for (int b = 0; b < 4; b++) sacc[a][b] = 0.f;
#pragma unroll
        for (int ks = 0; ks < 5; ks++) {
            int kb = ks * 16;
            uint32_t qaddr = sb + (uint32_t)(((wm*16 + arow)*88 + kb + akoff) * 2);
            uint32_t qf[4];
            ldsm4(qf, qaddr);
#pragma unroll
            for (int p = 0; p < 4; p++) {
                uint32_t kaddr = st + (uint32_t)(((wn*64 + p*16 + b4n)*88 + kb + b4k) * 2);
                uint32_t kh4[4];
                ldsm4(kh4, kaddr);
                mma16816h(sacc[2*p],   qf, kh4);
                mma16816h(sacc[2*p+1], qf, kh4+2);
            }
        }

        // ---- online softmax ----
        float lm0 = -1e30f, lm1 = -1e30f;
#pragma unroll
        for (int nt = 0; nt < 8; nt++) {
            lm0 = fmaxf(lm0, fmaxf(sacc[nt][0], sacc[nt][1]));
            lm1 = fmaxf(lm1, fmaxf(sacc[nt][2], sacc[nt][3]));
        }
        lm0 = fmaxf(lm0, __shfl_xor_sync(0xffffffffu, lm0, 1));
        lm0 = fmaxf(lm0, __shfl_xor_sync(0xffffffffu, lm0, 2));
        lm1 = fmaxf(lm1, __shfl_xor_sync(0xffffffffu, lm1, 1));
        lm1 = fmaxf(lm1, __shfl_xor_sync(0xffffffffu, lm1, 2));
        if ((lane & 3) == 0) {
            redm[wn*64 + r0] = lm0;
            redm[wn*64 + r1] = lm1;
        }
        __syncthreads();
        float mn0 = fmaxf(m_run0, fmaxf(redm[r0], redm[64 + r0]));
        float mn1 = fmaxf(m_run1, fmaxf(redm[r1], redm[64 + r1]));
        float al0 = __expf(m_run0 - mn0);
        float al1 = __expf(m_run1 - mn1);
        m_run0 = mn0; m_run1 = mn1;

        float ls0 = 0.f, ls1 = 0.f;
        size_t wrow0 = ((size_t)bh*SEQ + qt*64 + r0) * SEQ + (size_t)kt*128 + wn*64 + cin;
        size_t wrow1 = wrow0 + (size_t)8 * SEQ;
#pragma unroll
        for (int nt = 0; nt < 8; nt++) {
            float p0 = __expf(sacc[nt][0] - mn0);
            float p1 = __expf(sacc[nt][1] - mn0);
            float p2 = __expf(sacc[nt][2] - mn1);
            float p3 = __expf(sacc[nt][3] - mn1);
            ls0 += p0 + p1; ls1 += p2 + p3;
            *(float2*)&w_out[wrow0 + nt*8] = make_float2(p0, p1);
            *(float2*)&w_out[wrow1 + nt*8] = make_float2(p2, p3);
            sacc[nt][0] = p0; sacc[nt][1] = p1;
            sacc[nt][2] = p2; sacc[nt][3] = p3;
        }
        ls0 += __shfl_xor_sync(0xffffffffu, ls0, 1);
        ls0 += __shfl_xor_sync(0xffffffffu, ls0, 2);
        ls1 += __shfl_xor_sync(0xffffffffu, ls1, 1);
        ls1 += __shfl_xor_sync(0xffffffffu, ls1, 2);
        if ((lane & 3) == 0) {
            reds[wn*64 + r0] = ls0;
            reds[wn*64 + r1] = ls1;
        }
        if (wn == 0 && (lane & 3) == 0) {
            g_mt[((size_t)bh*SEQ + qt*64 + r0)*16 + kt] = mn0;
            g_mt[((size_t)bh*SEQ + qt*64 + r1)*16 + kt] = mn1;
        }
#pragma unroll
        for (int nt = 0; nt < 8; nt++) {
            O[nt][0] *= al0; O[nt][1] *= al0;
            O[nt][2] *= al1; O[nt][3] *= al1;
        }
        __syncthreads();
        l_run0 = l_run0*al0 + reds[r0] + reds[64 + r0];
        l_run1 = l_run1*al1 + reds[r1] + reds[64 + r1];

        // ---- O += P @ V  (P from registers: C-frag == A-frag layout) ----
#pragma unroll
        for (int p = 0; p < 4; p++) {
            uint32_t pf[4];
            __half2 h;
            h = __floats2half2_rn(sacc[2*p][0],   sacc[2*p][1]);   pf[0] = *(uint32_t*)&h;
            h = __floats2half2_rn(sacc[2*p][2],   sacc[2*p][3]);   pf[1] = *(uint32_t*)&h;
            h = __floats2half2_rn(sacc[2*p+1][0], sacc[2*p+1][1]); pf[2] = *(uint32_t*)&h;
            h = __floats2half2_rn(sacc[2*p+1][2], sacc[2*p+1][3]); pf[3] = *(uint32_t*)&h;
#pragma unroll
            for (int cb = 0; cb < 4; cb++) {
                uint32_t vaddr = st + VOFF +
                    (uint32_t)(((cb*16 + b4n)*136 + wn*64 + p*16 + b4k) * 2);
                uint32_t vh4[4];
                ldsm4(vh4, vaddr);
                mma16816h(O[2*cb],   pf, vh4);
                mma16816h(O[2*cb+1], pf, vh4+2);
            }
        }
        __syncthreads();
        if (kt + 2 < 16) load_kv_f(st, t, bh, (kt + 2) * 128);
    }

    // ---- cross-wn O reduction via stage0 region (dead now) ----
    float* exch = (float*)(smem + ST0B);   // 4 wm x 32 lanes x 32 floats = 16 KB
    if (wn == 1) {
        float* dst = exch + ((size_t)wm*32 + lane)*32;
#pragma unroll
        for (int j = 0; j < 8; j++)
            *(float4*)&dst[j*4] = make_float4(O[j][0], O[j][1], O[j][2], O[j][3]);
    }
    __syncthreads();
    if (wn == 0) {
        const float* src = exch + ((size_t)wm*32 + lane)*32;
#pragma unroll
        for (int j = 0; j < 8; j++) {
            float4 v = *(const float4*)&src[j*4];
            O[j][0] += v.x; O[j][1] += v.y; O[j][2] += v.z; O[j][3] += v.w;
        }
        // ---- epilogue: write att as fp16 ----
        float inv0 = 1.f / l_run0, inv1 = 1.f / l_run1;
        int b = bh >> 4, h = bh & 15;
        int rg0 = qt*64 + r0;
#pragma unroll
        for (int j = 0; j < 8; j++) {
            int d = h*64 + j*8 + cin;
            size_t i0 = ((size_t)b*SEQ + rg0)*1024 + d;
            size_t i1 = ((size_t)b*SEQ + rg0 + 8)*1024 + d;
            *(__half2*)&g_ah[i0] = __floats2half2_rn(O[j][0]*inv0, O[j][1]*inv0);
            *(__half2*)&g_ah[i1] = __floats2half2_rn(O[j][2]*inv1, O[j][3]*inv1);
        }
        if ((lane & 3) == 0) {
            g_m[(size_t)bh*SEQ + rg0] = m_run0;
            g_l[(size_t)bh*SEQ + rg0] = l_run0;
            g_m[(size_t)bh*SEQ + rg0 + 8] = m_run1;
            g_l[(size_t)bh*SEQ + rg0 + 8] = l_run1;
        }
    }
}

// ---------------- normalize w ----------------
__global__ __launch_bounds__(256) void norm_w_kernel(float* __restrict__ w)
{
    size_t idx = (size_t)blockIdx.x * 256 + threadIdx.x;
    size_t e0 = idx * 4;
    size_t row = e0 >> 11;
    int kt = (int)((e0 & 2047) >> 7);
    float f = __expf(g_mt[row*16 + kt] - g_m[row]) / g_l[row];
    float4 v = *(float4*)&w[e0];
    v.x *= f; v.y *= f; v.z *= f; v.w *= f;
    *(float4*)&w[e0] = v;
}

// ---------------- layernorm ----------------
__global__ __launch_bounds__(256) void ln_kernel(const float* __restrict__ gam,
    const float* __restrict__ bet, float* __restrict__ y)
{
    int i = blockIdx.x, t = threadIdx.x;
    float4 v = *(const float4*)&g_res[(size_t)i*1024 + t*4];
    float s  = v.x + v.y + v.z + v.w;
    float ss = v.x*v.x + v.y*v.y + v.z*v.z + v.w*v.w;
#pragma unroll
    for (int off = 16; off; off >>= 1) {
        s  += __shfl_xor_sync(0xffffffffu, s,  off);
        ss += __shfl_xor_sync(0xffffffffu, ss, off);
    }
    __shared__ float as[8], ass[8];
    if ((t & 31) == 0) { as[t >> 5] = s; ass[t >> 5] = ss; }
    __syncthreads();
    float S = 0.f, SS = 0.f;
#pragma unroll
    for (int u = 0; u < 8; u++) { S += as[u]; SS += ass[u]; }
    float mu  = S * (1.f/1024.f);
    float var = SS * (1.f/1024.f) - mu*mu;
    float inv = rsqrtf(var + 1e-5f);
    float4 gg = *(const float4*)&gam[t*4];
    float4 bb = *(const float4*)&bet[t*4];
    float4 o;
    o.x = (v.x - mu)*inv*gg.x + bb.x;
    o.y = (v.y - mu)*inv*gg.y + bb.y;
    o.z = (v.z - mu)*inv*gg.z + bb.z;
    o.w = (v.w - mu)*inv*gg.w + bb.w;
    *(float4*)&y[(size_t)i*1024 + t*4] = o;
}

// ---------------- launch ----------------
extern "C" void kernel_launch(void* const* d_in, const int* in_sizes, int n_in,
                              void* d_out, int out_size)
{
    const float* x       = (const float*)d_in[0];
    const float* Wq      = (const float*)d_in[1];
    const float* bq      = (const float*)d_in[2];
    const float* Wk      = (const float*)d_in[3];
    const float* bk      = (const float*)d_in[4];
    const float* Wv      = (const float*)d_in[5];
    const float* bv      = (const float*)d_in[6];
    const float* Wo      = (const float*)d_in[7];
    const float* bo      = (const float*)d_in[8];
    const float* ln_g    = (const float*)d_in[9];
    const float* ln_b    = (const float*)d_in[10];
    const float* qq_W    = (const float*)d_in[11];
    const float* qq_b    = (const float*)d_in[12];
    const float* qq_qw_r = (const float*)d_in[13];
    const float* qq_qw_i = (const float*)d_in[14];
    const float* qq_sg   = (const float*)d_in[15];
    const float* qq_em   = (const float*)d_in[16];
    const float* qq_mb   = (const float*)d_in[17];
    const float* qk_W    = (const float*)d_in[18];
    const float* qk_b    = (const float*)d_in[19];
    const float* qk_qw_r = (const float*)d_in[20];
    const float* qk_qw_i = (const float*)d_in[21];
    const float* qk_sg   = (const float*)d_in[22];
    const float* qk_em   = (const float*)d_in[23];
    const float* qk_mb   = (const float*)d_in[24];

    float* y = (float*)d_out;
    float* w = y + (size_t)MROWS*DMODEL;

    float *pQ, *pK, *pV, *pCq, *pCk, *pRes;
    cudaGetSymbolAddress((void**)&pQ,   g_Q);
    cudaGetSymbolAddress((void**)&pK,   g_K);
    cudaGetSymbolAddress((void**)&pV,   g_V);
    cudaGetSymbolAddress((void**)&pCq,  g_Cq);
    cudaGetSymbolAddress((void**)&pCk,  g_Ck);
    cudaGetSymbolAddress((void**)&pRes, g_res);
    __half *pXh, *pAh, *pWh;
    cudaGetSymbolAddress((void**)&pXh, g_xh);
    cudaGetSymbolAddress((void**)&pAh, g_ah);
    cudaGetSymbolAddress((void**)&pWh, g_Wh);

    cudaFuncSetAttribute(mma_gemm_kernel,
        cudaFuncAttributeMaxDynamicSharedMemorySize, GEMM_SMEM);
    cudaFuncSetAttribute(mma_gemm5_kernel,
        cudaFuncAttributeMaxDynamicSharedMemorySize, GEMM_SMEM);
    cudaFuncSetAttribute(flash_mma_kernel,
        cudaFuncAttributeMaxDynamicSharedMemorySize, FLASH2_SMEM);

    prep_m_kernel<<<1, 256>>>(qq_qw_r, qq_qw_i, qk_qw_r, qk_qw_i, qq_em, qk_em);
    quantum_kernel<<<MROWS, 128>>>(x, qq_sg, qk_sg);

    aconv_kernel<<<MROWS*DMODEL/(256*8), 256>>>(x, pXh);
    WconvP WP;
    WP.W[0] = Wq; WP.W[1] = Wk; WP.W[2] = Wv;
    WP.W[3] = qq_W; WP.W[4] = qk_W; WP.W[5] = Wo;
    wconv6_kernel<<<dim3(32, 32, 6), dim3(32, 8)>>>(WP, pWh);

    const size_t WSZ = (size_t)DMODEL*DMODEL;
    GemmP5 P;
    P.Bh[0] = pWh + 0*WSZ; P.bias[0] = bq;   P.out[0] = pQ;  P.tanh_f[0] = 0;
    P.Bh[1] = pWh + 1*WSZ; P.bias[1] = bk;   P.out[1] = pK;  P.tanh_f[1] = 0;
    P.Bh[2] = pWh + 2*WSZ; P.bias[2] = bv;   P.out[2] = pV;  P.tanh_f[2] = 0;
    P.Bh[3] = pWh + 3*WSZ; P.bias[3] = qq_b; P.out[3] = pCq; P.tanh_f[3] = 1;
    P.Bh[4] = pWh + 4*WSZ; P.bias[4] = qk_b; P.out[4] = pCk; P.tanh_f[4] = 1;
    dim3 g5(32, 8, 5);
    mma_gemm5_kernel<<<g5, 256, GEMM_SMEM>>>(pXh, P);

    combine_kernel<<<MROWS, 256>>>(qq_mb, qk_mb);
    vtrans_kernel<<<dim3(32, 32), 256>>>();

    flash_mma_kernel<<<dim3(32, 32), 256, FLASH2_SMEM>>>(w);

    norm_w_kernel<<<(NBH*(size_t)SEQ*SEQ)/(4*256), 256>>>(w);

    dim3 gg(32, 8);
    mma_gemm_kernel<<<gg, 256, GEMM_SMEM>>>(pAh, pWh + 5*WSZ, bo, x, pRes, 0);

    ln_kernel<<<MROWS, 256>>>(ln_g, ln_b, y);
}